// round 10
// baseline (speedup 1.0000x reference)
#include <cuda_runtime.h>
#include <cuda_bf16.h>
#include <math.h>
#include <stdint.h>

#define B_ROWS 4096
#define DM     256
#define DDYN   512
#define SCALE  0.125f
#define LN_EPS 1e-5f
#define WT_STRIDE 260
#define NCHUNK 26

// ---------------- device scratch ----------------
__device__ float g_h0 [B_ROWS * DM];
__device__ float g_u  [B_ROWS * DM * 4];
__device__ float g_qbk[B_ROWS * 4];
__device__ float g_z  [B_ROWS * DM];
// 26 chunks (Wstat 2, Wv 8, W1 8, W2 8): [256 n][128B row = 64B hi | 64B lo] swizzled
__device__ uint4 g_B[NCHUNK * 2048];

__device__ __forceinline__ uint32_t smem_u32(const void* p) {
    uint32_t a;
    asm("{ .reg .u64 t; cvta.to.shared.u64 t, %1; cvt.u32.u64 %0, t; }" : "=r"(a) : "l"(p));
    return a;
}

// ---------------- mma / ldmatrix ----------------
__device__ __forceinline__ void mma_bf16(float* d, const unsigned* a, unsigned b0, unsigned b1) {
    asm volatile("mma.sync.aligned.m16n8k16.row.col.f32.bf16.bf16.f32 "
        "{%0,%1,%2,%3}, {%4,%5,%6,%7}, {%8,%9}, {%0,%1,%2,%3};"
        : "+f"(d[0]), "+f"(d[1]), "+f"(d[2]), "+f"(d[3])
        : "r"(a[0]), "r"(a[1]), "r"(a[2]), "r"(a[3]), "r"(b0), "r"(b1));
}
__device__ __forceinline__ void ldsm4(unsigned* r, unsigned addr) {
    asm volatile("ldmatrix.sync.aligned.m8n8.x4.shared.b16 {%0,%1,%2,%3}, [%4];"
        : "=r"(r[0]), "=r"(r[1]), "=r"(r[2]), "=r"(r[3]) : "r"(addr));
}

// A smem layout: blocked atoms 8 rows x 64 cols (1KB), atom = (row>>3) + (col>>6)*16
__device__ __forceinline__ void storeA2(char* Ah, char* Al, int row, int col,
                                        float v0, float v1) {
    unsigned byte = ((unsigned)(row >> 3) << 10) + ((unsigned)(col >> 6) << 14)
                  + ((unsigned)(row & 7) << 7)
                  + ((((unsigned)(col & 63)) * 2u) ^ (((unsigned)(row & 7)) << 4));
    __nv_bfloat16 h0 = __float2bfloat16(v0), h1 = __float2bfloat16(v1);
    *(unsigned*)(Ah + byte) = (unsigned)__bfloat16_as_ushort(h0) |
                              ((unsigned)__bfloat16_as_ushort(h1) << 16);
    __nv_bfloat16 l0 = __float2bfloat16(v0 - __bfloat162float(h0));
    __nv_bfloat16 l1 = __float2bfloat16(v1 - __bfloat162float(h1));
    *(unsigned*)(Al + byte) = (unsigned)__bfloat16_as_ushort(l0) |
                              ((unsigned)__bfloat16_as_ushort(l1) << 16);
}

// ---------------- k0 ----------------
__global__ void k0(const float* __restrict__ Ws, const float* __restrict__ Wv,
                   const float* __restrict__ W1, const float* __restrict__ W2) {
    const int c = blockIdx.x, n = threadIdx.x;
    const float* W; int kbase;
    if (c < 2)       { W = Ws; kbase = c * 32; }
    else if (c < 10) { W = Wv; kbase = (c - 2) * 32; }
    else if (c < 18) { W = W1; kbase = (c - 10) * 32; }
    else             { W = W2; kbase = (c - 18) * 32; }
    char* bp = (char*)(g_B + (size_t)c * 2048) + n * 128;
    const unsigned nm = ((unsigned)n & 7u) << 4;
    for (int kl = 0; kl < 32; kl++) {
        float v = W[(size_t)(kbase + kl) * 256 + n];
        __nv_bfloat16 h = __float2bfloat16(v);
        __nv_bfloat16 l = __float2bfloat16(v - __bfloat162float(h));
        *(__nv_bfloat16*)(bp + (((unsigned)kl * 2u) ^ nm))       = h;
        *(__nv_bfloat16*)(bp + ((64u + (unsigned)kl * 2u) ^ nm)) = l;
    }
}

// ---------------- fp32 tiled GEMM helper (k1, k3) ----------------
template<int NTHREADS>
__device__ __forceinline__ void gemm_acc(
    const float* __restrict__ Asm, int astride, int kdim,
    const float* __restrict__ Wg, float* __restrict__ Wt,
    float acc[4][8], int tid)
{
#pragma unroll
    for (int t = 0; t < 4; t++)
#pragma unroll
        for (int j = 0; j < 8; j++) acc[t][j] = 0.f;
    const int tc = tid & 31, tok0 = (tid >> 5) * 4, col0 = tc * 8;
    const int nkt = kdim >> 4;
    for (int kt = 0; kt < nkt; ++kt) {
        const float4* src = reinterpret_cast<const float4*>(Wg + kt * 16 * DM);
#pragma unroll
        for (int f = tid; f < 1024; f += NTHREADS) {
            int row = f >> 6, c4 = f & 63;
            *reinterpret_cast<float4*>(Wt + row * WT_STRIDE + c4 * 4) = src[f];
        }
        __syncthreads();
#pragma unroll
        for (int kk4 = 0; kk4 < 4; ++kk4) {
            const int kbase = kt * 16 + kk4 * 4;
            float a_[4][4];
#pragma unroll
            for (int t = 0; t < 4; t++) {
                float4 v = *reinterpret_cast<const float4*>(Asm + (tok0 + t) * astride + kbase);
                a_[t][0]=v.x; a_[t][1]=v.y; a_[t][2]=v.z; a_[t][3]=v.w;
            }
#pragma unroll
            for (int r = 0; r < 4; r++) {
                const float4 w0 = *reinterpret_cast<const float4*>(Wt + (kk4*4+r)*WT_STRIDE + col0);
                const float4 w1 = *reinterpret_cast<const float4*>(Wt + (kk4*4+r)*WT_STRIDE + col0 + 4);
                float w[8] = {w0.x,w0.y,w0.z,w0.w,w1.x,w1.y,w1.z,w1.w};
#pragma unroll
                for (int t = 0; t < 4; t++) {
                    const float a = a_[t][r];
#pragma unroll
                    for (int j = 0; j < 8; j++) acc[t][j] = fmaf(a, w[j], acc[t][j]);
                }
            }
        }
        __syncthreads();
    }
}

// ---------------- k1 (unchanged) ----------------
__global__ void __launch_bounds__(256, 1) k1(
    const float* __restrict__ h_dyn, const float* __restrict__ W_dyn,
    const float* __restrict__ b_dyn, const float* __restrict__ g_ndyn,
    const float* __restrict__ b_ndyn, const float* __restrict__ Wq,
    const float* __restrict__ bq, const float* __restrict__ Wk,
    const float* __restrict__ bk)
{
    extern __shared__ float sm[];
    float* sm_hd  = sm;
    float* sm_h   = sm_hd + 32 * 512;
    float* sm_q   = sm_h  + 32 * 256;
    float* sm_wt  = sm_q  + 32 * 256;
    float* p_bdyn = sm_wt + 16 * WT_STRIDE;
    float* p_gn = p_bdyn + 256; float* p_bn = p_gn + 256;
    float* p_bq = p_bn + 256;   float* p_bk = p_bq + 256;

    const int tid = threadIdx.x;
    const int row0 = blockIdx.x * 32;
    {
        const float4* src = reinterpret_cast<const float4*>(h_dyn + (size_t)row0 * DDYN);
        for (int f = tid; f < 4096; f += 256) reinterpret_cast<float4*>(sm_hd)[f] = src[f];
    }
    if (tid < 64) {
        reinterpret_cast<float4*>(p_bdyn)[tid] = reinterpret_cast<const float4*>(b_dyn)[tid];
        reinterpret_cast<float4*>(p_gn)[tid]   = reinterpret_cast<const float4*>(g_ndyn)[tid];
        reinterpret_cast<float4*>(p_bn)[tid]   = reinterpret_cast<const float4*>(b_ndyn)[tid];
        reinterpret_cast<float4*>(p_bq)[tid]   = reinterpret_cast<const float4*>(bq)[tid];
        reinterpret_cast<float4*>(p_bk)[tid]   = reinterpret_cast<const float4*>(bk)[tid];
    }
    __syncthreads();

    float acc[4][8];
    gemm_acc<256>(sm_hd, 512, 512, W_dyn, sm_wt, acc, tid);
    {
        const int tc = tid & 31, tok0 = (tid >> 5) * 4, col0 = tc * 8;
#pragma unroll
        for (int t = 0; t < 4; t++) {
            float s = 0.f, s2 = 0.f;
#pragma unroll
            for (int j = 0; j < 8; j++) {
                float v = acc[t][j] + p_bdyn[col0 + j];
                acc[t][j] = v; s += v; s2 += v * v;
            }
            float* h0p = g_h0 + (size_t)(row0 + tok0 + t) * DM + col0;
            reinterpret_cast<float4*>(h0p)[0] = make_float4(acc[t][0],acc[t][1],acc[t][2],acc[t][3]);
            reinterpret_cast<float4*>(h0p)[1] = make_float4(acc[t][4],acc[t][5],acc[t][6],acc[t][7]);
#pragma unroll
            for (int off = 16; off; off >>= 1) {
                s  += __shfl_xor_sync(0xffffffffu, s,  off);
                s2 += __shfl_xor_sync(0xffffffffu, s2, off);
            }
            float mean = s * (1.f/256.f);
            float rstd = rsqrtf(s2 * (1.f/256.f) - mean*mean + LN_EPS);
#pragma unroll
            for (int j = 0; j < 8; j++)
                sm_h[(tok0+t)*DM + col0+j] = (acc[t][j]-mean)*rstd*p_gn[col0+j] + p_bn[col0+j];
        }
    }
    __syncthreads();

    gemm_acc<256>(sm_h, 256, 256, Wq, sm_wt, acc, tid);
    {
        const int tc = tid & 31, tok0 = (tid >> 5) * 4, col0 = tc * 8;
#pragma unroll
        for (int t = 0; t < 4; t++)
#pragma unroll
            for (int j = 0; j < 8; j++)
                sm_q[(tok0+t)*DM + col0+j] = acc[t][j] + p_bq[col0+j];
    }
    __syncthreads();

    for (int jt = 0; jt < 16; jt++) {
        const float4* src = reinterpret_cast<const float4*>(Wk + jt * 16 * DM);
        for (int f = tid; f < 1024; f += 256) {
            int r = f >> 6, c4 = f & 63;
            *reinterpret_cast<float4*>(sm_wt + r * WT_STRIDE + c4 * 4) = src[f];
        }
        __syncthreads();
        const int jl = tid & 15;
#pragma unroll
        for (int rr = 0; rr < 2; rr++) {
            const int r = (tid >> 4) + rr * 16;
            float ua[4];
#pragma unroll
            for (int h = 0; h < 4; h++) {
                float a = 0.f;
#pragma unroll
                for (int d4 = 0; d4 < 16; d4++) {
                    float4 qv = *reinterpret_cast<const float4*>(sm_q + r*DM + h*64 + d4*4);
                    float4 wv = *reinterpret_cast<const float4*>(sm_wt + jl*WT_STRIDE + h*64 + d4*4);
                    a += qv.x*wv.x + qv.y*wv.y + qv.z*wv.z + qv.w*wv.w;
                }
                ua[h] = a;
            }
            *reinterpret_cast<float4*>(g_u + (size_t)(row0+r)*1024 + (jt*16+jl)*4) =
                make_float4(ua[0], ua[1], ua[2], ua[3]);
        }
        __syncthreads();
    }
    if (tid < 128) {
        const int r = tid >> 2, h = tid & 3;
        float a = 0.f;
#pragma unroll
        for (int d = 0; d < 64; d++) a += sm_q[r*DM + h*64 + d] * p_bk[h*64 + d];
        g_qbk[(size_t)(row0+r)*4 + h] = a;
    }
}

// ---------------- k2m: HMMA fused token path, ldmatrix + 64x64 warp tiles ----------------
#define O_AH   0
#define O_AL   65536
#define O_B0   131072
#define O_B1   163840
#define O_PB   196608
#define O_US   205824
#define O_PS   216064
#define O_LG   220160
#define O_WN   228352
#define O_TAIL 230400
#define SMEM2  230464

__device__ __forceinline__ void prefetch_chunk(char* buf, int g, int tid) {
    const char* src = (const char*)(g_B + (size_t)g * 2048);
    unsigned dst = smem_u32(buf);
#pragma unroll
    for (int i = 0; i < 8; i++) {
        int o = (tid + i * 256) * 16;
        asm volatile("cp.async.cg.shared.global [%0], [%1], 16;"
            :: "r"(dst + o), "l"(src + o) : "memory");
    }
    asm volatile("cp.async.commit_group;" ::: "memory");
}

// warp grid: 8 warps = 2 (wm, 64 rows) x 4 (wn4, 64 cols)
__device__ __forceinline__ void gemm_tc(float acc[4][8][4],
    unsigned aHi, unsigned aLo, char* B0, char* B1,
    int g0, int nc, int wm, int wn4, int lane, int tid)
{
#pragma unroll
    for (int mt = 0; mt < 4; mt++)
#pragma unroll
        for (int nt = 0; nt < 8; nt++)
#pragma unroll
            for (int q = 0; q < 4; q++) acc[mt][nt][q] = 0.f;

    // A lane addressing: lanes 0-15 rows r0..r15 (k-seg 0), 16-31 same rows k-seg 1
    const int aseg = lane >> 4;
    unsigned Arow[4], Axor[4];
#pragma unroll
    for (int mt = 0; mt < 4; mt++) {
        int row = wm * 64 + mt * 16 + (lane & 15);
        Arow[mt] = ((unsigned)(row >> 3) << 10) | ((unsigned)(row & 7) << 7);
        Axor[mt] = (unsigned)(row & 7) << 4;
    }
    // B lane addressing: pair p covers nt=2p,2p+1
    const unsigned bseg = (lane >> 3) & 1;
    unsigned Bn[4], Bx[4];
#pragma unroll
    for (int p = 0; p < 4; p++) {
        int n = wn4 * 64 + p * 16 + (lane >> 4) * 8 + (lane & 7);
        Bn[p] = (unsigned)n * 128u;
        Bx[p] = ((unsigned)n & 7u) << 4;
    }

    for (int kc = 0; kc < nc; kc++) {
        const int g = g0 + kc;
        asm volatile("cp.async.wait_group 0;" ::: "memory");
        __syncthreads();
        if (g + 1 < NCHUNK) prefetch_chunk(((g + 1) & 1) ? B1 : B0, g + 1, tid);
        const unsigned bbase = smem_u32((g & 1) ? B1 : B0);
#pragma unroll
        for (int ks = 0; ks < 2; ks++) {
            const int kl16 = kc * 2 + ks;
            const unsigned acol = ((unsigned)(kl16 >> 2) << 14);
            const unsigned asub = (unsigned)((kl16 & 3) * 32 + aseg * 16);
            unsigned ahi[4][4], alo[4][4];
#pragma unroll
            for (int mt = 0; mt < 4; mt++) {
                unsigned off = acol + Arow[mt] + (asub ^ Axor[mt]);
                ldsm4(ahi[mt], aHi + off);
                ldsm4(alo[mt], aLo + off);
            }
            const unsigned bsub = (unsigned)(ks * 32 + bseg * 16);
#pragma unroll
            for (int p = 0; p < 4; p++) {
                unsigned bhi[4], blo[4];
                ldsm4(bhi, bbase + Bn[p] + (bsub ^ Bx[p]));
                ldsm4(blo, bbase + Bn[p] + ((64u + bsub) ^ Bx[p]));
#pragma unroll
                for (int mt = 0; mt < 4; mt++) {
                    mma_bf16(acc[mt][2*p],   ahi[mt], bhi[0], bhi[1]);
                    mma_bf16(acc[mt][2*p],   ahi[mt], blo[0], blo[1]);
                    mma_bf16(acc[mt][2*p],   alo[mt], bhi[0], bhi[1]);
                    mma_bf16(acc[mt][2*p+1], ahi[mt], bhi[2], bhi[3]);
                    mma_bf16(acc[mt][2*p+1], ahi[mt], blo[2], blo[3]);
                    mma_bf16(acc[mt][2*p+1], alo[mt], bhi[2], bhi[3]);
                }
            }
        }
    }
    __syncthreads();
}

// LN epilogue on fragments; optional logit partials (S1)
__device__ __forceinline__ void epi_ln_m(float acc[4][8][4],
    const float* bias, const float* gg, const float* bb,
    char* Ah, char* Al, float* ps, const float* us, float* lg,
    int wm, int wn4, int lane, bool do_logits)
{
    const int g8 = lane >> 2, tp = lane & 3;
    float s[8], s2[8];
#pragma unroll
    for (int i = 0; i < 8; i++) { s[i] = 0.f; s2[i] = 0.f; }
#pragma unroll
    for (int mt = 0; mt < 4; mt++)
#pragma unroll
        for (int nt = 0; nt < 8; nt++) {
            int C = wn4 * 64 + nt * 8 + tp * 2;
            float b0v = bias[C], b1v = bias[C + 1];
            float v0 = acc[mt][nt][0] + b0v, v1 = acc[mt][nt][1] + b1v;
            float v2 = acc[mt][nt][2] + b0v, v3 = acc[mt][nt][3] + b1v;
            acc[mt][nt][0]=v0; acc[mt][nt][1]=v1; acc[mt][nt][2]=v2; acc[mt][nt][3]=v3;
            s[mt*2]   += v0 + v1;  s2[mt*2]   += v0*v0 + v1*v1;
            s[mt*2+1] += v2 + v3;  s2[mt*2+1] += v2*v2 + v3*v3;
        }
#pragma unroll
    for (int off = 1; off <= 2; off <<= 1)
#pragma unroll
        for (int i = 0; i < 8; i++) {
            s[i]  += __shfl_xor_sync(0xffffffffu, s[i],  off);
            s2[i] += __shfl_xor_sync(0xffffffffu, s2[i], off);
        }
    if (tp == 0) {
#pragma unroll
        for (int i = 0; i < 8; i++) {
            int row = wm*64 + (i>>1)*16 + (i&1)*8 + g8;
            ps[(row*4 + wn4)*2]     = s[i];
            ps[(row*4 + wn4)*2 + 1] = s2[i];
        }
    }
    __syncthreads();
    float mean[8], rstd[8];
#pragma unroll
    for (int i = 0; i < 8; i++) {
        int row = wm*64 + (i>>1)*16 + (i&1)*8 + g8;
        float ss = 0.f, ss2 = 0.f;
#pragma unroll
        for (int x = 0; x < 4; x++) { ss += ps[(row*4+x)*2]; ss2 += ps[(row*4+x)*2+1]; }
        mean[i] = ss * (1.f/256.f);
        rstd[i] = rsqrtf(ss2 * (1.f/256.f) - mean[i]*mean[i] + LN_EPS);
    }
    float la[8][4];
    if (do_logits)
#pragma unroll
        for (int i = 0; i < 8; i++)
#pragma unroll
            for (int h = 0; h < 4; h++) la[i][h] = 0.f;
#pragma unroll
    for (int mt = 0; mt < 4; mt++)
#pragma unroll
        for (int nt = 0; nt < 8; nt++) {
            int C = wn4 * 64 + nt * 8 + tp * 2;
            float g0 = gg[C], g1 = gg[C+1], e0 = bb[C], e1 = bb[C+1];
#pragma unroll
            for (int rh = 0; rh < 2; rh++) {
                int i = mt*2 + rh;
                int row = wm*64 + mt*16 + rh*8 + g8;
                float n0 = (acc[mt][nt][rh*2]   - mean[i]) * rstd[i] * g0 + e0;
                float n1 = (acc[mt][nt][rh*2+1] - mean[i]) * rstd[i] * g1 + e1;
                storeA2(Ah, Al, row, C, n0, n1);
                if (do_logits) {
                    float4 u0 = *(const float4*)(us + wm*1024 + C*4);
                    float4 u1 = *(const float4*)(us + wm*1024 + (C+1)*4);
                    la[i][0] += n0*u0.x + n1*u1.x;
                    la[i][1] += n0*u0.y + n1*u1.y;
                    la[i][2] += n0*u0.z + n1*u1.z;
                    la[i][3] += n0*u0.w + n1*u1.w;
                }
            }
        }
    if (do_logits) {
#pragma unroll
        for (int off = 1; off <= 2; off <<= 1)
#pragma unroll
            for (int i = 0; i < 8; i++)
#pragma unroll
                for (int h = 0; h < 4; h++)
                    la[i][h] += __shfl_xor_sync(0xffffffffu, la[i][h], off);
        if (tp == 0)
#pragma unroll
            for (int i = 0; i < 8; i++) {
                int row = wm*64 + (i>>1)*16 + (i&1)*8 + g8;
#pragma unroll
                for (int h = 0; h < 4; h++) lg[row*16 + wn4*4 + h] = la[i][h];
            }
    }
    __syncthreads();
}

__global__ void __launch_bounds__(256, 1) k2m(
    const float* __restrict__ x_stat,
    const float* __restrict__ b_stat, const float* __restrict__ g_nstat,
    const float* __restrict__ b_nstat, const float* __restrict__ bv,
    const float* __restrict__ g_mlp,  const float* __restrict__ b_mlp,
    const float* __restrict__ b1,     const float* __restrict__ b2,
    float* __restrict__ out)
{
    extern __shared__ char smc[];
    char*  Ah  = smc + O_AH;
    char*  Al  = smc + O_AL;
    char*  B0  = smc + O_B0;
    char*  B1  = smc + O_B1;
    float* pb  = (float*)(smc + O_PB);
    float* us  = (float*)(smc + O_US);
    float* ps  = (float*)(smc + O_PS);
    float* lg  = (float*)(smc + O_LG);
    float* zs  = (float*)(smc + O_LG);   // reuse after S1
    float* wns = (float*)(smc + O_WN);
    float* qbk = (float*)(smc + O_TAIL);
    float* ssm = (float*)(smc + O_TAIL + 32);

    const int tid = threadIdx.x, lane = tid & 31, w = tid >> 5;
    const int wm = w & 1, wn4 = w >> 1;
    const int g8 = lane >> 2, tp = lane & 3;
    const size_t b0 = (size_t)blockIdx.x * 2;
    const unsigned aHi = smem_u32(Ah), aLo = smem_u32(Al);

    prefetch_chunk(B0, 0, tid);

    // ---- cooperative staging ----
    for (int idx = tid; idx < 2048; idx += 256) {
        int rr = idx >> 4, c4 = (idx & 15) * 4;
        float4 v = *reinterpret_cast<const float4*>(
            x_stat + (b0 + (rr >> 6)) * 4096 + (size_t)(rr & 63) * 64 + c4);
        storeA2(Ah, Al, rr, c4,     v.x, v.y);
        storeA2(Ah, Al, rr, c4 + 2, v.z, v.w);
    }
#pragma unroll
    for (int i = 0; i < 2; i++)
        reinterpret_cast<float4*>(us)[tid + i * 256] =
            reinterpret_cast<const float4*>(g_u + b0 * 1024)[tid + i * 256];
    if (tid < 64) {
        reinterpret_cast<float4*>(pb + 0*256)[tid] = reinterpret_cast<const float4*>(b_stat)[tid];
        reinterpret_cast<float4*>(pb + 1*256)[tid] = reinterpret_cast<const float4*>(g_nstat)[tid];
        reinterpret_cast<float4*>(pb + 2*256)[tid] = reinterpret_cast<const float4*>(b_nstat)[tid];
        reinterpret_cast<float4*>(pb + 3*256)[tid] = reinterpret_cast<const float4*>(bv)[tid];
        reinterpret_cast<float4*>(pb + 4*256)[tid] = reinterpret_cast<const float4*>(g_mlp)[tid];
        reinterpret_cast<float4*>(pb + 5*256)[tid] = reinterpret_cast<const float4*>(b_mlp)[tid];
        reinterpret_cast<float4*>(pb + 6*256)[tid] = reinterpret_cast<const float4*>(b1)[tid];
        reinterpret_cast<float4*>(pb + 7*256)[tid] = reinterpret_cast<const float4*>(b2)[tid];
    }
    if (tid < 8) qbk[tid] = g_qbk[b0 * 4 + tid];

    float acc[4][8][4];

    // ---- S1: s = x_stat @ W_stat ; LN -> A ; logit partials (chunks 0-1) ----
    gemm_tc(acc, aHi, aLo, B0, B1, 0, 2, wm, wn4, lane, tid);
    epi_ln_m(acc, pb + 0*256, pb + 1*256, pb + 2*256, Ah, Al, ps, us, lg,
             wm, wn4, lane, true);

    // ---- logits -> sigmoid -> normalize -> w_mean ----
#pragma unroll
    for (int ii = 0; ii < 2; ii++) {
        int idx = tid + ii * 256;
        int row = idx >> 2, h = idx & 3;
        float lv = qbk[(row >> 6) * 4 + h];
#pragma unroll
        for (int x = 0; x < 4; x++) lv += lg[row*16 + x*4 + h];
        wns[idx] = 1.f / (1.f + expf(-lv * SCALE));
    }
    __syncthreads();
    if (tid < 8) {
        int half = tid >> 2, h = tid & 3;
        float sum = 0.f;
        for (int k = 0; k < 64; k++) sum += wns[(half*64 + k)*4 + h];
        ssm[tid] = sum + 1e-6f;
    }
    __syncthreads();
#pragma unroll
    for (int ii = 0; ii < 2; ii++) {
        int idx = tid + ii * 256;
        wns[idx] = wns[idx] / ssm[(idx >> 8) * 4 + (idx & 3)];
    }
    __syncthreads();
    if (tid < 128)
        out[(size_t)B_ROWS * DM + (b0 + (tid >> 6)) * 64 + (tid & 63)] =
            0.25f * (wns[tid*4] + wns[tid*4+1] + wns[tid*4+2] + wns[tid*4+3]);
    __syncthreads();

    // ---- S2: v = s @ Wv ; LN(g_mlp) -> A (chunks 2-9) ----
    gemm_tc(acc, aHi, aLo, B0, B1, 2, 8, wm, wn4, lane, tid);
    epi_ln_m(acc, pb + 3*256, pb + 4*256, pb + 5*256, Ah, Al, ps, us, lg,
             wm, wn4, lane, false);

    // ---- S3: t = gelu(v @ W1 + b1) -> A (chunks 10-17) ----
    gemm_tc(acc, aHi, aLo, B0, B1, 10, 8, wm, wn4, lane, tid);
#pragma unroll
    for (int mt = 0; mt < 4; mt++)
#pragma unroll
        for (int nt = 0; nt < 8; nt++) {
            int C = wn4 * 64 + nt * 8 + tp * 2;
            float e0 = pb[6*256 + C], e1 = pb[6*256 + C + 1];
#pragma unroll
            for (int rh = 0; rh < 2; rh++) {
                int row = wm*64 + mt*16 + rh*8 + g8;
                float x0 = acc[mt][nt][rh*2]   + e0;
                float x1 = acc[mt][nt][rh*2+1] + e1;
                float n0 = 0.5f * x0 * (1.f + erff(x0 * 0.70710678118f));
                float n1 = 0.5f * x1 * (1.f + erff(x1 * 0.70710678118f));
                storeA2(Ah, Al, row, C, n0, n1);
            }
        }
    __syncthreads();

    // ---- S4: vtok = t @ W2 + b2 ; weighted column sums -> z (chunks 18-25) ----
    gemm_tc(acc, aHi, aLo, B0, B1, 18, 8, wm, wn4, lane, tid);
    zs[tid] = 0.f; zs[tid + 256] = 0.f;
    __syncthreads();
    {
        float za[8], zb[8];
#pragma unroll
        for (int nt = 0; nt < 8; nt++) { za[nt] = 0.f; zb[nt] = 0.f; }
#pragma unroll
        for (int mt = 0; mt < 4; mt++)
#pragma unroll
            for (int nt = 0; nt < 8; nt++) {
                int C = wn4 * 64 + nt * 8 + tp * 2;
                int hcol = C >> 6;
                float e0 = pb[7*256 + C], e1 = pb[7*256 + C + 1];
#pragma unroll
                for (int rh = 0; rh < 2; rh++) {
                    int row = wm*64 + mt*16 + rh*8 + g8;
                    float wf = wns[row*4 + hcol];
                    za[nt] += (acc[mt][nt][rh*2]   + e0) * wf;
                    zb[nt] += (acc[mt][nt][rh*2+1] + e1) * wf;
                }
            }
#pragma unroll
        for (int off = 4; off <= 16; off <<= 1)
#pragma unroll
            for (int nt = 0; nt < 8; nt++) {
                za[nt] += __shfl_xor_sync(0xffffffffu, za[nt], off);
                zb[nt] += __shfl_xor_sync(0xffffffffu, zb[nt], off);
            }
        if (lane < 4) {
#pragma unroll
            for (int nt = 0; nt < 8; nt++) {
                int C = wn4 * 64 + nt * 8 + lane * 2;
                atomicAdd(&zs[wm*256 + C],     za[nt]);
                atomicAdd(&zs[wm*256 + C + 1], zb[nt]);
            }
        }
    }
    __syncthreads();
    g_z[b0 * 256 + tid]       = zs[tid];
    g_z[b0 * 256 + tid + 256] = zs[tid + 256];
}

// ---------------- k3: c = z @ Wo + bo ; out = h0 + rs*c ----------------
__global__ void __launch_bounds__(256, 1) k3(
    const float* __restrict__ Wo, const float* __restrict__ bo,
    const float* __restrict__ res_p, float* __restrict__ out)
{
    extern __shared__ float sm[];
    float* zsm = sm;
    float* Wt  = zsm + 32 * 256;
    float* pbo = Wt + 16 * WT_STRIDE;
    const int tid = threadIdx.x, row0 = blockIdx.x * 32;
    for (int f = tid; f < 2048; f += 256)
        reinterpret_cast<float4*>(zsm)[f] =
            reinterpret_cast<const float4*>(g_z + (size_t)row0 * 256)[f];
    if (tid < 64)
        reinterpret_cast<float4*>(pbo)[tid] = reinterpret_cast<const float4*>(bo)[tid];
    __syncthreads();
    float acc[4][8];
    gemm_acc<256>(zsm, 256, 256, Wo, Wt, acc, tid);
    const float rs = *res_p;
    const int tc = tid & 31, tok0 = (tid >> 5) * 4, col0 = tc * 8;
#pragma unroll
    for (int t = 0; t < 4; t++) {
        const size_t r = (size_t)(row0 + tok0 + t);
#pragma unroll
        for (int j = 0; j < 8; j++)
            out[r * 256 + col0 + j] =
                g_h0[r * 256 + col0 + j] + rs * (acc[t][j] + pbo[col0 + j]);
    }
}

// ============================================================
extern "C" void kernel_launch(void* const* d_in, const int* in_sizes, int n_in,
                              void* d_out, int out_size)
{
    const float* h_dyn   = (const float*)d_in[0];
    const float* x_stat  = (const float*)d_in[1];
    const float* W_dyn   = (const float*)d_in[2];
    const float* b_dyn   = (const float*)d_in[3];
    const float* W_stat  = (const float*)d_in[4];
    const float* b_stat  = (const float*)d_in[5];
    const float* g_ndyn  = (const float*)d_in[6];
    const float* b_ndyn  = (const float*)d_in[7];
    const float* g_nstat = (const float*)d_in[8];
    const float* b_nstat = (const float*)d_in[9];
    const float* Wq  = (const float*)d_in[10];
    const float* bq  = (const float*)d_in[11];
    const float* Wk  = (const float*)d_in[12];
    const float* bk  = (const float*)d_in[13];
    const float* Wv  = (const float*)d_in[14];
    const float* bv  = (const float*)d_in[15];
    const float* g_mlp = (const float*)d_in[16];
    const float* b_mlp = (const float*)d_in[17];
    const float* W1  = (const float*)d_in[18];
    const float* b1  = (const float*)d_in[19];
    const float* W2  = (const float*)d_in[20];
    const float* b2  = (const float*)d_in[21];
    const float* Wo  = (const float*)d_in[22];
    const float* bo  = (const float*)d_in[23];
    const float* res_sc = (const float*)d_in[24];
    float* out = (float*)d_out;

    const int SMEM1 = (32*512 + 32*256 + 32*256 + 16*WT_STRIDE + 5*256) * 4;
    const int SMEM3 = (32*256 + 16*WT_STRIDE + 256) * 4;
    cudaFuncSetAttribute(k1,  cudaFuncAttributeMaxDynamicSharedMemorySize, SMEM1);
    cudaFuncSetAttribute(k2m, cudaFuncAttributeMaxDynamicSharedMemorySize, SMEM2);
    cudaFuncSetAttribute(k3,  cudaFuncAttributeMaxDynamicSharedMemorySize, SMEM3);

    k0<<<NCHUNK, 256>>>(W_stat, Wv, W1, W2);
    k1<<<B_ROWS / 32, 256, SMEM1>>>(h_dyn, W_dyn, b_dyn, g_ndyn, b_ndyn, Wq, bq, Wk, bk);
    k2m<<<B_ROWS / 2, 256, SMEM2>>>(x_stat, b_stat, g_nstat, b_nstat, bv,
                                    g_mlp, b_mlp, b1, b2, out);
    k3<<<B_ROWS / 32, 256, SMEM3>>>(Wo, bo, res_sc, out);
}

// round 11
// speedup vs baseline: 1.1480x; 1.1480x over previous
#include <cuda_runtime.h>
#include <cuda_bf16.h>
#include <math.h>
#include <stdint.h>

#define B_ROWS 4096
#define DM     256
#define DDYN   512
#define SCALE  0.125f
#define LN_EPS 1e-5f
#define WT_STRIDE 260
#define NCHUNK 26

// ---------------- device scratch ----------------
__device__ float g_h0 [B_ROWS * DM];
__device__ float g_u  [B_ROWS * DM * 4];
__device__ float g_qbk[B_ROWS * 4];
__device__ float g_z  [B_ROWS * DM];
// 26 chunks (Wstat 2, Wv 8, W1 8, W2 8): [256 n][128B row = 64B hi | 64B lo] swizzled
__device__ uint4 g_B[NCHUNK * 2048];

__device__ __forceinline__ uint32_t smem_u32(const void* p) {
    uint32_t a;
    asm("{ .reg .u64 t; cvta.to.shared.u64 t, %1; cvt.u32.u64 %0, t; }" : "=r"(a) : "l"(p));
    return a;
}

// ---------------- mma / ldmatrix ----------------
__device__ __forceinline__ void mma_bf16(float* d, const unsigned* a, unsigned b0, unsigned b1) {
    asm volatile("mma.sync.aligned.m16n8k16.row.col.f32.bf16.bf16.f32 "
        "{%0,%1,%2,%3}, {%4,%5,%6,%7}, {%8,%9}, {%0,%1,%2,%3};"
        : "+f"(d[0]), "+f"(d[1]), "+f"(d[2]), "+f"(d[3])
        : "r"(a[0]), "r"(a[1]), "r"(a[2]), "r"(a[3]), "r"(b0), "r"(b1));
}
__device__ __forceinline__ void ldsm4(unsigned* r, unsigned addr) {
    asm volatile("ldmatrix.sync.aligned.m8n8.x4.shared.b16 {%0,%1,%2,%3}, [%4];"
        : "=r"(r[0]), "=r"(r[1]), "=r"(r[2]), "=r"(r[3]) : "r"(addr));
}

// A smem layout: blocked atoms 8 rows x 64 cols (1KB), atom = (row>>3) + (col>>6)*16
__device__ __forceinline__ void storeA2(char* Ah, char* Al, int row, int col,
                                        float v0, float v1) {
    unsigned byte = ((unsigned)(row >> 3) << 10) + ((unsigned)(col >> 6) << 14)
                  + ((unsigned)(row & 7) << 7)
                  + ((((unsigned)(col & 63)) * 2u) ^ (((unsigned)(row & 7)) << 4));
    __nv_bfloat16 h0 = __float2bfloat16(v0), h1 = __float2bfloat16(v1);
    *(unsigned*)(Ah + byte) = (unsigned)__bfloat16_as_ushort(h0) |
                              ((unsigned)__bfloat16_as_ushort(h1) << 16);
    __nv_bfloat16 l0 = __float2bfloat16(v0 - __bfloat162float(h0));
    __nv_bfloat16 l1 = __float2bfloat16(v1 - __bfloat162float(h1));
    *(unsigned*)(Al + byte) = (unsigned)__bfloat16_as_ushort(l0) |
                              ((unsigned)__bfloat16_as_ushort(l1) << 16);
}

// ---------------- k0 ----------------
__global__ void k0(const float* __restrict__ Ws, const float* __restrict__ Wv,
                   const float* __restrict__ W1, const float* __restrict__ W2) {
    const int c = blockIdx.x, n = threadIdx.x;
    const float* W; int kbase;
    if (c < 2)       { W = Ws; kbase = c * 32; }
    else if (c < 10) { W = Wv; kbase = (c - 2) * 32; }
    else if (c < 18) { W = W1; kbase = (c - 10) * 32; }
    else             { W = W2; kbase = (c - 18) * 32; }
    char* bp = (char*)(g_B + (size_t)c * 2048) + n * 128;
    const unsigned nm = ((unsigned)n & 7u) << 4;
    for (int kl = 0; kl < 32; kl++) {
        float v = W[(size_t)(kbase + kl) * 256 + n];
        __nv_bfloat16 h = __float2bfloat16(v);
        __nv_bfloat16 l = __float2bfloat16(v - __bfloat162float(h));
        *(__nv_bfloat16*)(bp + (((unsigned)kl * 2u) ^ nm))       = h;
        *(__nv_bfloat16*)(bp + ((64u + (unsigned)kl * 2u) ^ nm)) = l;
    }
}

// ---------------- fp32 tiled GEMM helper (k1, k3) ----------------
template<int NTHREADS>
__device__ __forceinline__ void gemm_acc(
    const float* __restrict__ Asm, int astride, int kdim,
    const float* __restrict__ Wg, float* __restrict__ Wt,
    float acc[4][8], int tid)
{
#pragma unroll
    for (int t = 0; t < 4; t++)
#pragma unroll
        for (int j = 0; j < 8; j++) acc[t][j] = 0.f;
    const int tc = tid & 31, tok0 = (tid >> 5) * 4, col0 = tc * 8;
    const int nkt = kdim >> 4;
    for (int kt = 0; kt < nkt; ++kt) {
        const float4* src = reinterpret_cast<const float4*>(Wg + kt * 16 * DM);
#pragma unroll
        for (int f = tid; f < 1024; f += NTHREADS) {
            int row = f >> 6, c4 = f & 63;
            *reinterpret_cast<float4*>(Wt + row * WT_STRIDE + c4 * 4) = src[f];
        }
        __syncthreads();
#pragma unroll
        for (int kk4 = 0; kk4 < 4; ++kk4) {
            const int kbase = kt * 16 + kk4 * 4;
            float a_[4][4];
#pragma unroll
            for (int t = 0; t < 4; t++) {
                float4 v = *reinterpret_cast<const float4*>(Asm + (tok0 + t) * astride + kbase);
                a_[t][0]=v.x; a_[t][1]=v.y; a_[t][2]=v.z; a_[t][3]=v.w;
            }
#pragma unroll
            for (int r = 0; r < 4; r++) {
                const float4 w0 = *reinterpret_cast<const float4*>(Wt + (kk4*4+r)*WT_STRIDE + col0);
                const float4 w1 = *reinterpret_cast<const float4*>(Wt + (kk4*4+r)*WT_STRIDE + col0 + 4);
                float w[8] = {w0.x,w0.y,w0.z,w0.w,w1.x,w1.y,w1.z,w1.w};
#pragma unroll
                for (int t = 0; t < 4; t++) {
                    const float a = a_[t][r];
#pragma unroll
                    for (int j = 0; j < 8; j++) acc[t][j] = fmaf(a, w[j], acc[t][j]);
                }
            }
        }
        __syncthreads();
    }
}

// ---------------- k1 (unchanged) ----------------
__global__ void __launch_bounds__(256, 1) k1(
    const float* __restrict__ h_dyn, const float* __restrict__ W_dyn,
    const float* __restrict__ b_dyn, const float* __restrict__ g_ndyn,
    const float* __restrict__ b_ndyn, const float* __restrict__ Wq,
    const float* __restrict__ bq, const float* __restrict__ Wk,
    const float* __restrict__ bk)
{
    extern __shared__ float sm[];
    float* sm_hd  = sm;
    float* sm_h   = sm_hd + 32 * 512;
    float* sm_q   = sm_h  + 32 * 256;
    float* sm_wt  = sm_q  + 32 * 256;
    float* p_bdyn = sm_wt + 16 * WT_STRIDE;
    float* p_gn = p_bdyn + 256; float* p_bn = p_gn + 256;
    float* p_bq = p_bn + 256;   float* p_bk = p_bq + 256;

    const int tid = threadIdx.x;
    const int row0 = blockIdx.x * 32;
    {
        const float4* src = reinterpret_cast<const float4*>(h_dyn + (size_t)row0 * DDYN);
        for (int f = tid; f < 4096; f += 256) reinterpret_cast<float4*>(sm_hd)[f] = src[f];
    }
    if (tid < 64) {
        reinterpret_cast<float4*>(p_bdyn)[tid] = reinterpret_cast<const float4*>(b_dyn)[tid];
        reinterpret_cast<float4*>(p_gn)[tid]   = reinterpret_cast<const float4*>(g_ndyn)[tid];
        reinterpret_cast<float4*>(p_bn)[tid]   = reinterpret_cast<const float4*>(b_ndyn)[tid];
        reinterpret_cast<float4*>(p_bq)[tid]   = reinterpret_cast<const float4*>(bq)[tid];
        reinterpret_cast<float4*>(p_bk)[tid]   = reinterpret_cast<const float4*>(bk)[tid];
    }
    __syncthreads();

    float acc[4][8];
    gemm_acc<256>(sm_hd, 512, 512, W_dyn, sm_wt, acc, tid);
    {
        const int tc = tid & 31, tok0 = (tid >> 5) * 4, col0 = tc * 8;
#pragma unroll
        for (int t = 0; t < 4; t++) {
            float s = 0.f, s2 = 0.f;
#pragma unroll
            for (int j = 0; j < 8; j++) {
                float v = acc[t][j] + p_bdyn[col0 + j];
                acc[t][j] = v; s += v; s2 += v * v;
            }
            float* h0p = g_h0 + (size_t)(row0 + tok0 + t) * DM + col0;
            reinterpret_cast<float4*>(h0p)[0] = make_float4(acc[t][0],acc[t][1],acc[t][2],acc[t][3]);
            reinterpret_cast<float4*>(h0p)[1] = make_float4(acc[t][4],acc[t][5],acc[t][6],acc[t][7]);
#pragma unroll
            for (int off = 16; off; off >>= 1) {
                s  += __shfl_xor_sync(0xffffffffu, s,  off);
                s2 += __shfl_xor_sync(0xffffffffu, s2, off);
            }
            float mean = s * (1.f/256.f);
            float rstd = rsqrtf(s2 * (1.f/256.f) - mean*mean + LN_EPS);
#pragma unroll
            for (int j = 0; j < 8; j++)
                sm_h[(tok0+t)*DM + col0+j] = (acc[t][j]-mean)*rstd*p_gn[col0+j] + p_bn[col0+j];
        }
    }
    __syncthreads();

    gemm_acc<256>(sm_h, 256, 256, Wq, sm_wt, acc, tid);
    {
        const int tc = tid & 31, tok0 = (tid >> 5) * 4, col0 = tc * 8;
#pragma unroll
        for (int t = 0; t < 4; t++)
#pragma unroll
            for (int j = 0; j < 8; j++)
                sm_q[(tok0+t)*DM + col0+j] = acc[t][j] + p_bq[col0+j];
    }
    __syncthreads();

    for (int jt = 0; jt < 16; jt++) {
        const float4* src = reinterpret_cast<const float4*>(Wk + jt * 16 * DM);
        for (int f = tid; f < 1024; f += 256) {
            int r = f >> 6, c4 = f & 63;
            *reinterpret_cast<float4*>(sm_wt + r * WT_STRIDE + c4 * 4) = src[f];
        }
        __syncthreads();
        const int jl = tid & 15;
#pragma unroll
        for (int rr = 0; rr < 2; rr++) {
            const int r = (tid >> 4) + rr * 16;
            float ua[4];
#pragma unroll
            for (int h = 0; h < 4; h++) {
                float a = 0.f;
#pragma unroll
                for (int d4 = 0; d4 < 16; d4++) {
                    float4 qv = *reinterpret_cast<const float4*>(sm_q + r*DM + h*64 + d4*4);
                    float4 wv = *reinterpret_cast<const float4*>(sm_wt + jl*WT_STRIDE + h*64 + d4*4);
                    a += qv.x*wv.x + qv.y*wv.y + qv.z*wv.z + qv.w*wv.w;
                }
                ua[h] = a;
            }
            *reinterpret_cast<float4*>(g_u + (size_t)(row0+r)*1024 + (jt*16+jl)*4) =
                make_float4(ua[0], ua[1], ua[2], ua[3]);
        }
        __syncthreads();
    }
    if (tid < 128) {
        const int r = tid >> 2, h = tid & 3;
        float a = 0.f;
#pragma unroll
        for (int d = 0; d < 64; d++) a += sm_q[r*DM + h*64 + d] * p_bk[h*64 + d];
        g_qbk[(size_t)(row0+r)*4 + h] = a;
    }
}

// ---------------- k2m: HMMA fused token path (512 thr, 4x4 warp grid, ldmatrix) ----
#define O_AH   0
#define O_AL   65536
#define O_B0   131072
#define O_B1   163840
#define O_PB   196608
#define O_US   205824
#define O_PS   216064
#define O_LG   220160
#define O_WN   228352
#define O_TAIL 230400
#define SMEM2  230464

__device__ __forceinline__ void prefetch_chunk(char* buf, int g, int tid) {
    const char* src = (const char*)(g_B + (size_t)g * 2048);
    unsigned dst = smem_u32(buf);
#pragma unroll
    for (int i = 0; i < 4; i++) {
        int o = (tid + i * 512) * 16;
        asm volatile("cp.async.cg.shared.global [%0], [%1], 16;"
            :: "r"(dst + o), "l"(src + o) : "memory");
    }
    asm volatile("cp.async.commit_group;" ::: "memory");
}

// warp grid: 16 warps = 4 (wm, 32 rows) x 4 (wn4, 64 cols); ldmatrix fragment loads
__device__ __forceinline__ void gemm_tc(float acc[2][8][4],
    unsigned aHi, unsigned aLo, char* B0, char* B1,
    int g0, int nc, int wm, int wn4, int lane, int tid)
{
#pragma unroll
    for (int mt = 0; mt < 2; mt++)
#pragma unroll
        for (int nt = 0; nt < 8; nt++)
#pragma unroll
            for (int q = 0; q < 4; q++) acc[mt][nt][q] = 0.f;

    // A lane addressing (proven in R10): lanes 0-15 rows, k-seg = lane>>4
    const int aseg = lane >> 4;
    unsigned Arow[2], Axor[2];
#pragma unroll
    for (int mt = 0; mt < 2; mt++) {
        int row = wm * 32 + mt * 16 + (lane & 15);
        Arow[mt] = ((unsigned)(row >> 3) << 10) | ((unsigned)(row & 7) << 7);
        Axor[mt] = (unsigned)(row & 7) << 4;
    }
    // B lane addressing (proven in R10): pair p covers nt=2p,2p+1
    const unsigned bseg = (lane >> 3) & 1;
    unsigned Bn[4], Bx[4];
#pragma unroll
    for (int p = 0; p < 4; p++) {
        int n = wn4 * 64 + p * 16 + (lane >> 4) * 8 + (lane & 7);
        Bn[p] = (unsigned)n * 128u;
        Bx[p] = ((unsigned)n & 7u) << 4;
    }

    for (int kc = 0; kc < nc; kc++) {
        const int g = g0 + kc;
        asm volatile("cp.async.wait_group 0;" ::: "memory");
        __syncthreads();
        if (g + 1 < NCHUNK) prefetch_chunk(((g + 1) & 1) ? B1 : B0, g + 1, tid);
        const unsigned bbase = smem_u32((g & 1) ? B1 : B0);
#pragma unroll
        for (int ks = 0; ks < 2; ks++) {
            const int kl16 = kc * 2 + ks;
            const unsigned acol = ((unsigned)(kl16 >> 2) << 14);
            const unsigned asub = (unsigned)((kl16 & 3) * 32 + aseg * 16);
            unsigned ahi[2][4], alo[2][4];
#pragma unroll
            for (int mt = 0; mt < 2; mt++) {
                unsigned off = acol + Arow[mt] + (asub ^ Axor[mt]);
                ldsm4(ahi[mt], aHi + off);
                ldsm4(alo[mt], aLo + off);
            }
            const unsigned bsub = (unsigned)(ks * 32 + bseg * 16);
#pragma unroll
            for (int p = 0; p < 4; p++) {
                unsigned bhi[4], blo[4];
                ldsm4(bhi, bbase + Bn[p] + (bsub ^ Bx[p]));
                ldsm4(blo, bbase + Bn[p] + ((64u + bsub) ^ Bx[p]));
#pragma unroll
                for (int mt = 0; mt < 2; mt++) {
                    mma_bf16(acc[mt][2*p],   ahi[mt], bhi[0], bhi[1]);
                    mma_bf16(acc[mt][2*p],   ahi[mt], blo[0], blo[1]);
                    mma_bf16(acc[mt][2*p],   alo[mt], bhi[0], bhi[1]);
                    mma_bf16(acc[mt][2*p+1], ahi[mt], bhi[2], bhi[3]);
                    mma_bf16(acc[mt][2*p+1], ahi[mt], blo[2], blo[3]);
                    mma_bf16(acc[mt][2*p+1], alo[mt], bhi[2], bhi[3]);
                }
            }
        }
    }
    __syncthreads();
}

// LN epilogue on register fragments; optional logit partials (S1)
__device__ __forceinline__ void epi_ln_m(float acc[2][8][4],
    const float* bias, const float* gg, const float* bb,
    char* Ah, char* Al, float* ps, const float* us, float* lg,
    int wm, int wn4, int lane, bool do_logits)
{
    const int g8 = lane >> 2, tp = lane & 3;
    float s[4] = {0,0,0,0}, s2[4] = {0,0,0,0};
#pragma unroll
    for (int mt = 0; mt < 2; mt++)
#pragma unroll
        for (int nt = 0; nt < 8; nt++) {
            int C = wn4 * 64 + nt * 8 + tp * 2;
            float b0v = bias[C], b1v = bias[C + 1];
            float v0 = acc[mt][nt][0] + b0v, v1 = acc[mt][nt][1] + b1v;
            float v2 = acc[mt][nt][2] + b0v, v3 = acc[mt][nt][3] + b1v;
            acc[mt][nt][0]=v0; acc[mt][nt][1]=v1; acc[mt][nt][2]=v2; acc[mt][nt][3]=v3;
            s[mt*2]   += v0 + v1;  s2[mt*2]   += v0*v0 + v1*v1;
            s[mt*2+1] += v2 + v3;  s2[mt*2+1] += v2*v2 + v3*v3;
        }
#pragma unroll
    for (int off = 1; off <= 2; off <<= 1)
#pragma unroll
        for (int i = 0; i < 4; i++) {
            s[i]  += __shfl_xor_sync(0xffffffffu, s[i],  off);
            s2[i] += __shfl_xor_sync(0xffffffffu, s2[i], off);
        }
    if (tp == 0) {
#pragma unroll
        for (int i = 0; i < 4; i++) {
            int row = wm*32 + (i>>1)*16 + (i&1)*8 + g8;
            ps[(row*4 + wn4)*2]     = s[i];
            ps[(row*4 + wn4)*2 + 1] = s2[i];
        }
    }
    __syncthreads();
    float mean[4], rstd[4];
#pragma unroll
    for (int i = 0; i < 4; i++) {
        int row = wm*32 + (i>>1)*16 + (i&1)*8 + g8;
        float ss = 0.f, ss2 = 0.f;
#pragma unroll
        for (int x = 0; x < 4; x++) { ss += ps[(row*4+x)*2]; ss2 += ps[(row*4+x)*2+1]; }
        mean[i] = ss * (1.f/256.f);
        rstd[i] = rsqrtf(ss2 * (1.f/256.f) - mean[i]*mean[i] + LN_EPS);
    }
    float la[4][4];
    if (do_logits)
#pragma unroll
        for (int i = 0; i < 4; i++)
#pragma unroll
            for (int h = 0; h < 4; h++) la[i][h] = 0.f;
    const int half = wm >> 1;
#pragma unroll
    for (int mt = 0; mt < 2; mt++)
#pragma unroll
        for (int nt = 0; nt < 8; nt++) {
            int C = wn4 * 64 + nt * 8 + tp * 2;
            float g0 = gg[C], g1 = gg[C+1], e0 = bb[C], e1 = bb[C+1];
#pragma unroll
            for (int rh = 0; rh < 2; rh++) {
                int i = mt*2 + rh;
                int row = wm*32 + mt*16 + rh*8 + g8;
                float n0 = (acc[mt][nt][rh*2]   - mean[i]) * rstd[i] * g0 + e0;
                float n1 = (acc[mt][nt][rh*2+1] - mean[i]) * rstd[i] * g1 + e1;
                storeA2(Ah, Al, row, C, n0, n1);
                if (do_logits) {
                    float4 u0 = *(const float4*)(us + half*1024 + C*4);
                    float4 u1 = *(const float4*)(us + half*1024 + (C+1)*4);
                    la[i][0] += n0*u0.x + n1*u1.x;
                    la[i][1] += n0*u0.y + n1*u1.y;
                    la[i][2] += n0*u0.z + n1*u1.z;
                    la[i][3] += n0*u0.w + n1*u1.w;
                }
            }
        }
    if (do_logits) {
#pragma unroll
        for (int off = 1; off <= 2; off <<= 1)
#pragma unroll
            for (int i = 0; i < 4; i++)
#pragma unroll
                for (int h = 0; h < 4; h++)
                    la[i][h] += __shfl_xor_sync(0xffffffffu, la[i][h], off);
        if (tp == 0)
#pragma unroll
            for (int i = 0; i < 4; i++) {
                int row = wm*32 + (i>>1)*16 + (i&1)*8 + g8;
#pragma unroll
                for (int h = 0; h < 4; h++) lg[row*16 + wn4*4 + h] = la[i][h];
            }
    }
    __syncthreads();
}

__global__ void __launch_bounds__(512, 1) k2m(
    const float* __restrict__ x_stat,
    const float* __restrict__ b_stat, const float* __restrict__ g_nstat,
    const float* __restrict__ b_nstat, const float* __restrict__ bv,
    const float* __restrict__ g_mlp,  const float* __restrict__ b_mlp,
    const float* __restrict__ b1,     const float* __restrict__ b2,
    float* __restrict__ out)
{
    extern __shared__ char smc[];
    char*  Ah  = smc + O_AH;
    char*  Al  = smc + O_AL;
    char*  B0  = smc + O_B0;
    char*  B1  = smc + O_B1;
    float* pb  = (float*)(smc + O_PB);
    float* us  = (float*)(smc + O_US);
    float* ps  = (float*)(smc + O_PS);
    float* lg  = (float*)(smc + O_LG);
    float* zs  = (float*)(smc + O_LG);   // reuse after S1
    float* wns = (float*)(smc + O_WN);
    float* qbk = (float*)(smc + O_TAIL);
    float* ssm = (float*)(smc + O_TAIL + 32);

    const int tid = threadIdx.x, lane = tid & 31, w = tid >> 5;
    const int wm = w & 3, wn4 = w >> 2;
    const int g8 = lane >> 2, tp = lane & 3;
    const size_t b0 = (size_t)blockIdx.x * 2;
    const unsigned aHi = smem_u32(Ah), aLo = smem_u32(Al);

    prefetch_chunk(B0, 0, tid);

    // ---- cooperative staging ----
    for (int idx = tid; idx < 2048; idx += 512) {
        int rr = idx >> 4, c4 = (idx & 15) * 4;
        float4 v = *reinterpret_cast<const float4*>(
            x_stat + (b0 + (rr >> 6)) * 4096 + (size_t)(rr & 63) * 64 + c4);
        storeA2(Ah, Al, rr, c4,     v.x, v.y);
        storeA2(Ah, Al, rr, c4 + 2, v.z, v.w);
    }
    if (tid < 512)
        reinterpret_cast<float4*>(us)[tid] =
            reinterpret_cast<const float4*>(g_u + b0 * 1024)[tid];
    if (tid < 64) {
        reinterpret_cast<float4*>(pb + 0*256)[tid] = reinterpret_cast<const float4*>(b_stat)[tid];
        reinterpret_cast<float4*>(pb + 1*256)[tid] = reinterpret_cast<const float4*>(g_nstat)[tid];
        reinterpret_cast<float4*>(pb + 2*256)[tid] = reinterpret_cast<const float4*>(b_nstat)[tid];
        reinterpret_cast<float4*>(pb + 3*256)[tid] = reinterpret_cast<const float4*>(bv)[tid];
        reinterpret_cast<float4*>(pb + 4*256)[tid] = reinterpret_cast<const float4*>(g_mlp)[tid];
        reinterpret_cast<float4*>(pb + 5*256)[tid] = reinterpret_cast<const float4*>(b_mlp)[tid];
        reinterpret_cast<float4*>(pb + 6*256)[tid] = reinterpret_cast<const float4*>(b1)[tid];
        reinterpret_cast<float4*>(pb + 7*256)[tid] = reinterpret_cast<const float4*>(b2)[tid];
    }
    if (tid < 8) qbk[tid] = g_qbk[b0 * 4 + tid];

    float acc[2][8][4];

    // ---- S1: s = x_stat @ W_stat ; LN -> A ; logit partials (chunks 0-1) ----
    gemm_tc(acc, aHi, aLo, B0, B1, 0, 2, wm, wn4, lane, tid);
    epi_ln_m(acc, pb + 0*256, pb + 1*256, pb + 2*256, Ah, Al, ps, us, lg,
             wm, wn4, lane, true);

    // ---- logits -> sigmoid -> normalize -> w_mean ----
    {
        int row = tid >> 2, h = tid & 3;
        float lv = qbk[(row >> 6) * 4 + h];
#pragma unroll
        for (int x = 0; x < 4; x++) lv += lg[row*16 + x*4 + h];
        wns[tid] = 1.f / (1.f + expf(-lv * SCALE));
    }
    __syncthreads();
    if (tid < 8) {
        int half = tid >> 2, h = tid & 3;
        float sum = 0.f;
        for (int k = 0; k < 64; k++) sum += wns[(half*64 + k)*4 + h];
        ssm[tid] = sum + 1e-6f;
    }
    __syncthreads();
    wns[tid] = wns[tid] / ssm[(tid >> 8) * 4 + (tid & 3)];
    __syncthreads();
    if (tid < 128)
        out[(size_t)B_ROWS * DM + (b0 + (tid >> 6)) * 64 + (tid & 63)] =
            0.25f * (wns[tid*4] + wns[tid*4+1] + wns[tid*4+2] + wns[tid*4+3]);
    __syncthreads();

    // ---- S2: v = s @ Wv ; LN(g_mlp) -> A (chunks 2-9) ----
    gemm_tc(acc, aHi, aLo, B0, B1, 2, 8, wm, wn4, lane, tid);
    epi_ln_m(acc, pb + 3*256, pb + 4*256, pb + 5*256, Ah, Al, ps, us, lg,
             wm, wn4, lane, false);

    // ---- S3: t = gelu(v @ W1 + b1) -> A (chunks 10-17) ----
    gemm_tc(acc, aHi, aLo, B0, B1, 10, 8, wm, wn4, lane, tid);
#pragma unroll
    for (int mt = 0; mt < 2; mt++)
#pragma unroll
        for (int nt = 0; nt < 8; nt++) {
            int C = wn4 * 64 + nt * 8 + tp * 2;
            float e0 = pb[6*256 + C], e1 = pb[6*256 + C + 1];
#pragma unroll
            for (int rh = 0; rh < 2; rh++) {
                int row = wm*32 + mt*16 + rh*8 + g8;
                float x0 = acc[mt][nt][rh*2]   + e0;
                float x1 = acc[mt][nt][rh*2+1] + e1;
                float n0 = 0.5f * x0 * (1.f + erff(x0 * 0.70710678118f));
                float n1 = 0.5f * x1 * (1.f + erff(x1 * 0.70710678118f));
                storeA2(Ah, Al, row, C, n0, n1);
            }
        }
    __syncthreads();

    // ---- S4: vtok = t @ W2 + b2 ; weighted column sums -> z (chunks 18-25) ----
    gemm_tc(acc, aHi, aLo, B0, B1, 18, 8, wm, wn4, lane, tid);
    if (tid < 512) zs[tid] = 0.f;
    __syncthreads();
    {
        float za[8], zb[8];
#pragma unroll
        for (int nt = 0; nt < 8; nt++) { za[nt] = 0.f; zb[nt] = 0.f; }
#pragma unroll
        for (int mt = 0; mt < 2; mt++)
#pragma unroll
            for (int nt = 0; nt < 8; nt++) {
                int C = wn4 * 64 + nt * 8 + tp * 2;
                int hcol = C >> 6;
                float e0 = pb[7*256 + C], e1 = pb[7*256 + C + 1];
#pragma unroll
                for (int rh = 0; rh < 2; rh++) {
                    int row = wm*32 + mt*16 + rh*8 + g8;
                    float wf = wns[row*4 + hcol];
                    za[nt] += (acc[mt][nt][rh*2]   + e0) * wf;
                    zb[nt] += (acc[mt][nt][rh*2+1] + e1) * wf;
                }
            }
#pragma unroll
        for (int off = 4; off <= 16; off <<= 1)
#pragma unroll
            for (int nt = 0; nt < 8; nt++) {
                za[nt] += __shfl_xor_sync(0xffffffffu, za[nt], off);
                zb[nt] += __shfl_xor_sync(0xffffffffu, zb[nt], off);
            }
        if (lane < 4) {
            int half = wm >> 1;
#pragma unroll
            for (int nt = 0; nt < 8; nt++) {
                int C = wn4 * 64 + nt * 8 + lane * 2;
                atomicAdd(&zs[half*256 + C],     za[nt]);
                atomicAdd(&zs[half*256 + C + 1], zb[nt]);
            }
        }
    }
    __syncthreads();
    g_z[b0 * 256 + tid] = zs[tid];
}

// ---------------- k3: c = z @ Wo + bo ; out = h0 + rs*c ----------------
__global__ void __launch_bounds__(256, 1) k3(
    const float* __restrict__ Wo, const float* __restrict__ bo,
    const float* __restrict__ res_p, float* __restrict__ out)
{
    extern __shared__ float sm[];
    float* zsm = sm;
    float* Wt  = zsm + 32 * 256;
    float* pbo = Wt + 16 * WT_STRIDE;
    const int tid = threadIdx.x, row0 = blockIdx.x * 32;
    for (int f = tid; f < 2048; f += 256)
        reinterpret_cast<float4*>(zsm)[f] =
            reinterpret_cast<const float4*>(g_z + (size_t)row0 * 256)[f];
    if (tid < 64)
        reinterpret_cast<float4*>(pbo)[tid] = reinterpret_cast<const float4*>(bo)[tid];
    __syncthreads();
    float acc[4][8];
    gemm_acc<256>(zsm, 256, 256, Wo, Wt, acc, tid);
    const float rs = *res_p;
    const int tc = tid & 31, tok0 = (tid >> 5) * 4, col0 = tc * 8;
#pragma unroll
    for (int t = 0; t < 4; t++) {
        const size_t r = (size_t)(row0 + tok0 + t);
#pragma unroll
        for (int j = 0; j < 8; j++)
            out[r * 256 + col0 + j] =
                g_h0[r * 256 + col0 + j] + rs * (acc[t][j] + pbo[col0 + j]);
    }
}

// ============================================================
extern "C" void kernel_launch(void* const* d_in, const int* in_sizes, int n_in,
                              void* d_out, int out_size)
{
    const float* h_dyn   = (const float*)d_in[0];
    const float* x_stat  = (const float*)d_in[1];
    const float* W_dyn   = (const float*)d_in[2];
    const float* b_dyn   = (const float*)d_in[3];
    const float* W_stat  = (const float*)d_in[4];
    const float* b_stat  = (const float*)d_in[5];
    const float* g_ndyn  = (const float*)d_in[6];
    const float* b_ndyn  = (const float*)d_in[7];
    const float* g_nstat = (const float*)d_in[8];
    const float* b_nstat = (const float*)d_in[9];
    const float* Wq  = (const float*)d_in[10];
    const float* bq  = (const float*)d_in[11];
    const float* Wk  = (const float*)d_in[12];
    const float* bk  = (const float*)d_in[13];
    const float* Wv  = (const float*)d_in[14];
    const float* bv  = (const float*)d_in[15];
    const float* g_mlp = (const float*)d_in[16];
    const float* b_mlp = (const float*)d_in[17];
    const float* W1  = (const float*)d_in[18];
    const float* b1  = (const float*)d_in[19];
    const float* W2  = (const float*)d_in[20];
    const float* b2  = (const float*)d_in[21];
    const float* Wo  = (const float*)d_in[22];
    const float* bo  = (const float*)d_in[23];
    const float* res_sc = (const float*)d_in[24];
    float* out = (float*)d_out;

    const int SMEM1 = (32*512 + 32*256 + 32*256 + 16*WT_STRIDE + 5*256) * 4;
    const int SMEM3 = (32*256 + 16*WT_STRIDE + 256) * 4;
    cudaFuncSetAttribute(k1,  cudaFuncAttributeMaxDynamicSharedMemorySize, SMEM1);
    cudaFuncSetAttribute(k2m, cudaFuncAttributeMaxDynamicSharedMemorySize, SMEM2);
    cudaFuncSetAttribute(k3,  cudaFuncAttributeMaxDynamicSharedMemorySize, SMEM3);

    k0<<<NCHUNK, 256>>>(W_stat, Wv, W1, W2);
    k1<<<B_ROWS / 32, 256, SMEM1>>>(h_dyn, W_dyn, b_dyn, g_ndyn, b_ndyn, Wq, bq, Wk, bk);
    k2m<<<B_ROWS / 2, 512, SMEM2>>>(x_stat, b_stat, g_nstat, b_nstat, bv,
                                    g_mlp, b_mlp, b1, b2, out);
    k3<<<B_ROWS / 32, 256, SMEM3>>>(Wo, bo, res_sc, out);
}

// round 12
// speedup vs baseline: 1.4309x; 1.2464x over previous
#include <cuda_runtime.h>
#include <cuda_fp16.h>
#include <math.h>
#include <stdint.h>

#define B_ROWS 4096
#define DM     256
#define DDYN   512
#define SCALE  0.125f
#define LN_EPS 1e-5f
#define WT_STRIDE 260
#define NCHUNK 13

// ---------------- device scratch ----------------
__device__ float g_h0 [B_ROWS * DM];
__device__ float g_u  [B_ROWS * DM * 4];
__device__ float g_qbk[B_ROWS * 4];
__device__ float g_z  [B_ROWS * DM];
// 13 chunks (Wstat 1, Wv 4, W1 4, W2 4): [256 n][64 k fp16 = 128B row, XOR-8 swizzle]
__device__ uint4 g_B[NCHUNK * 2048];

__device__ __forceinline__ uint32_t smem_u32(const void* p) {
    uint32_t a;
    asm("{ .reg .u64 t; cvta.to.shared.u64 t, %1; cvt.u32.u64 %0, t; }" : "=r"(a) : "l"(p));
    return a;
}

// ---------------- mma / ldmatrix ----------------
__device__ __forceinline__ void mma_f16(float* d, const unsigned* a, unsigned b0, unsigned b1) {
    asm volatile("mma.sync.aligned.m16n8k16.row.col.f32.f16.f16.f32 "
        "{%0,%1,%2,%3}, {%4,%5,%6,%7}, {%8,%9}, {%0,%1,%2,%3};"
        : "+f"(d[0]), "+f"(d[1]), "+f"(d[2]), "+f"(d[3])
        : "r"(a[0]), "r"(a[1]), "r"(a[2]), "r"(a[3]), "r"(b0), "r"(b1));
}
__device__ __forceinline__ void ldsm4(unsigned* r, unsigned addr) {
    asm volatile("ldmatrix.sync.aligned.m8n8.x4.shared.b16 {%0,%1,%2,%3}, [%4];"
        : "=r"(r[0]), "=r"(r[1]), "=r"(r[2]), "=r"(r[3]) : "r"(addr));
}

// A smem layout: blocked atoms 8 rows x 64 cols (1KB), atom = (row>>3) + (col>>6)*16
// fp16 2-term split: A = Ah + Al
__device__ __forceinline__ void storeA2(char* Ah, char* Al, int row, int col,
                                        float v0, float v1) {
    unsigned byte = ((unsigned)(row >> 3) << 10) + ((unsigned)(col >> 6) << 14)
                  + ((unsigned)(row & 7) << 7)
                  + ((((unsigned)(col & 63)) * 2u) ^ (((unsigned)(row & 7)) << 4));
    __half h0 = __float2half_rn(v0), h1 = __float2half_rn(v1);
    *(unsigned*)(Ah + byte) = (unsigned)__half_as_ushort(h0) |
                              ((unsigned)__half_as_ushort(h1) << 16);
    __half l0 = __float2half_rn(v0 - __half2float(h0));
    __half l1 = __float2half_rn(v1 - __half2float(h1));
    *(unsigned*)(Al + byte) = (unsigned)__half_as_ushort(l0) |
                              ((unsigned)__half_as_ushort(l1) << 16);
}

// ---------------- k0: weights -> single-fp16 swizzled chunk images ----------------
__global__ void k0(const float* __restrict__ Ws, const float* __restrict__ Wv,
                   const float* __restrict__ W1, const float* __restrict__ W2) {
    const int c = blockIdx.x, n = threadIdx.x;   // c: 0..12, n: 0..255
    const float* W; int kbase;
    if (c == 0)      { W = Ws; kbase = 0; }
    else if (c <= 4) { W = Wv; kbase = (c - 1) * 64; }
    else if (c <= 8) { W = W1; kbase = (c - 5) * 64; }
    else             { W = W2; kbase = (c - 9) * 64; }
    char* bp = (char*)(g_B + (size_t)c * 2048) + n * 128;
    const unsigned nm = ((unsigned)n & 7u) << 4;
    for (int kl = 0; kl < 64; kl++) {
        float v = W[(size_t)(kbase + kl) * 256 + n];
        *(__half*)(bp + (((unsigned)kl * 2u) ^ nm)) = __float2half_rn(v);
    }
}

// ---------------- fp32 tiled GEMM helper (k1, k3) ----------------
template<int NTHREADS>
__device__ __forceinline__ void gemm_acc(
    const float* __restrict__ Asm, int astride, int kdim,
    const float* __restrict__ Wg, float* __restrict__ Wt,
    float acc[4][8], int tid)
{
#pragma unroll
    for (int t = 0; t < 4; t++)
#pragma unroll
        for (int j = 0; j < 8; j++) acc[t][j] = 0.f;
    const int tc = tid & 31, tok0 = (tid >> 5) * 4, col0 = tc * 8;
    const int nkt = kdim >> 4;
    for (int kt = 0; kt < nkt; ++kt) {
        const float4* src = reinterpret_cast<const float4*>(Wg + kt * 16 * DM);
#pragma unroll
        for (int f = tid; f < 1024; f += NTHREADS) {
            int row = f >> 6, c4 = f & 63;
            *reinterpret_cast<float4*>(Wt + row * WT_STRIDE + c4 * 4) = src[f];
        }
        __syncthreads();
#pragma unroll
        for (int kk4 = 0; kk4 < 4; ++kk4) {
            const int kbase = kt * 16 + kk4 * 4;
            float a_[4][4];
#pragma unroll
            for (int t = 0; t < 4; t++) {
                float4 v = *reinterpret_cast<const float4*>(Asm + (tok0 + t) * astride + kbase);
                a_[t][0]=v.x; a_[t][1]=v.y; a_[t][2]=v.z; a_[t][3]=v.w;
            }
#pragma unroll
            for (int r = 0; r < 4; r++) {
                const float4 w0 = *reinterpret_cast<const float4*>(Wt + (kk4*4+r)*WT_STRIDE + col0);
                const float4 w1 = *reinterpret_cast<const float4*>(Wt + (kk4*4+r)*WT_STRIDE + col0 + 4);
                float w[8] = {w0.x,w0.y,w0.z,w0.w,w1.x,w1.y,w1.z,w1.w};
#pragma unroll
                for (int t = 0; t < 4; t++) {
                    const float a = a_[t][r];
#pragma unroll
                    for (int j = 0; j < 8; j++) acc[t][j] = fmaf(a, w[j], acc[t][j]);
                }
            }
        }
        __syncthreads();
    }
}

// ---------------- k1 (unchanged) ----------------
__global__ void __launch_bounds__(256, 1) k1(
    const float* __restrict__ h_dyn, const float* __restrict__ W_dyn,
    const float* __restrict__ b_dyn, const float* __restrict__ g_ndyn,
    const float* __restrict__ b_ndyn, const float* __restrict__ Wq,
    const float* __restrict__ bq, const float* __restrict__ Wk,
    const float* __restrict__ bk)
{
    extern __shared__ float sm[];
    float* sm_hd  = sm;
    float* sm_h   = sm_hd + 32 * 512;
    float* sm_q   = sm_h  + 32 * 256;
    float* sm_wt  = sm_q  + 32 * 256;
    float* p_bdyn = sm_wt + 16 * WT_STRIDE;
    float* p_gn = p_bdyn + 256; float* p_bn = p_gn + 256;
    float* p_bq = p_bn + 256;   float* p_bk = p_bq + 256;

    const int tid = threadIdx.x;
    const int row0 = blockIdx.x * 32;
    {
        const float4* src = reinterpret_cast<const float4*>(h_dyn + (size_t)row0 * DDYN);
        for (int f = tid; f < 4096; f += 256) reinterpret_cast<float4*>(sm_hd)[f] = src[f];
    }
    if (tid < 64) {
        reinterpret_cast<float4*>(p_bdyn)[tid] = reinterpret_cast<const float4*>(b_dyn)[tid];
        reinterpret_cast<float4*>(p_gn)[tid]   = reinterpret_cast<const float4*>(g_ndyn)[tid];
        reinterpret_cast<float4*>(p_bn)[tid]   = reinterpret_cast<const float4*>(b_ndyn)[tid];
        reinterpret_cast<float4*>(p_bq)[tid]   = reinterpret_cast<const float4*>(bq)[tid];
        reinterpret_cast<float4*>(p_bk)[tid]   = reinterpret_cast<const float4*>(bk)[tid];
    }
    __syncthreads();

    float acc[4][8];
    gemm_acc<256>(sm_hd, 512, 512, W_dyn, sm_wt, acc, tid);
    {
        const int tc = tid & 31, tok0 = (tid >> 5) * 4, col0 = tc * 8;
#pragma unroll
        for (int t = 0; t < 4; t++) {
            float s = 0.f, s2 = 0.f;
#pragma unroll
            for (int j = 0; j < 8; j++) {
                float v = acc[t][j] + p_bdyn[col0 + j];
                acc[t][j] = v; s += v; s2 += v * v;
            }
            float* h0p = g_h0 + (size_t)(row0 + tok0 + t) * DM + col0;
            reinterpret_cast<float4*>(h0p)[0] = make_float4(acc[t][0],acc[t][1],acc[t][2],acc[t][3]);
            reinterpret_cast<float4*>(h0p)[1] = make_float4(acc[t][4],acc[t][5],acc[t][6],acc[t][7]);
#pragma unroll
            for (int off = 16; off; off >>= 1) {
                s  += __shfl_xor_sync(0xffffffffu, s,  off);
                s2 += __shfl_xor_sync(0xffffffffu, s2, off);
            }
            float mean = s * (1.f/256.f);
            float rstd = rsqrtf(s2 * (1.f/256.f) - mean*mean + LN_EPS);
#pragma unroll
            for (int j = 0; j < 8; j++)
                sm_h[(tok0+t)*DM + col0+j] = (acc[t][j]-mean)*rstd*p_gn[col0+j] + p_bn[col0+j];
        }
    }
    __syncthreads();

    gemm_acc<256>(sm_h, 256, 256, Wq, sm_wt, acc, tid);
    {
        const int tc = tid & 31, tok0 = (tid >> 5) * 4, col0 = tc * 8;
#pragma unroll
        for (int t = 0; t < 4; t++)
#pragma unroll
            for (int j = 0; j < 8; j++)
                sm_q[(tok0+t)*DM + col0+j] = acc[t][j] + p_bq[col0+j];
    }
    __syncthreads();

    for (int jt = 0; jt < 16; jt++) {
        const float4* src = reinterpret_cast<const float4*>(Wk + jt * 16 * DM);
        for (int f = tid; f < 1024; f += 256) {
            int r = f >> 6, c4 = f & 63;
            *reinterpret_cast<float4*>(sm_wt + r * WT_STRIDE + c4 * 4) = src[f];
        }
        __syncthreads();
        const int jl = tid & 15;
#pragma unroll
        for (int rr = 0; rr < 2; rr++) {
            const int r = (tid >> 4) + rr * 16;
            float ua[4];
#pragma unroll
            for (int h = 0; h < 4; h++) {
                float a = 0.f;
#pragma unroll
                for (int d4 = 0; d4 < 16; d4++) {
                    float4 qv = *reinterpret_cast<const float4*>(sm_q + r*DM + h*64 + d4*4);
                    float4 wv = *reinterpret_cast<const float4*>(sm_wt + jl*WT_STRIDE + h*64 + d4*4);
                    a += qv.x*wv.x + qv.y*wv.y + qv.z*wv.z + qv.w*wv.w;
                }
                ua[h] = a;
            }
            *reinterpret_cast<float4*>(g_u + (size_t)(row0+r)*1024 + (jt*16+jl)*4) =
                make_float4(ua[0], ua[1], ua[2], ua[3]);
        }
        __syncthreads();
    }
    if (tid < 128) {
        const int r = tid >> 2, h = tid & 3;
        float a = 0.f;
#pragma unroll
        for (int d = 0; d < 64; d++) a += sm_q[r*DM + h*64 + d] * p_bk[h*64 + d];
        g_qbk[(size_t)(row0+r)*4 + h] = a;
    }
}

// ---------------- k2m: HMMA fused token path (fp16 2-term, 13 chunks) ----------------
#define O_AH   0
#define O_AL   65536
#define O_B0   131072
#define O_B1   163840
#define O_PB   196608
#define O_US   205824
#define O_PS   216064
#define O_LG   220160
#define O_WN   228352
#define O_TAIL 230400
#define SMEM2  230464

__device__ __forceinline__ void prefetch_chunk(char* buf, int g, int tid) {
    const char* src = (const char*)(g_B + (size_t)g * 2048);
    unsigned dst = smem_u32(buf);
#pragma unroll
    for (int i = 0; i < 4; i++) {
        int o = (tid + i * 512) * 16;
        asm volatile("cp.async.cg.shared.global [%0], [%1], 16;"
            :: "r"(dst + o), "l"(src + o) : "memory");
    }
    asm volatile("cp.async.commit_group;" ::: "memory");
}

// warp grid: 16 warps = 4 (wm, 32 rows) x 4 (wn4, 64 cols); each chunk covers 64 k
__device__ __forceinline__ void gemm_tc(float acc[2][8][4],
    unsigned aHi, unsigned aLo, char* B0, char* B1,
    int g0, int nc, int wm, int wn4, int lane, int tid)
{
#pragma unroll
    for (int mt = 0; mt < 2; mt++)
#pragma unroll
        for (int nt = 0; nt < 8; nt++)
#pragma unroll
            for (int q = 0; q < 4; q++) acc[mt][nt][q] = 0.f;

    const int aseg = lane >> 4;
    unsigned Arow[2], Axor[2];
#pragma unroll
    for (int mt = 0; mt < 2; mt++) {
        int row = wm * 32 + mt * 16 + (lane & 15);
        Arow[mt] = ((unsigned)(row >> 3) << 10) | ((unsigned)(row & 7) << 7);
        Axor[mt] = (unsigned)(row & 7) << 4;
    }
    const unsigned bseg = (lane >> 3) & 1;
    unsigned Bn[4], Bx[4];
#pragma unroll
    for (int p = 0; p < 4; p++) {
        int n = wn4 * 64 + p * 16 + (lane >> 4) * 8 + (lane & 7);
        Bn[p] = (unsigned)n * 128u;
        Bx[p] = ((unsigned)n & 7u) << 4;
    }

    for (int kc = 0; kc < nc; kc++) {
        const int g = g0 + kc;
        asm volatile("cp.async.wait_group 0;" ::: "memory");
        __syncthreads();
        if (g + 1 < NCHUNK) prefetch_chunk(((g + 1) & 1) ? B1 : B0, g + 1, tid);
        const unsigned bbase = smem_u32((g & 1) ? B1 : B0);
        // chunk g covers A atom-col (g - g0 within stage) = kc, 4 k16 steps
        const unsigned acol = (unsigned)kc << 14;
#pragma unroll
        for (int ks = 0; ks < 4; ks++) {
            const unsigned asub = (unsigned)(ks * 32 + aseg * 16);
            unsigned ahi[2][4], alo[2][4];
#pragma unroll
            for (int mt = 0; mt < 2; mt++) {
                unsigned off = acol + Arow[mt] + (asub ^ Axor[mt]);
                ldsm4(ahi[mt], aHi + off);
                ldsm4(alo[mt], aLo + off);
            }
            const unsigned bsub = (unsigned)(ks * 32 + bseg * 16);
#pragma unroll
            for (int p = 0; p < 4; p++) {
                unsigned b[4];
                ldsm4(b, bbase + Bn[p] + (bsub ^ Bx[p]));
#pragma unroll
                for (int mt = 0; mt < 2; mt++) {
                    mma_f16(acc[mt][2*p],   ahi[mt], b[0], b[1]);
                    mma_f16(acc[mt][2*p],   alo[mt], b[0], b[1]);
                    mma_f16(acc[mt][2*p+1], ahi[mt], b[2], b[3]);
                    mma_f16(acc[mt][2*p+1], alo[mt], b[2], b[3]);
                }
            }
        }
    }
    __syncthreads();
}

// LN epilogue on register fragments; optional logit partials (S1)
__device__ __forceinline__ void epi_ln_m(float acc[2][8][4],
    const float* bias, const float* gg, const float* bb,
    char* Ah, char* Al, float* ps, const float* us, float* lg,
    int wm, int wn4, int lane, bool do_logits)
{
    const int g8 = lane >> 2, tp = lane & 3;
    float s[4] = {0,0,0,0}, s2[4] = {0,0,0,0};
#pragma unroll
    for (int mt = 0; mt < 2; mt++)
#pragma unroll
        for (int nt = 0; nt < 8; nt++) {
            int C = wn4 * 64 + nt * 8 + tp * 2;
            float b0v = bias[C], b1v = bias[C + 1];
            float v0 = acc[mt][nt][0] + b0v, v1 = acc[mt][nt][1] + b1v;
            float v2 = acc[mt][nt][2] + b0v, v3 = acc[mt][nt][3] + b1v;
            acc[mt][nt][0]=v0; acc[mt][nt][1]=v1; acc[mt][nt][2]=v2; acc[mt][nt][3]=v3;
            s[mt*2]   += v0 + v1;  s2[mt*2]   += v0*v0 + v1*v1;
            s[mt*2+1] += v2 + v3;  s2[mt*2+1] += v2*v2 + v3*v3;
        }
#pragma unroll
    for (int off = 1; off <= 2; off <<= 1)
#pragma unroll
        for (int i = 0; i < 4; i++) {
            s[i]  += __shfl_xor_sync(0xffffffffu, s[i],  off);
            s2[i] += __shfl_xor_sync(0xffffffffu, s2[i], off);
        }
    if (tp == 0) {
#pragma unroll
        for (int i = 0; i < 4; i++) {
            int row = wm*32 + (i>>1)*16 + (i&1)*8 + g8;
            ps[(row*4 + wn4)*2]     = s[i];
            ps[(row*4 + wn4)*2 + 1] = s2[i];
        }
    }
    __syncthreads();
    float mean[4], rstd[4];
#pragma unroll
    for (int i = 0; i < 4; i++) {
        int row = wm*32 + (i>>1)*16 + (i&1)*8 + g8;
        float ss = 0.f, ss2 = 0.f;
#pragma unroll
        for (int x = 0; x < 4; x++) { ss += ps[(row*4+x)*2]; ss2 += ps[(row*4+x)*2+1]; }
        mean[i] = ss * (1.f/256.f);
        rstd[i] = rsqrtf(ss2 * (1.f/256.f) - mean[i]*mean[i] + LN_EPS);
    }
    float la[4][4];
    if (do_logits)
#pragma unroll
        for (int i = 0; i < 4; i++)
#pragma unroll
            for (int h = 0; h < 4; h++) la[i][h] = 0.f;
    const int half = wm >> 1;
#pragma unroll
    for (int mt = 0; mt < 2; mt++)
#pragma unroll
        for (int nt = 0; nt < 8; nt++) {
            int C = wn4 * 64 + nt * 8 + tp * 2;
            float g0 = gg[C], g1 = gg[C+1], e0 = bb[C], e1 = bb[C+1];
#pragma unroll
            for (int rh = 0; rh < 2; rh++) {
                int i = mt*2 + rh;
                int row = wm*32 + mt*16 + rh*8 + g8;
                float n0 = (acc[mt][nt][rh*2]   - mean[i]) * rstd[i] * g0 + e0;
                float n1 = (acc[mt][nt][rh*2+1] - mean[i]) * rstd[i] * g1 + e1;
                storeA2(Ah, Al, row, C, n0, n1);
                if (do_logits) {
                    float4 u0 = *(const float4*)(us + half*1024 + C*4);
                    float4 u1 = *(const float4*)(us + half*1024 + (C+1)*4);
                    la[i][0] += n0*u0.x + n1*u1.x;
                    la[i][1] += n0*u0.y + n1*u1.y;
                    la[i][2] += n0*u0.z + n1*u1.z;
                    la[i][3] += n0*u0.w + n1*u1.w;
                }
            }
        }
    if (do_logits) {
#pragma unroll
        for (int off = 1; off <= 2; off <<= 1)
#pragma unroll
            for (int i = 0; i < 4; i++)
#pragma unroll
                for (int h = 0; h < 4; h++)
                    la[i][h] += __shfl_xor_sync(0xffffffffu, la[i][h], off);
        if (tp == 0)
#pragma unroll
            for (int i = 0; i < 4; i++) {
                int row = wm*32 + (i>>1)*16 + (i&1)*8 + g8;
#pragma unroll
                for (int h = 0; h < 4; h++) lg[row*16 + wn4*4 + h] = la[i][h];
            }
    }
    __syncthreads();
}

__global__ void __launch_bounds__(512, 1) k2m(
    const float* __restrict__ x_stat,
    const float* __restrict__ b_stat, const float* __restrict__ g_nstat,
    const float* __restrict__ b_nstat, const float* __restrict__ bv,
    const float* __restrict__ g_mlp,  const float* __restrict__ b_mlp,
    const float* __restrict__ b1,     const float* __restrict__ b2,
    float* __restrict__ out)
{
    extern __shared__ char smc[];
    char*  Ah  = smc + O_AH;
    char*  Al  = smc + O_AL;
    char*  B0  = smc + O_B0;
    char*  B1  = smc + O_B1;
    float* pb  = (float*)(smc + O_PB);
    float* us  = (float*)(smc + O_US);
    float* ps  = (float*)(smc + O_PS);
    float* lg  = (float*)(smc + O_LG);
    float* zs  = (float*)(smc + O_LG);   // reuse after S1
    float* wns = (float*)(smc + O_WN);
    float* qbk = (float*)(smc + O_TAIL);
    float* ssm = (float*)(smc + O_TAIL + 32);

    const int tid = threadIdx.x, lane = tid & 31, w = tid >> 5;
    const int wm = w & 3, wn4 = w >> 2;
    const int g8 = lane >> 2, tp = lane & 3;
    const size_t b0 = (size_t)blockIdx.x * 2;
    const unsigned aHi = smem_u32(Ah), aLo = smem_u32(Al);

    prefetch_chunk(B0, 0, tid);

    // ---- cooperative staging ----
    for (int idx = tid; idx < 2048; idx += 512) {
        int rr = idx >> 4, c4 = (idx & 15) * 4;
        float4 v = *reinterpret_cast<const float4*>(
            x_stat + (b0 + (rr >> 6)) * 4096 + (size_t)(rr & 63) * 64 + c4);
        storeA2(Ah, Al, rr, c4,     v.x, v.y);
        storeA2(Ah, Al, rr, c4 + 2, v.z, v.w);
    }
    if (tid < 512)
        reinterpret_cast<float4*>(us)[tid] =
            reinterpret_cast<const float4*>(g_u + b0 * 1024)[tid];
    if (tid < 64) {
        reinterpret_cast<float4*>(pb + 0*256)[tid] = reinterpret_cast<const float4*>(b_stat)[tid];
        reinterpret_cast<float4*>(pb + 1*256)[tid] = reinterpret_cast<const float4*>(g_nstat)[tid];
        reinterpret_cast<float4*>(pb + 2*256)[tid] = reinterpret_cast<const float4*>(b_nstat)[tid];
        reinterpret_cast<float4*>(pb + 3*256)[tid] = reinterpret_cast<const float4*>(bv)[tid];
        reinterpret_cast<float4*>(pb + 4*256)[tid] = reinterpret_cast<const float4*>(g_mlp)[tid];
        reinterpret_cast<float4*>(pb + 5*256)[tid] = reinterpret_cast<const float4*>(b_mlp)[tid];
        reinterpret_cast<float4*>(pb + 6*256)[tid] = reinterpret_cast<const float4*>(b1)[tid];
        reinterpret_cast<float4*>(pb + 7*256)[tid] = reinterpret_cast<const float4*>(b2)[tid];
    }
    if (tid < 8) qbk[tid] = g_qbk[b0 * 4 + tid];

    float acc[2][8][4];

    // ---- S1: s = x_stat @ W_stat ; LN -> A ; logit partials (chunk 0) ----
    gemm_tc(acc, aHi, aLo, B0, B1, 0, 1, wm, wn4, lane, tid);
    epi_ln_m(acc, pb + 0*256, pb + 1*256, pb + 2*256, Ah, Al, ps, us, lg,
             wm, wn4, lane, true);

    // ---- logits -> sigmoid -> normalize -> w_mean ----
    {
        int row = tid >> 2, h = tid & 3;
        float lv = qbk[(row >> 6) * 4 + h];
#pragma unroll
        for (int x = 0; x < 4; x++) lv += lg[row*16 + x*4 + h];
        wns[tid] = 1.f / (1.f + expf(-lv * SCALE));
    }
    __syncthreads();
    if (tid < 8) {
        int half = tid >> 2, h = tid & 3;
        float sum = 0.f;
        for (int k = 0; k < 64; k++) sum += wns[(half*64 + k)*4 + h];
        ssm[tid] = sum + 1e-6f;
    }
    __syncthreads();
    wns[tid] = wns[tid] / ssm[(tid >> 8) * 4 + (tid & 3)];
    __syncthreads();
    if (tid < 128)
        out[(size_t)B_ROWS * DM + (b0 + (tid >> 6)) * 64 + (tid & 63)] =
            0.25f * (wns[tid*4] + wns[tid*4+1] + wns[tid*4+2] + wns[tid*4+3]);
    __syncthreads();

    // ---- S2: v = s @ Wv ; LN(g_mlp) -> A (chunks 1-4) ----
    gemm_tc(acc, aHi, aLo, B0, B1, 1, 4, wm, wn4, lane, tid);
    epi_ln_m(acc, pb + 3*256, pb + 4*256, pb + 5*256, Ah, Al, ps, us, lg,
             wm, wn4, lane, false);

    // ---- S3: t = gelu(v @ W1 + b1) -> A (chunks 5-8) ----
    gemm_tc(acc, aHi, aLo, B0, B1, 5, 4, wm, wn4, lane, tid);
#pragma unroll
    for (int mt = 0; mt < 2; mt++)
#pragma unroll
        for (int nt = 0; nt < 8; nt++) {
            int C = wn4 * 64 + nt * 8 + tp * 2;
            float e0 = pb[6*256 + C], e1 = pb[6*256 + C + 1];
#pragma unroll
            for (int rh = 0; rh < 2; rh++) {
                int row = wm*32 + mt*16 + rh*8 + g8;
                float x0 = acc[mt][nt][rh*2]   + e0;
                float x1 = acc[mt][nt][rh*2+1] + e1;
                float n0 = 0.5f * x0 * (1.f + erff(x0 * 0.70710678118f));
                float n1 = 0.5f * x1 * (1.f + erff(x1 * 0.70710678118f));
                storeA2(Ah, Al, row, C, n0, n1);
            }
        }
    __syncthreads();

    // ---- S4: vtok = t @ W2 + b2 ; weighted column sums -> z (chunks 9-12) ----
    gemm_tc(acc, aHi, aLo, B0, B1, 9, 4, wm, wn4, lane, tid);
    if (tid < 512) zs[tid] = 0.f;
    __syncthreads();
    {
        float za[8], zb[8];
#pragma unroll
        for (int nt = 0; nt < 8; nt++) { za[nt] = 0.f; zb[nt] = 0.f; }
#pragma unroll
        for (int mt = 0; mt < 2; mt++)
#pragma unroll
            for (int nt = 0; nt < 8; nt++) {
                int C = wn4 * 64 + nt * 8 + tp * 2;
                int hcol = C >> 6;
                float e0 = pb[7*256 + C], e1 = pb[7*256 + C + 1];
#pragma unroll
                for (int rh = 0; rh < 2; rh++) {
                    int row = wm*32 + mt*16 + rh*8 + g8;
                    float wf = wns[row*4 + hcol];
                    za[nt] += (acc[mt][nt][rh*2]   + e0) * wf;
                    zb[nt] += (acc[mt][nt][rh*2+1] + e1) * wf;
                }
            }
#pragma unroll
        for (int off = 4; off <= 16; off <<= 1)
#pragma unroll
            for (int nt = 0; nt < 8; nt++) {
                za[nt] += __shfl_xor_sync(0xffffffffu, za[nt], off);
                zb[nt] += __shfl_xor_sync(0xffffffffu, zb[nt], off);
            }
        if (lane < 4) {
            int half = wm >> 1;
#pragma unroll
            for (int nt = 0; nt < 8; nt++) {
                int C = wn4 * 64 + nt * 8 + lane * 2;
                atomicAdd(&zs[half*256 + C],     za[nt]);
                atomicAdd(&zs[half*256 + C + 1], zb[nt]);
            }
        }
    }
    __syncthreads();
    g_z[b0 * 256 + tid] = zs[tid];
}

// ---------------- k3: c = z @ Wo + bo ; out = h0 + rs*c ----------------
__global__ void __launch_bounds__(256, 1) k3(
    const float* __restrict__ Wo, const float* __restrict__ bo,
    const float* __restrict__ res_p, float* __restrict__ out)
{
    extern __shared__ float sm[];
    float* zsm = sm;
    float* Wt  = zsm + 32 * 256;
    float* pbo = Wt + 16 * WT_STRIDE;
    const int tid = threadIdx.x, row0 = blockIdx.x * 32;
    for (int f = tid; f < 2048; f += 256)
        reinterpret_cast<float4*>(zsm)[f] =
            reinterpret_cast<const float4*>(g_z + (size_t)row0 * 256)[f];
    if (tid < 64)
        reinterpret_cast<float4*>(pbo)[tid] = reinterpret_cast<const float4*>(bo)[tid];
    __syncthreads();
    float acc[4][8];
    gemm_acc<256>(zsm, 256, 256, Wo, Wt, acc, tid);
    const float rs = *res_p;
    const int tc = tid & 31, tok0 = (tid >> 5) * 4, col0 = tc * 8;
#pragma unroll
    for (int t = 0; t < 4; t++) {
        const size_t r = (size_t)(row0 + tok0 + t);
#pragma unroll
        for (int j = 0; j < 8; j++)
            out[r * 256 + col0 + j] =
                g_h0[r * 256 + col0 + j] + rs * (acc[t][j] + pbo[col0 + j]);
    }
}

// ============================================================
extern "C" void kernel_launch(void* const* d_in, const int* in_sizes, int n_in,
                              void* d_out, int out_size)
{
    const float* h_dyn   = (const float*)d_in[0];
    const float* x_stat  = (const float*)d_in[1];
    const float* W_dyn   = (const float*)d_in[2];
    const float* b_dyn   = (const float*)d_in[3];
    const float* W_stat  = (const float*)d_in[4];
    const float* b_stat  = (const float*)d_in[5];
    const float* g_ndyn  = (const float*)d_in[6];
    const float* b_ndyn  = (const float*)d_in[7];
    const float* g_nstat = (const float*)d_in[8];
    const float* b_nstat = (const float*)d_in[9];
    const float* Wq  = (const float*)d_in[10];
    const float* bq  = (const float*)d_in[11];
    const float* Wk  = (const float*)d_in[12];
    const float* bk  = (const float*)d_in[13];
    const float* Wv  = (const float*)d_in[14];
    const float* bv  = (const float*)d_in[15];
    const float* g_mlp = (const float*)d_in[16];
    const float* b_mlp = (const float*)d_in[17];
    const float* W1  = (const float*)d_in[18];
    const float* b1  = (const float*)d_in[19];
    const float* W2  = (const float*)d_in[20];
    const float* b2  = (const float*)d_in[21];
    const float* Wo  = (const float*)d_in[22];
    const float* bo  = (const float*)d_in[23];
    const float* res_sc = (const float*)d_in[24];
    float* out = (float*)d_out;

    const int SMEM1 = (32*512 + 32*256 + 32*256 + 16*WT_STRIDE + 5*256) * 4;
    const int SMEM3 = (32*256 + 16*WT_STRIDE + 256) * 4;
    cudaFuncSetAttribute(k1,  cudaFuncAttributeMaxDynamicSharedMemorySize, SMEM1);
    cudaFuncSetAttribute(k2m, cudaFuncAttributeMaxDynamicSharedMemorySize, SMEM2);
    cudaFuncSetAttribute(k3,  cudaFuncAttributeMaxDynamicSharedMemorySize, SMEM3);

    k0<<<NCHUNK, 256>>>(W_stat, Wv, W1, W2);
    k1<<<B_ROWS / 32, 256, SMEM1>>>(h_dyn, W_dyn, b_dyn, g_ndyn, b_ndyn, Wq, bq, Wk, bk);
    k2m<<<B_ROWS / 2, 512, SMEM2>>>(x_stat, b_stat, g_nstat, b_nstat, bv,
                                    g_mlp, b_mlp, b1, b2, out);
    k3<<<B_ROWS / 32, 256, SMEM3>>>(Wo, bo, res_sc, out);
}

// round 13
// speedup vs baseline: 1.8050x; 1.2615x over previous
#include <cuda_runtime.h>
#include <cuda_fp16.h>
#include <math.h>
#include <stdint.h>

#define B_ROWS 4096
#define DM     256
#define DDYN   512
#define SCALE  0.125f
#define LN_EPS 1e-5f
#define WT_STRIDE 260
#define NCHUNK 13

// ---------------- device scratch ----------------
__device__ float g_h0 [B_ROWS * DM];
__device__ float g_u  [B_ROWS * DM * 4];
__device__ float g_qbk[B_ROWS * 4];
__device__ float g_z  [B_ROWS * DM];
// 13 chunks (Wstat 1, Wv 4, W1 4, W2 4): [256 n][64 k fp16 = 128B row, XOR-8 swizzle]
__device__ uint4 g_B[NCHUNK * 2048];

__device__ __forceinline__ uint32_t smem_u32(const void* p) {
    uint32_t a;
    asm("{ .reg .u64 t; cvta.to.shared.u64 t, %1; cvt.u32.u64 %0, t; }" : "=r"(a) : "l"(p));
    return a;
}

// ---------------- mma / ldmatrix ----------------
__device__ __forceinline__ void mma_f16(float* d, const unsigned* a, unsigned b0, unsigned b1) {
    asm volatile("mma.sync.aligned.m16n8k16.row.col.f32.f16.f16.f32 "
        "{%0,%1,%2,%3}, {%4,%5,%6,%7}, {%8,%9}, {%0,%1,%2,%3};"
        : "+f"(d[0]), "+f"(d[1]), "+f"(d[2]), "+f"(d[3])
        : "r"(a[0]), "r"(a[1]), "r"(a[2]), "r"(a[3]), "r"(b0), "r"(b1));
}
__device__ __forceinline__ void ldsm4(unsigned* r, unsigned addr) {
    asm volatile("ldmatrix.sync.aligned.m8n8.x4.shared.b16 {%0,%1,%2,%3}, [%4];"
        : "=r"(r[0]), "=r"(r[1]), "=r"(r[2]), "=r"(r[3]) : "r"(addr));
}

// A smem layout: blocked atoms 8 rows x 64 cols (1KB), atom = (row>>3) + (col>>6)*16
// single-fp16 A (logits/LN always computed from fp32 registers before rounding)
__device__ __forceinline__ void storeA2(char* Ah, int row, int col,
                                        float v0, float v1) {
    unsigned byte = ((unsigned)(row >> 3) << 10) + ((unsigned)(col >> 6) << 14)
                  + ((unsigned)(row & 7) << 7)
                  + ((((unsigned)(col & 63)) * 2u) ^ (((unsigned)(row & 7)) << 4));
    __half h0 = __float2half_rn(v0), h1 = __float2half_rn(v1);
    *(unsigned*)(Ah + byte) = (unsigned)__half_as_ushort(h0) |
                              ((unsigned)__half_as_ushort(h1) << 16);
}

// ---------------- k0: weights -> single-fp16 swizzled chunk images ----------------
__global__ void k0(const float* __restrict__ Ws, const float* __restrict__ Wv,
                   const float* __restrict__ W1, const float* __restrict__ W2) {
    const int c = blockIdx.x, n = threadIdx.x;   // c: 0..12, n: 0..255
    const float* W; int kbase;
    if (c == 0)      { W = Ws; kbase = 0; }
    else if (c <= 4) { W = Wv; kbase = (c - 1) * 64; }
    else if (c <= 8) { W = W1; kbase = (c - 5) * 64; }
    else             { W = W2; kbase = (c - 9) * 64; }
    char* bp = (char*)(g_B + (size_t)c * 2048) + n * 128;
    const unsigned nm = ((unsigned)n & 7u) << 4;
    for (int kl = 0; kl < 64; kl++) {
        float v = W[(size_t)(kbase + kl) * 256 + n];
        *(__half*)(bp + (((unsigned)kl * 2u) ^ nm)) = __float2half_rn(v);
    }
}

// ---------------- fp32 tiled GEMM helper (k1, k3) ----------------
template<int NTHREADS>
__device__ __forceinline__ void gemm_acc(
    const float* __restrict__ Asm, int astride, int kdim,
    const float* __restrict__ Wg, float* __restrict__ Wt,
    float acc[4][8], int tid)
{
#pragma unroll
    for (int t = 0; t < 4; t++)
#pragma unroll
        for (int j = 0; j < 8; j++) acc[t][j] = 0.f;
    const int tc = tid & 31, tok0 = (tid >> 5) * 4, col0 = tc * 8;
    const int nkt = kdim >> 4;
    for (int kt = 0; kt < nkt; ++kt) {
        const float4* src = reinterpret_cast<const float4*>(Wg + kt * 16 * DM);
#pragma unroll
        for (int f = tid; f < 1024; f += NTHREADS) {
            int row = f >> 6, c4 = f & 63;
            *reinterpret_cast<float4*>(Wt + row * WT_STRIDE + c4 * 4) = src[f];
        }
        __syncthreads();
#pragma unroll
        for (int kk4 = 0; kk4 < 4; ++kk4) {
            const int kbase = kt * 16 + kk4 * 4;
            float a_[4][4];
#pragma unroll
            for (int t = 0; t < 4; t++) {
                float4 v = *reinterpret_cast<const float4*>(Asm + (tok0 + t) * astride + kbase);
                a_[t][0]=v.x; a_[t][1]=v.y; a_[t][2]=v.z; a_[t][3]=v.w;
            }
#pragma unroll
            for (int r = 0; r < 4; r++) {
                const float4 w0 = *reinterpret_cast<const float4*>(Wt + (kk4*4+r)*WT_STRIDE + col0);
                const float4 w1 = *reinterpret_cast<const float4*>(Wt + (kk4*4+r)*WT_STRIDE + col0 + 4);
                float w[8] = {w0.x,w0.y,w0.z,w0.w,w1.x,w1.y,w1.z,w1.w};
#pragma unroll
                for (int t = 0; t < 4; t++) {
                    const float a = a_[t][r];
#pragma unroll
                    for (int j = 0; j < 8; j++) acc[t][j] = fmaf(a, w[j], acc[t][j]);
                }
            }
        }
        __syncthreads();
    }
}

// ---------------- k1 (unchanged) ----------------
__global__ void __launch_bounds__(256, 1) k1(
    const float* __restrict__ h_dyn, const float* __restrict__ W_dyn,
    const float* __restrict__ b_dyn, const float* __restrict__ g_ndyn,
    const float* __restrict__ b_ndyn, const float* __restrict__ Wq,
    const float* __restrict__ bq, const float* __restrict__ Wk,
    const float* __restrict__ bk)
{
    extern __shared__ float sm[];
    float* sm_hd  = sm;
    float* sm_h   = sm_hd + 32 * 512;
    float* sm_q   = sm_h  + 32 * 256;
    float* sm_wt  = sm_q  + 32 * 256;
    float* p_bdyn = sm_wt + 16 * WT_STRIDE;
    float* p_gn = p_bdyn + 256; float* p_bn = p_gn + 256;
    float* p_bq = p_bn + 256;   float* p_bk = p_bq + 256;

    const int tid = threadIdx.x;
    const int row0 = blockIdx.x * 32;
    {
        const float4* src = reinterpret_cast<const float4*>(h_dyn + (size_t)row0 * DDYN);
        for (int f = tid; f < 4096; f += 256) reinterpret_cast<float4*>(sm_hd)[f] = src[f];
    }
    if (tid < 64) {
        reinterpret_cast<float4*>(p_bdyn)[tid] = reinterpret_cast<const float4*>(b_dyn)[tid];
        reinterpret_cast<float4*>(p_gn)[tid]   = reinterpret_cast<const float4*>(g_ndyn)[tid];
        reinterpret_cast<float4*>(p_bn)[tid]   = reinterpret_cast<const float4*>(b_ndyn)[tid];
        reinterpret_cast<float4*>(p_bq)[tid]   = reinterpret_cast<const float4*>(bq)[tid];
        reinterpret_cast<float4*>(p_bk)[tid]   = reinterpret_cast<const float4*>(bk)[tid];
    }
    __syncthreads();

    float acc[4][8];
    gemm_acc<256>(sm_hd, 512, 512, W_dyn, sm_wt, acc, tid);
    {
        const int tc = tid & 31, tok0 = (tid >> 5) * 4, col0 = tc * 8;
#pragma unroll
        for (int t = 0; t < 4; t++) {
            float s = 0.f, s2 = 0.f;
#pragma unroll
            for (int j = 0; j < 8; j++) {
                float v = acc[t][j] + p_bdyn[col0 + j];
                acc[t][j] = v; s += v; s2 += v * v;
            }
            float* h0p = g_h0 + (size_t)(row0 + tok0 + t) * DM + col0;
            reinterpret_cast<float4*>(h0p)[0] = make_float4(acc[t][0],acc[t][1],acc[t][2],acc[t][3]);
            reinterpret_cast<float4*>(h0p)[1] = make_float4(acc[t][4],acc[t][5],acc[t][6],acc[t][7]);
#pragma unroll
            for (int off = 16; off; off >>= 1) {
                s  += __shfl_xor_sync(0xffffffffu, s,  off);
                s2 += __shfl_xor_sync(0xffffffffu, s2, off);
            }
            float mean = s * (1.f/256.f);
            float rstd = rsqrtf(s2 * (1.f/256.f) - mean*mean + LN_EPS);
#pragma unroll
            for (int j = 0; j < 8; j++)
                sm_h[(tok0+t)*DM + col0+j] = (acc[t][j]-mean)*rstd*p_gn[col0+j] + p_bn[col0+j];
        }
    }
    __syncthreads();

    gemm_acc<256>(sm_h, 256, 256, Wq, sm_wt, acc, tid);
    {
        const int tc = tid & 31, tok0 = (tid >> 5) * 4, col0 = tc * 8;
#pragma unroll
        for (int t = 0; t < 4; t++)
#pragma unroll
            for (int j = 0; j < 8; j++)
                sm_q[(tok0+t)*DM + col0+j] = acc[t][j] + p_bq[col0+j];
    }
    __syncthreads();

    for (int jt = 0; jt < 16; jt++) {
        const float4* src = reinterpret_cast<const float4*>(Wk + jt * 16 * DM);
        for (int f = tid; f < 1024; f += 256) {
            int r = f >> 6, c4 = f & 63;
            *reinterpret_cast<float4*>(sm_wt + r * WT_STRIDE + c4 * 4) = src[f];
        }
        __syncthreads();
        const int jl = tid & 15;
#pragma unroll
        for (int rr = 0; rr < 2; rr++) {
            const int r = (tid >> 4) + rr * 16;
            float ua[4];
#pragma unroll
            for (int h = 0; h < 4; h++) {
                float a = 0.f;
#pragma unroll
                for (int d4 = 0; d4 < 16; d4++) {
                    float4 qv = *reinterpret_cast<const float4*>(sm_q + r*DM + h*64 + d4*4);
                    float4 wv = *reinterpret_cast<const float4*>(sm_wt + jl*WT_STRIDE + h*64 + d4*4);
                    a += qv.x*wv.x + qv.y*wv.y + qv.z*wv.z + qv.w*wv.w;
                }
                ua[h] = a;
            }
            *reinterpret_cast<float4*>(g_u + (size_t)(row0+r)*1024 + (jt*16+jl)*4) =
                make_float4(ua[0], ua[1], ua[2], ua[3]);
        }
        __syncthreads();
    }
    if (tid < 128) {
        const int r = tid >> 2, h = tid & 3;
        float a = 0.f;
#pragma unroll
        for (int d = 0; d < 64; d++) a += sm_q[r*DM + h*64 + d] * p_bk[h*64 + d];
        g_qbk[(size_t)(row0+r)*4 + h] = a;
    }
}

// ---------------- k2m: HMMA fused token path (single fp16, 13 chunks) ----------------
#define O_AH   0
#define O_B0   65536
#define O_B1   98304
#define O_PB   131072
#define O_US   140288
#define O_PS   148480
#define O_LG   152576
#define O_WN   160768
#define O_TAIL 162816
#define SMEM2  162880

__device__ __forceinline__ void prefetch_chunk(char* buf, int g, int tid) {
    const char* src = (const char*)(g_B + (size_t)g * 2048);
    unsigned dst = smem_u32(buf);
#pragma unroll
    for (int i = 0; i < 4; i++) {
        int o = (tid + i * 512) * 16;
        asm volatile("cp.async.cg.shared.global [%0], [%1], 16;"
            :: "r"(dst + o), "l"(src + o) : "memory");
    }
    asm volatile("cp.async.commit_group;" ::: "memory");
}

// warp grid: 16 warps = 4 (wm, 32 rows) x 4 (wn4, 64 cols); each chunk covers 64 k
__device__ __forceinline__ void gemm_tc(float acc[2][8][4],
    unsigned aHi, char* B0, char* B1,
    int g0, int nc, int wm, int wn4, int lane, int tid)
{
#pragma unroll
    for (int mt = 0; mt < 2; mt++)
#pragma unroll
        for (int nt = 0; nt < 8; nt++)
#pragma unroll
            for (int q = 0; q < 4; q++) acc[mt][nt][q] = 0.f;

    const int aseg = lane >> 4;
    unsigned Arow[2], Axor[2];
#pragma unroll
    for (int mt = 0; mt < 2; mt++) {
        int row = wm * 32 + mt * 16 + (lane & 15);
        Arow[mt] = ((unsigned)(row >> 3) << 10) | ((unsigned)(row & 7) << 7);
        Axor[mt] = (unsigned)(row & 7) << 4;
    }
    const unsigned bseg = (lane >> 3) & 1;
    unsigned Bn[4], Bx[4];
#pragma unroll
    for (int p = 0; p < 4; p++) {
        int n = wn4 * 64 + p * 16 + (lane >> 4) * 8 + (lane & 7);
        Bn[p] = (unsigned)n * 128u;
        Bx[p] = ((unsigned)n & 7u) << 4;
    }

    for (int kc = 0; kc < nc; kc++) {
        const int g = g0 + kc;
        asm volatile("cp.async.wait_group 0;" ::: "memory");
        __syncthreads();
        if (g + 1 < NCHUNK) prefetch_chunk(((g + 1) & 1) ? B1 : B0, g + 1, tid);
        const unsigned bbase = smem_u32((g & 1) ? B1 : B0);
        const unsigned acol = (unsigned)kc << 14;
#pragma unroll
        for (int ks = 0; ks < 4; ks++) {
            const unsigned asub = (unsigned)(ks * 32 + aseg * 16);
            unsigned ahi[2][4];
#pragma unroll
            for (int mt = 0; mt < 2; mt++) {
                unsigned off = acol + Arow[mt] + (asub ^ Axor[mt]);
                ldsm4(ahi[mt], aHi + off);
            }
            const unsigned bsub = (unsigned)(ks * 32 + bseg * 16);
#pragma unroll
            for (int p = 0; p < 4; p++) {
                unsigned b[4];
                ldsm4(b, bbase + Bn[p] + (bsub ^ Bx[p]));
#pragma unroll
                for (int mt = 0; mt < 2; mt++) {
                    mma_f16(acc[mt][2*p],   ahi[mt], b[0], b[1]);
                    mma_f16(acc[mt][2*p+1], ahi[mt], b[2], b[3]);
                }
            }
        }
    }
    __syncthreads();
}

// LN epilogue on register fragments; optional logit partials (S1)
__device__ __forceinline__ void epi_ln_m(float acc[2][8][4],
    const float* bias, const float* gg, const float* bb,
    char* Ah, float* ps, const float* us, float* lg,
    int wm, int wn4, int lane, bool do_logits)
{
    const int g8 = lane >> 2, tp = lane & 3;
    float s[4] = {0,0,0,0}, s2[4] = {0,0,0,0};
#pragma unroll
    for (int mt = 0; mt < 2; mt++)
#pragma unroll
        for (int nt = 0; nt < 8; nt++) {
            int C = wn4 * 64 + nt * 8 + tp * 2;
            float b0v = bias[C], b1v = bias[C + 1];
            float v0 = acc[mt][nt][0] + b0v, v1 = acc[mt][nt][1] + b1v;
            float v2 = acc[mt][nt][2] + b0v, v3 = acc[mt][nt][3] + b1v;
            acc[mt][nt][0]=v0; acc[mt][nt][1]=v1; acc[mt][nt][2]=v2; acc[mt][nt][3]=v3;
            s[mt*2]   += v0 + v1;  s2[mt*2]   += v0*v0 + v1*v1;
            s[mt*2+1] += v2 + v3;  s2[mt*2+1] += v2*v2 + v3*v3;
        }
#pragma unroll
    for (int off = 1; off <= 2; off <<= 1)
#pragma unroll
        for (int i = 0; i < 4; i++) {
            s[i]  += __shfl_xor_sync(0xffffffffu, s[i],  off);
            s2[i] += __shfl_xor_sync(0xffffffffu, s2[i], off);
        }
    if (tp == 0) {
#pragma unroll
        for (int i = 0; i < 4; i++) {
            int row = wm*32 + (i>>1)*16 + (i&1)*8 + g8;
            ps[(row*4 + wn4)*2]     = s[i];
            ps[(row*4 + wn4)*2 + 1] = s2[i];
        }
    }
    __syncthreads();
    float mean[4], rstd[4];
#pragma unroll
    for (int i = 0; i < 4; i++) {
        int row = wm*32 + (i>>1)*16 + (i&1)*8 + g8;
        float ss = 0.f, ss2 = 0.f;
#pragma unroll
        for (int x = 0; x < 4; x++) { ss += ps[(row*4+x)*2]; ss2 += ps[(row*4+x)*2+1]; }
        mean[i] = ss * (1.f/256.f);
        rstd[i] = rsqrtf(ss2 * (1.f/256.f) - mean[i]*mean[i] + LN_EPS);
    }
    float la[4][4];
    if (do_logits)
#pragma unroll
        for (int i = 0; i < 4; i++)
#pragma unroll
            for (int h = 0; h < 4; h++) la[i][h] = 0.f;
    const int half = wm >> 1;
#pragma unroll
    for (int mt = 0; mt < 2; mt++)
#pragma unroll
        for (int nt = 0; nt < 8; nt++) {
            int C = wn4 * 64 + nt * 8 + tp * 2;
            float g0 = gg[C], g1 = gg[C+1], e0 = bb[C], e1 = bb[C+1];
#pragma unroll
            for (int rh = 0; rh < 2; rh++) {
                int i = mt*2 + rh;
                int row = wm*32 + mt*16 + rh*8 + g8;
                float n0 = (acc[mt][nt][rh*2]   - mean[i]) * rstd[i] * g0 + e0;
                float n1 = (acc[mt][nt][rh*2+1] - mean[i]) * rstd[i] * g1 + e1;
                storeA2(Ah, row, C, n0, n1);
                if (do_logits) {
                    float4 u0 = *(const float4*)(us + half*1024 + C*4);
                    float4 u1 = *(const float4*)(us + half*1024 + (C+1)*4);
                    la[i][0] += n0*u0.x + n1*u1.x;
                    la[i][1] += n0*u0.y + n1*u1.y;
                    la[i][2] += n0*u0.z + n1*u1.z;
                    la[i][3] += n0*u0.w + n1*u1.w;
                }
            }
        }
    if (do_logits) {
#pragma unroll
        for (int off = 1; off <= 2; off <<= 1)
#pragma unroll
            for (int i = 0; i < 4; i++)
#pragma unroll
                for (int h = 0; h < 4; h++)
                    la[i][h] += __shfl_xor_sync(0xffffffffu, la[i][h], off);
        if (tp == 0)
#pragma unroll
            for (int i = 0; i < 4; i++) {
                int row = wm*32 + (i>>1)*16 + (i&1)*8 + g8;
#pragma unroll
                for (int h = 0; h < 4; h++) lg[row*16 + wn4*4 + h] = la[i][h];
            }
    }
    __syncthreads();
}

__global__ void __launch_bounds__(512, 1) k2m(
    const float* __restrict__ x_stat,
    const float* __restrict__ b_stat, const float* __restrict__ g_nstat,
    const float* __restrict__ b_nstat, const float* __restrict__ bv,
    const float* __restrict__ g_mlp,  const float* __restrict__ b_mlp,
    const float* __restrict__ b1,     const float* __restrict__ b2,
    float* __restrict__ out)
{
    extern __shared__ char smc[];
    char*  Ah  = smc + O_AH;
    char*  B0  = smc + O_B0;
    char*  B1  = smc + O_B1;
    float* pb  = (float*)(smc + O_PB);
    float* us  = (float*)(smc + O_US);
    float* ps  = (float*)(smc + O_PS);
    float* lg  = (float*)(smc + O_LG);
    float* zs  = (float*)(smc + O_LG);   // reuse after S1
    float* wns = (float*)(smc + O_WN);
    float* qbk = (float*)(smc + O_TAIL);
    float* ssm = (float*)(smc + O_TAIL + 32);

    const int tid = threadIdx.x, lane = tid & 31, w = tid >> 5;
    const int wm = w & 3, wn4 = w >> 2;
    const int g8 = lane >> 2, tp = lane & 3;
    const size_t b0 = (size_t)blockIdx.x * 2;
    const unsigned aHi = smem_u32(Ah);

    prefetch_chunk(B0, 0, tid);

    // ---- cooperative staging ----
    for (int idx = tid; idx < 2048; idx += 512) {
        int rr = idx >> 4, c4 = (idx & 15) * 4;
        float4 v = *reinterpret_cast<const float4*>(
            x_stat + (b0 + (rr >> 6)) * 4096 + (size_t)(rr & 63) * 64 + c4);
        storeA2(Ah, rr, c4,     v.x, v.y);
        storeA2(Ah, rr, c4 + 2, v.z, v.w);
    }
    if (tid < 512)
        reinterpret_cast<float4*>(us)[tid] =
            reinterpret_cast<const float4*>(g_u + b0 * 1024)[tid];
    if (tid < 64) {
        reinterpret_cast<float4*>(pb + 0*256)[tid] = reinterpret_cast<const float4*>(b_stat)[tid];
        reinterpret_cast<float4*>(pb + 1*256)[tid] = reinterpret_cast<const float4*>(g_nstat)[tid];
        reinterpret_cast<float4*>(pb + 2*256)[tid] = reinterpret_cast<const float4*>(b_nstat)[tid];
        reinterpret_cast<float4*>(pb + 3*256)[tid] = reinterpret_cast<const float4*>(bv)[tid];
        reinterpret_cast<float4*>(pb + 4*256)[tid] = reinterpret_cast<const float4*>(g_mlp)[tid];
        reinterpret_cast<float4*>(pb + 5*256)[tid] = reinterpret_cast<const float4*>(b_mlp)[tid];
        reinterpret_cast<float4*>(pb + 6*256)[tid] = reinterpret_cast<const float4*>(b1)[tid];
        reinterpret_cast<float4*>(pb + 7*256)[tid] = reinterpret_cast<const float4*>(b2)[tid];
    }
    if (tid < 8) qbk[tid] = g_qbk[b0 * 4 + tid];

    float acc[2][8][4];

    // ---- S1: s = x_stat @ W_stat ; LN -> A ; logit partials (chunk 0) ----
    gemm_tc(acc, aHi, B0, B1, 0, 1, wm, wn4, lane, tid);
    epi_ln_m(acc, pb + 0*256, pb + 1*256, pb + 2*256, Ah, ps, us, lg,
             wm, wn4, lane, true);

    // ---- logits -> sigmoid -> normalize -> w_mean ----
    {
        int row = tid >> 2, h = tid & 3;
        float lv = qbk[(row >> 6) * 4 + h];
#pragma unroll
        for (int x = 0; x < 4; x++) lv += lg[row*16 + x*4 + h];
        wns[tid] = 1.f / (1.f + expf(-lv * SCALE));
    }
    __syncthreads();
    if (tid < 8) {
        int half = tid >> 2, h = tid & 3;
        float sum = 0.f;
        for (int k = 0; k < 64; k++) sum += wns[(half*64 + k)*4 + h];
        ssm[tid] = sum + 1e-6f;
    }
    __syncthreads();
    wns[tid] = wns[tid] / ssm[(tid >> 8) * 4 + (tid & 3)];
    __syncthreads();
    if (tid < 128)
        out[(size_t)B_ROWS * DM + (b0 + (tid >> 6)) * 64 + (tid & 63)] =
            0.25f * (wns[tid*4] + wns[tid*4+1] + wns[tid*4+2] + wns[tid*4+3]);
    __syncthreads();

    // ---- S2: v = s @ Wv ; LN(g_mlp) -> A (chunks 1-4) ----
    gemm_tc(acc, aHi, B0, B1, 1, 4, wm, wn4, lane, tid);
    epi_ln_m(acc, pb + 3*256, pb + 4*256, pb + 5*256, Ah, ps, us, lg,
             wm, wn4, lane, false);

    // ---- S3: t = gelu(v @ W1 + b1) -> A (chunks 5-8) ----
    gemm_tc(acc, aHi, B0, B1, 5, 4, wm, wn4, lane, tid);
#pragma unroll
    for (int mt = 0; mt < 2; mt++)
#pragma unroll
        for (int nt = 0; nt < 8; nt++) {
            int C = wn4 * 64 + nt * 8 + tp * 2;
            float e0 = pb[6*256 + C], e1 = pb[6*256 + C + 1];
#pragma unroll
            for (int rh = 0; rh < 2; rh++) {
                int row = wm*32 + mt*16 + rh*8 + g8;
                float x0 = acc[mt][nt][rh*2]   + e0;
                float x1 = acc[mt][nt][rh*2+1] + e1;
                float n0 = 0.5f * x0 * (1.f + erff(x0 * 0.70710678118f));
                float n1 = 0.5f * x1 * (1.f + erff(x1 * 0.70710678118f));
                storeA2(Ah, row, C, n0, n1);
            }
        }
    __syncthreads();

    // ---- S4: vtok = t @ W2 + b2 ; weighted column sums -> z (chunks 9-12) ----
    gemm_tc(acc, aHi, B0, B1, 9, 4, wm, wn4, lane, tid);
    if (tid < 512) zs[tid] = 0.f;
    __syncthreads();
    {
        float za[8], zb[8];
#pragma unroll
        for (int nt = 0; nt < 8; nt++) { za[nt] = 0.f; zb[nt] = 0.f; }
#pragma unroll
        for (int mt = 0; mt < 2; mt++)
#pragma unroll
            for (int nt = 0; nt < 8; nt++) {
                int C = wn4 * 64 + nt * 8 + tp * 2;
                int hcol = C >> 6;
                float e0 = pb[7*256 + C], e1 = pb[7*256 + C + 1];
#pragma unroll
                for (int rh = 0; rh < 2; rh++) {
                    int row = wm*32 + mt*16 + rh*8 + g8;
                    float wf = wns[row*4 + hcol];
                    za[nt] += (acc[mt][nt][rh*2]   + e0) * wf;
                    zb[nt] += (acc[mt][nt][rh*2+1] + e1) * wf;
                }
            }
#pragma unroll
        for (int off = 4; off <= 16; off <<= 1)
#pragma unroll
            for (int nt = 0; nt < 8; nt++) {
                za[nt] += __shfl_xor_sync(0xffffffffu, za[nt], off);
                zb[nt] += __shfl_xor_sync(0xffffffffu, zb[nt], off);
            }
        if (lane < 4) {
            int half = wm >> 1;
#pragma unroll
            for (int nt = 0; nt < 8; nt++) {
                int C = wn4 * 64 + nt * 8 + lane * 2;
                atomicAdd(&zs[half*256 + C],     za[nt]);
                atomicAdd(&zs[half*256 + C + 1], zb[nt]);
            }
        }
    }
    __syncthreads();
    g_z[b0 * 256 + tid] = zs[tid];
}

// ---------------- k3: c = z @ Wo + bo ; out = h0 + rs*c ----------------
__global__ void __launch_bounds__(256, 1) k3(
    const float* __restrict__ Wo, const float* __restrict__ bo,
    const float* __restrict__ res_p, float* __restrict__ out)
{
    extern __shared__ float sm[];
    float* zsm = sm;
    float* Wt  = zsm + 32 * 256;
    float* pbo = Wt + 16 * WT_STRIDE;
    const int tid = threadIdx.x, row0 = blockIdx.x * 32;
    for (int f = tid; f < 2048; f += 256)
        reinterpret_cast<float4*>(zsm)[f] =
            reinterpret_cast<const float4*>(g_z + (size_t)row0 * 256)[f];
    if (tid < 64)
        reinterpret_cast<float4*>(pbo)[tid] = reinterpret_cast<const float4*>(bo)[tid];
    __syncthreads();
    float acc[4][8];
    gemm_acc<256>(zsm, 256, 256, Wo, Wt, acc, tid);
    const float rs = *res_p;
    const int tc = tid & 31, tok0 = (tid >> 5) * 4, col0 = tc * 8;
#pragma unroll
    for (int t = 0; t < 4; t++) {
        const size_t r = (size_t)(row0 + tok0 + t);
#pragma unroll
        for (int j = 0; j < 8; j++)
            out[r * 256 + col0 + j] =
                g_h0[r * 256 + col0 + j] + rs * (acc[t][j] + pbo[col0 + j]);
    }
}

// ============================================================
extern "C" void kernel_launch(void* const* d_in, const int* in_sizes, int n_in,
                              void* d_out, int out_size)
{
    const float* h_dyn   = (const float*)d_in[0];
    const float* x_stat  = (const float*)d_in[1];
    const float* W_dyn   = (const float*)d_in[2];
    const float* b_dyn   = (const float*)d_in[3];
    const float* W_stat  = (const float*)d_in[4];
    const float* b_stat  = (const float*)d_in[5];
    const float* g_ndyn  = (const float*)d_in[6];
    const float* b_ndyn  = (const float*)d_in[7];
    const float* g_nstat = (const float*)d_in[8];
    const float* b_nstat = (const float*)d_in[9];
    const float* Wq  = (const float*)d_in[10];
    const float* bq  = (const float*)d_in[11];
    const float* Wk  = (const float*)d_in[12];
    const float* bk  = (const float*)d_in[13];
    const float* Wv  = (const float*)d_in[14];
    const float* bv  = (const float*)d_in[15];
    const float* g_mlp = (const float*)d_in[16];
    const float* b_mlp = (const float*)d_in[17];
    const float* W1  = (const float*)d_in[18];
    const float* b1  = (const float*)d_in[19];
    const float* W2  = (const float*)d_in[20];
    const float* b2  = (const float*)d_in[21];
    const float* Wo  = (const float*)d_in[22];
    const float* bo  = (const float*)d_in[23];
    const float* res_sc = (const float*)d_in[24];
    float* out = (float*)d_out;

    const int SMEM1 = (32*512 + 32*256 + 32*256 + 16*WT_STRIDE + 5*256) * 4;
    const int SMEM3 = (32*256 + 16*WT_STRIDE + 256) * 4;
    cudaFuncSetAttribute(k1,  cudaFuncAttributeMaxDynamicSharedMemorySize, SMEM1);
    cudaFuncSetAttribute(k2m, cudaFuncAttributeMaxDynamicSharedMemorySize, SMEM2);
    cudaFuncSetAttribute(k3,  cudaFuncAttributeMaxDynamicSharedMemorySize, SMEM3);

    k0<<<NCHUNK, 256>>>(W_stat, Wv, W1, W2);
    k1<<<B_ROWS / 32, 256, SMEM1>>>(h_dyn, W_dyn, b_dyn, g_ndyn, b_ndyn, Wq, bq, Wk, bk);
    k2m<<<B_ROWS / 2, 512, SMEM2>>>(x_stat, b_stat, g_nstat, b_nstat, bv,
                                    g_mlp, b_mlp, b1, b2, out);
    k3<<<B_ROWS / 32, 256, SMEM3>>>(Wo, bo, res_sc, out);
}

// round 14
// speedup vs baseline: 1.8529x; 1.0265x over previous
#include <cuda_runtime.h>
#include <cuda_fp16.h>
#include <math.h>
#include <stdint.h>

#define B_ROWS 4096
#define DM     256
#define DDYN   512
#define SCALE  0.125f
#define LN_EPS 1e-5f
#define WT_STRIDE 260
#define NCHUNK 17

// ---------------- device scratch ----------------
__device__ float g_h0 [B_ROWS * DM];
__device__ float g_u  [B_ROWS * DM * 4];
__device__ float g_qbk[B_ROWS * 4];
__device__ float g_z  [B_ROWS * DM];
// 17 chunks (Wstat 1, Wv 4, W1 4, W2 4, Wo 4): [256 n][64 k fp16 = 128B row, XOR-8]
__device__ uint4 g_B[NCHUNK * 2048];

__device__ __forceinline__ uint32_t smem_u32(const void* p) {
    uint32_t a;
    asm("{ .reg .u64 t; cvta.to.shared.u64 t, %1; cvt.u32.u64 %0, t; }" : "=r"(a) : "l"(p));
    return a;
}

// ---------------- mma / ldmatrix ----------------
__device__ __forceinline__ void mma_f16(float* d, const unsigned* a, unsigned b0, unsigned b1) {
    asm volatile("mma.sync.aligned.m16n8k16.row.col.f32.f16.f16.f32 "
        "{%0,%1,%2,%3}, {%4,%5,%6,%7}, {%8,%9}, {%0,%1,%2,%3};"
        : "+f"(d[0]), "+f"(d[1]), "+f"(d[2]), "+f"(d[3])
        : "r"(a[0]), "r"(a[1]), "r"(a[2]), "r"(a[3]), "r"(b0), "r"(b1));
}
__device__ __forceinline__ void ldsm4(unsigned* r, unsigned addr) {
    asm volatile("ldmatrix.sync.aligned.m8n8.x4.shared.b16 {%0,%1,%2,%3}, [%4];"
        : "=r"(r[0]), "=r"(r[1]), "=r"(r[2]), "=r"(r[3]) : "r"(addr));
}

// A smem layout: blocked atoms 8 rows x 64 cols (1KB), atom = (row>>3) + (col>>6)*16
__device__ __forceinline__ void storeA2(char* Ah, int row, int col,
                                        float v0, float v1) {
    unsigned byte = ((unsigned)(row >> 3) << 10) + ((unsigned)(col >> 6) << 14)
                  + ((unsigned)(row & 7) << 7)
                  + ((((unsigned)(col & 63)) * 2u) ^ (((unsigned)(row & 7)) << 4));
    __half h0 = __float2half_rn(v0), h1 = __float2half_rn(v1);
    *(unsigned*)(Ah + byte) = (unsigned)__half_as_ushort(h0) |
                              ((unsigned)__half_as_ushort(h1) << 16);
}

// ---------------- k0: weights -> single-fp16 swizzled chunk images ----------------
__global__ void k0(const float* __restrict__ Ws, const float* __restrict__ Wv,
                   const float* __restrict__ W1, const float* __restrict__ W2,
                   const float* __restrict__ Wo) {
    const int c = blockIdx.x, n = threadIdx.x;   // c: 0..16, n: 0..255
    const float* W; int kbase;
    if (c == 0)       { W = Ws; kbase = 0; }
    else if (c <= 4)  { W = Wv; kbase = (c - 1) * 64; }
    else if (c <= 8)  { W = W1; kbase = (c - 5) * 64; }
    else if (c <= 12) { W = W2; kbase = (c - 9) * 64; }
    else              { W = Wo; kbase = (c - 13) * 64; }
    char* bp = (char*)(g_B + (size_t)c * 2048) + n * 128;
    const unsigned nm = ((unsigned)n & 7u) << 4;
    for (int kl = 0; kl < 64; kl++) {
        float v = W[(size_t)(kbase + kl) * 256 + n];
        *(__half*)(bp + (((unsigned)kl * 2u) ^ nm)) = __float2half_rn(v);
    }
}

// ---------------- fp32 tiled GEMM helper (k1) ----------------
template<int NTHREADS>
__device__ __forceinline__ void gemm_acc(
    const float* __restrict__ Asm, int astride, int kdim,
    const float* __restrict__ Wg, float* __restrict__ Wt,
    float acc[4][8], int tid)
{
#pragma unroll
    for (int t = 0; t < 4; t++)
#pragma unroll
        for (int j = 0; j < 8; j++) acc[t][j] = 0.f;
    const int tc = tid & 31, tok0 = (tid >> 5) * 4, col0 = tc * 8;
    const int nkt = kdim >> 4;
    for (int kt = 0; kt < nkt; ++kt) {
        const float4* src = reinterpret_cast<const float4*>(Wg + kt * 16 * DM);
#pragma unroll
        for (int f = tid; f < 1024; f += NTHREADS) {
            int row = f >> 6, c4 = f & 63;
            *reinterpret_cast<float4*>(Wt + row * WT_STRIDE + c4 * 4) = src[f];
        }
        __syncthreads();
#pragma unroll
        for (int kk4 = 0; kk4 < 4; ++kk4) {
            const int kbase = kt * 16 + kk4 * 4;
            float a_[4][4];
#pragma unroll
            for (int t = 0; t < 4; t++) {
                float4 v = *reinterpret_cast<const float4*>(Asm + (tok0 + t) * astride + kbase);
                a_[t][0]=v.x; a_[t][1]=v.y; a_[t][2]=v.z; a_[t][3]=v.w;
            }
#pragma unroll
            for (int r = 0; r < 4; r++) {
                const float4 w0 = *reinterpret_cast<const float4*>(Wt + (kk4*4+r)*WT_STRIDE + col0);
                const float4 w1 = *reinterpret_cast<const float4*>(Wt + (kk4*4+r)*WT_STRIDE + col0 + 4);
                float w[8] = {w0.x,w0.y,w0.z,w0.w,w1.x,w1.y,w1.z,w1.w};
#pragma unroll
                for (int t = 0; t < 4; t++) {
                    const float a = a_[t][r];
#pragma unroll
                    for (int j = 0; j < 8; j++) acc[t][j] = fmaf(a, w[j], acc[t][j]);
                }
            }
        }
        __syncthreads();
    }
}

// ---------------- k1: fp32, u-stage rewritten (q in regs, Wk broadcast LDG) ----------------
__global__ void __launch_bounds__(256, 1) k1(
    const float* __restrict__ h_dyn, const float* __restrict__ W_dyn,
    const float* __restrict__ b_dyn, const float* __restrict__ g_ndyn,
    const float* __restrict__ b_ndyn, const float* __restrict__ Wq,
    const float* __restrict__ bq, const float* __restrict__ Wk,
    const float* __restrict__ bk)
{
    extern __shared__ float sm[];
    float* sm_hd  = sm;
    float* sm_h   = sm_hd + 32 * 512;
    float* sm_q   = sm_h  + 32 * 256;
    float* sm_wt  = sm_q  + 32 * 256;
    float* p_bdyn = sm_wt + 16 * WT_STRIDE;
    float* p_gn = p_bdyn + 256; float* p_bn = p_gn + 256;
    float* p_bq = p_bn + 256;   float* p_bk = p_bq + 256;

    const int tid = threadIdx.x;
    const int row0 = blockIdx.x * 32;
    {
        const float4* src = reinterpret_cast<const float4*>(h_dyn + (size_t)row0 * DDYN);
        for (int f = tid; f < 4096; f += 256) reinterpret_cast<float4*>(sm_hd)[f] = src[f];
    }
    if (tid < 64) {
        reinterpret_cast<float4*>(p_bdyn)[tid] = reinterpret_cast<const float4*>(b_dyn)[tid];
        reinterpret_cast<float4*>(p_gn)[tid]   = reinterpret_cast<const float4*>(g_ndyn)[tid];
        reinterpret_cast<float4*>(p_bn)[tid]   = reinterpret_cast<const float4*>(b_ndyn)[tid];
        reinterpret_cast<float4*>(p_bq)[tid]   = reinterpret_cast<const float4*>(bq)[tid];
        reinterpret_cast<float4*>(p_bk)[tid]   = reinterpret_cast<const float4*>(bk)[tid];
    }
    __syncthreads();

    float acc[4][8];
    gemm_acc<256>(sm_hd, 512, 512, W_dyn, sm_wt, acc, tid);
    {
        const int tc = tid & 31, tok0 = (tid >> 5) * 4, col0 = tc * 8;
#pragma unroll
        for (int t = 0; t < 4; t++) {
            float s = 0.f, s2 = 0.f;
#pragma unroll
            for (int j = 0; j < 8; j++) {
                float v = acc[t][j] + p_bdyn[col0 + j];
                acc[t][j] = v; s += v; s2 += v * v;
            }
            float* h0p = g_h0 + (size_t)(row0 + tok0 + t) * DM + col0;
            reinterpret_cast<float4*>(h0p)[0] = make_float4(acc[t][0],acc[t][1],acc[t][2],acc[t][3]);
            reinterpret_cast<float4*>(h0p)[1] = make_float4(acc[t][4],acc[t][5],acc[t][6],acc[t][7]);
#pragma unroll
            for (int off = 16; off; off >>= 1) {
                s  += __shfl_xor_sync(0xffffffffu, s,  off);
                s2 += __shfl_xor_sync(0xffffffffu, s2, off);
            }
            float mean = s * (1.f/256.f);
            float rstd = rsqrtf(s2 * (1.f/256.f) - mean*mean + LN_EPS);
#pragma unroll
            for (int j = 0; j < 8; j++)
                sm_h[(tok0+t)*DM + col0+j] = (acc[t][j]-mean)*rstd*p_gn[col0+j] + p_bn[col0+j];
        }
    }
    __syncthreads();

    gemm_acc<256>(sm_h, 256, 256, Wq, sm_wt, acc, tid);
    {
        const int tc = tid & 31, tok0 = (tid >> 5) * 4, col0 = tc * 8;
#pragma unroll
        for (int t = 0; t < 4; t++)
#pragma unroll
            for (int j = 0; j < 8; j++)
                sm_q[(tok0+t)*DM + col0+j] = acc[t][j] + p_bq[col0+j];
    }
    __syncthreads();

    // ---- u[b,j,h]: warp = (head, j-half), lane = row; q segment in regs,
    //      Wk rows via broadcast global loads (all lanes same address) ----
    {
        const int w = tid >> 5, lane = tid & 31;
        const int h = w & 3, jh = w >> 2;
        float4 qr[16];
#pragma unroll
        for (int d4 = 0; d4 < 16; d4++)
            qr[d4] = *reinterpret_cast<const float4*>(sm_q + lane * DM + h * 64 + d4 * 4);
        const int j0 = jh * 128;
        for (int j = j0; j < j0 + 128; j++) {
            const float4* wrow = reinterpret_cast<const float4*>(Wk + (size_t)j * DM + h * 64);
            float a = 0.f;
#pragma unroll
            for (int d4 = 0; d4 < 16; d4++) {
                float4 wv = wrow[d4];
                a += qr[d4].x*wv.x + qr[d4].y*wv.y + qr[d4].z*wv.z + qr[d4].w*wv.w;
            }
            g_u[(size_t)(row0 + lane) * 1024 + j * 4 + h] = a;
        }
    }

    if (tid < 128) {
        const int r = tid >> 2, h = tid & 3;
        float a = 0.f;
#pragma unroll
        for (int d = 0; d < 64; d++) a += sm_q[r*DM + h*64 + d] * p_bk[h*64 + d];
        g_qbk[(size_t)(row0+r)*4 + h] = a;
    }
}

// ---------------- shared HMMA machinery ----------------
#define O_AH   0
#define O_B0   65536
#define O_B1   98304
#define O_PB   131072
#define O_US   140288
#define O_PS   148480
#define O_LG   152576
#define O_WN   160768
#define O_TAIL 162816
#define SMEM2  162880

__device__ __forceinline__ void prefetch_chunk(char* buf, int g, int tid) {
    const char* src = (const char*)(g_B + (size_t)g * 2048);
    unsigned dst = smem_u32(buf);
#pragma unroll
    for (int i = 0; i < 4; i++) {
        int o = (tid + i * 512) * 16;
        asm volatile("cp.async.cg.shared.global [%0], [%1], 16;"
            :: "r"(dst + o), "l"(src + o) : "memory");
    }
    asm volatile("cp.async.commit_group;" ::: "memory");
}

// warp grid: 16 warps = 4 (wm, 32 rows) x 4 (wn4, 64 cols); each chunk covers 64 k
__device__ __forceinline__ void gemm_tc(float acc[2][8][4],
    unsigned aHi, char* B0, char* B1,
    int g0, int nc, int gmax, int wm, int wn4, int lane, int tid)
{
#pragma unroll
    for (int mt = 0; mt < 2; mt++)
#pragma unroll
        for (int nt = 0; nt < 8; nt++)
#pragma unroll
            for (int q = 0; q < 4; q++) acc[mt][nt][q] = 0.f;

    const int aseg = lane >> 4;
    unsigned Arow[2], Axor[2];
#pragma unroll
    for (int mt = 0; mt < 2; mt++) {
        int row = wm * 32 + mt * 16 + (lane & 15);
        Arow[mt] = ((unsigned)(row >> 3) << 10) | ((unsigned)(row & 7) << 7);
        Axor[mt] = (unsigned)(row & 7) << 4;
    }
    const unsigned bseg = (lane >> 3) & 1;
    unsigned Bn[4], Bx[4];
#pragma unroll
    for (int p = 0; p < 4; p++) {
        int n = wn4 * 64 + p * 16 + (lane >> 4) * 8 + (lane & 7);
        Bn[p] = (unsigned)n * 128u;
        Bx[p] = ((unsigned)n & 7u) << 4;
    }

    for (int kc = 0; kc < nc; kc++) {
        const int g = g0 + kc;
        asm volatile("cp.async.wait_group 0;" ::: "memory");
        __syncthreads();
        if (g + 1 < gmax) prefetch_chunk(((g + 1) & 1) ? B1 : B0, g + 1, tid);
        const unsigned bbase = smem_u32((g & 1) ? B1 : B0);
        const unsigned acol = (unsigned)kc << 14;
#pragma unroll
        for (int ks = 0; ks < 4; ks++) {
            const unsigned asub = (unsigned)(ks * 32 + aseg * 16);
            unsigned ahi[2][4];
#pragma unroll
            for (int mt = 0; mt < 2; mt++) {
                unsigned off = acol + Arow[mt] + (asub ^ Axor[mt]);
                ldsm4(ahi[mt], aHi + off);
            }
            const unsigned bsub = (unsigned)(ks * 32 + bseg * 16);
#pragma unroll
            for (int p = 0; p < 4; p++) {
                unsigned b[4];
                ldsm4(b, bbase + Bn[p] + (bsub ^ Bx[p]));
#pragma unroll
                for (int mt = 0; mt < 2; mt++) {
                    mma_f16(acc[mt][2*p],   ahi[mt], b[0], b[1]);
                    mma_f16(acc[mt][2*p+1], ahi[mt], b[2], b[3]);
                }
            }
        }
    }
    __syncthreads();
}

// LN epilogue on register fragments; optional logit partials (S1)
__device__ __forceinline__ void epi_ln_m(float acc[2][8][4],
    const float* bias, const float* gg, const float* bb,
    char* Ah, float* ps, const float* us, float* lg,
    int wm, int wn4, int lane, bool do_logits)
{
    const int g8 = lane >> 2, tp = lane & 3;
    float s[4] = {0,0,0,0}, s2[4] = {0,0,0,0};
#pragma unroll
    for (int mt = 0; mt < 2; mt++)
#pragma unroll
        for (int nt = 0; nt < 8; nt++) {
            int C = wn4 * 64 + nt * 8 + tp * 2;
            float b0v = bias[C], b1v = bias[C + 1];
            float v0 = acc[mt][nt][0] + b0v, v1 = acc[mt][nt][1] + b1v;
            float v2 = acc[mt][nt][2] + b0v, v3 = acc[mt][nt][3] + b1v;
            acc[mt][nt][0]=v0; acc[mt][nt][1]=v1; acc[mt][nt][2]=v2; acc[mt][nt][3]=v3;
            s[mt*2]   += v0 + v1;  s2[mt*2]   += v0*v0 + v1*v1;
            s[mt*2+1] += v2 + v3;  s2[mt*2+1] += v2*v2 + v3*v3;
        }
#pragma unroll
    for (int off = 1; off <= 2; off <<= 1)
#pragma unroll
        for (int i = 0; i < 4; i++) {
            s[i]  += __shfl_xor_sync(0xffffffffu, s[i],  off);
            s2[i] += __shfl_xor_sync(0xffffffffu, s2[i], off);
        }
    if (tp == 0) {
#pragma unroll
        for (int i = 0; i < 4; i++) {
            int row = wm*32 + (i>>1)*16 + (i&1)*8 + g8;
            ps[(row*4 + wn4)*2]     = s[i];
            ps[(row*4 + wn4)*2 + 1] = s2[i];
        }
    }
    __syncthreads();
    float mean[4], rstd[4];
#pragma unroll
    for (int i = 0; i < 4; i++) {
        int row = wm*32 + (i>>1)*16 + (i&1)*8 + g8;
        float ss = 0.f, ss2 = 0.f;
#pragma unroll
        for (int x = 0; x < 4; x++) { ss += ps[(row*4+x)*2]; ss2 += ps[(row*4+x)*2+1]; }
        mean[i] = ss * (1.f/256.f);
        rstd[i] = rsqrtf(ss2 * (1.f/256.f) - mean[i]*mean[i] + LN_EPS);
    }
    float la[4][4];
    if (do_logits)
#pragma unroll
        for (int i = 0; i < 4; i++)
#pragma unroll
            for (int h = 0; h < 4; h++) la[i][h] = 0.f;
    const int half = wm >> 1;
#pragma unroll
    for (int mt = 0; mt < 2; mt++)
#pragma unroll
        for (int nt = 0; nt < 8; nt++) {
            int C = wn4 * 64 + nt * 8 + tp * 2;
            float g0 = gg[C], g1 = gg[C+1], e0 = bb[C], e1 = bb[C+1];
#pragma unroll
            for (int rh = 0; rh < 2; rh++) {
                int i = mt*2 + rh;
                int row = wm*32 + mt*16 + rh*8 + g8;
                float n0 = (acc[mt][nt][rh*2]   - mean[i]) * rstd[i] * g0 + e0;
                float n1 = (acc[mt][nt][rh*2+1] - mean[i]) * rstd[i] * g1 + e1;
                storeA2(Ah, row, C, n0, n1);
                if (do_logits) {
                    float4 u0 = *(const float4*)(us + half*1024 + C*4);
                    float4 u1 = *(const float4*)(us + half*1024 + (C+1)*4);
                    la[i][0] += n0*u0.x + n1*u1.x;
                    la[i][1] += n0*u0.y + n1*u1.y;
                    la[i][2] += n0*u0.z + n1*u1.z;
                    la[i][3] += n0*u0.w + n1*u1.w;
                }
            }
        }
    if (do_logits) {
#pragma unroll
        for (int off = 1; off <= 2; off <<= 1)
#pragma unroll
            for (int i = 0; i < 4; i++)
#pragma unroll
                for (int h = 0; h < 4; h++)
                    la[i][h] += __shfl_xor_sync(0xffffffffu, la[i][h], off);
        if (tp == 0)
#pragma unroll
            for (int i = 0; i < 4; i++) {
                int row = wm*32 + (i>>1)*16 + (i&1)*8 + g8;
#pragma unroll
                for (int h = 0; h < 4; h++) lg[row*16 + wn4*4 + h] = la[i][h];
            }
    }
    __syncthreads();
}

__global__ void __launch_bounds__(512, 1) k2m(
    const float* __restrict__ x_stat,
    const float* __restrict__ b_stat, const float* __restrict__ g_nstat,
    const float* __restrict__ b_nstat, const float* __restrict__ bv,
    const float* __restrict__ g_mlp,  const float* __restrict__ b_mlp,
    const float* __restrict__ b1,     const float* __restrict__ b2,
    float* __restrict__ out)
{
    extern __shared__ char smc[];
    char*  Ah  = smc + O_AH;
    char*  B0  = smc + O_B0;
    char*  B1  = smc + O_B1;
    float* pb  = (float*)(smc + O_PB);
    float* us  = (float*)(smc + O_US);
    float* ps  = (float*)(smc + O_PS);
    float* lg  = (float*)(smc + O_LG);
    float* zs  = (float*)(smc + O_LG);   // reuse after S1
    float* wns = (float*)(smc + O_WN);
    float* qbk = (float*)(smc + O_TAIL);
    float* ssm = (float*)(smc + O_TAIL + 32);

    const int tid = threadIdx.x, lane = tid & 31, w = tid >> 5;
    const int wm = w & 3, wn4 = w >> 2;
    const int g8 = lane >> 2, tp = lane & 3;
    const size_t b0 = (size_t)blockIdx.x * 2;
    const unsigned aHi = smem_u32(Ah);

    prefetch_chunk(B0, 0, tid);

    // ---- cooperative staging ----
    for (int idx = tid; idx < 2048; idx += 512) {
        int rr = idx >> 4, c4 = (idx & 15) * 4;
        float4 v = *reinterpret_cast<const float4*>(
            x_stat + (b0 + (rr >> 6)) * 4096 + (size_t)(rr & 63) * 64 + c4);
        storeA2(Ah, rr, c4,     v.x, v.y);
        storeA2(Ah, rr, c4 + 2, v.z, v.w);
    }
    if (tid < 512)
        reinterpret_cast<float4*>(us)[tid] =
            reinterpret_cast<const float4*>(g_u + b0 * 1024)[tid];
    if (tid < 64) {
        reinterpret_cast<float4*>(pb + 0*256)[tid] = reinterpret_cast<const float4*>(b_stat)[tid];
        reinterpret_cast<float4*>(pb + 1*256)[tid] = reinterpret_cast<const float4*>(g_nstat)[tid];
        reinterpret_cast<float4*>(pb + 2*256)[tid] = reinterpret_cast<const float4*>(b_nstat)[tid];
        reinterpret_cast<float4*>(pb + 3*256)[tid] = reinterpret_cast<const float4*>(bv)[tid];
        reinterpret_cast<float4*>(pb + 4*256)[tid] = reinterpret_cast<const float4*>(g_mlp)[tid];
        reinterpret_cast<float4*>(pb + 5*256)[tid] = reinterpret_cast<const float4*>(b_mlp)[tid];
        reinterpret_cast<float4*>(pb + 6*256)[tid] = reinterpret_cast<const float4*>(b1)[tid];
        reinterpret_cast<float4*>(pb + 7*256)[tid] = reinterpret_cast<const float4*>(b2)[tid];
    }
    if (tid < 8) qbk[tid] = g_qbk[b0 * 4 + tid];

    float acc[2][8][4];

    // ---- S1: s = x_stat @ W_stat ; LN -> A ; logit partials (chunk 0) ----
    gemm_tc(acc, aHi, B0, B1, 0, 1, 13, wm, wn4, lane, tid);
    epi_ln_m(acc, pb + 0*256, pb + 1*256, pb + 2*256, Ah, ps, us, lg,
             wm, wn4, lane, true);

    // ---- logits -> sigmoid -> normalize -> w_mean ----
    {
        int row = tid >> 2, h = tid & 3;
        float lv = qbk[(row >> 6) * 4 + h];
#pragma unroll
        for (int x = 0; x < 4; x++) lv += lg[row*16 + x*4 + h];
        wns[tid] = 1.f / (1.f + expf(-lv * SCALE));
    }
    __syncthreads();
    if (tid < 8) {
        int half = tid >> 2, h = tid & 3;
        float sum = 0.f;
        for (int k = 0; k < 64; k++) sum += wns[(half*64 + k)*4 + h];
        ssm[tid] = sum + 1e-6f;
    }
    __syncthreads();
    wns[tid] = wns[tid] / ssm[(tid >> 8) * 4 + (tid & 3)];
    __syncthreads();
    if (tid < 128)
        out[(size_t)B_ROWS * DM + (b0 + (tid >> 6)) * 64 + (tid & 63)] =
            0.25f * (wns[tid*4] + wns[tid*4+1] + wns[tid*4+2] + wns[tid*4+3]);
    __syncthreads();

    // ---- S2: v = s @ Wv ; LN(g_mlp) -> A (chunks 1-4) ----
    gemm_tc(acc, aHi, B0, B1, 1, 4, 13, wm, wn4, lane, tid);
    epi_ln_m(acc, pb + 3*256, pb + 4*256, pb + 5*256, Ah, ps, us, lg,
             wm, wn4, lane, false);

    // ---- S3: t = gelu(v @ W1 + b1) -> A (chunks 5-8) ----
    gemm_tc(acc, aHi, B0, B1, 5, 4, 13, wm, wn4, lane, tid);
#pragma unroll
    for (int mt = 0; mt < 2; mt++)
#pragma unroll
        for (int nt = 0; nt < 8; nt++) {
            int C = wn4 * 64 + nt * 8 + tp * 2;
            float e0 = pb[6*256 + C], e1 = pb[6*256 + C + 1];
#pragma unroll
            for (int rh = 0; rh < 2; rh++) {
                int row = wm*32 + mt*16 + rh*8 + g8;
                float x0 = acc[mt][nt][rh*2]   + e0;
                float x1 = acc[mt][nt][rh*2+1] + e1;
                float n0 = 0.5f * x0 * (1.f + erff(x0 * 0.70710678118f));
                float n1 = 0.5f * x1 * (1.f + erff(x1 * 0.70710678118f));
                storeA2(Ah, row, C, n0, n1);
            }
        }
    __syncthreads();

    // ---- S4: vtok = t @ W2 + b2 ; weighted column sums -> z (chunks 9-12) ----
    gemm_tc(acc, aHi, B0, B1, 9, 4, 13, wm, wn4, lane, tid);
    if (tid < 512) zs[tid] = 0.f;
    __syncthreads();
    {
        float za[8], zb[8];
#pragma unroll
        for (int nt = 0; nt < 8; nt++) { za[nt] = 0.f; zb[nt] = 0.f; }
#pragma unroll
        for (int mt = 0; mt < 2; mt++)
#pragma unroll
            for (int nt = 0; nt < 8; nt++) {
                int C = wn4 * 64 + nt * 8 + tp * 2;
                int hcol = C >> 6;
                float e0 = pb[7*256 + C], e1 = pb[7*256 + C + 1];
#pragma unroll
                for (int rh = 0; rh < 2; rh++) {
                    int row = wm*32 + mt*16 + rh*8 + g8;
                    float wf = wns[row*4 + hcol];
                    za[nt] += (acc[mt][nt][rh*2]   + e0) * wf;
                    zb[nt] += (acc[mt][nt][rh*2+1] + e1) * wf;
                }
            }
#pragma unroll
        for (int off = 4; off <= 16; off <<= 1)
#pragma unroll
            for (int nt = 0; nt < 8; nt++) {
                za[nt] += __shfl_xor_sync(0xffffffffu, za[nt], off);
                zb[nt] += __shfl_xor_sync(0xffffffffu, zb[nt], off);
            }
        if (lane < 4) {
            int half = wm >> 1;
#pragma unroll
            for (int nt = 0; nt < 8; nt++) {
                int C = wn4 * 64 + nt * 8 + lane * 2;
                atomicAdd(&zs[half*256 + C],     za[nt]);
                atomicAdd(&zs[half*256 + C + 1], zb[nt]);
            }
        }
    }
    __syncthreads();
    g_z[b0 * 256 + tid] = zs[tid];
}

// ---------------- k3t: c = z @ Wo (HMMA) ; out = h0 + rs*(c + bo) ----------------
#define O3_AH 0
#define O3_B0 65536
#define O3_B1 98304
#define O3_PB 131072
#define SMEM3T 132096

__global__ void __launch_bounds__(512, 1) k3t(
    const float* __restrict__ bo, const float* __restrict__ res_p,
    float* __restrict__ out)
{
    extern __shared__ char smc[];
    char*  Ah  = smc + O3_AH;
    char*  B0  = smc + O3_B0;
    char*  B1  = smc + O3_B1;
    float* pbo = (float*)(smc + O3_PB);

    const int tid = threadIdx.x, lane = tid & 31, w = tid >> 5;
    const int wm = w & 3, wn4 = w >> 2;
    const int g8 = lane >> 2, tp = lane & 3;
    const size_t b0 = (size_t)blockIdx.x * 128;
    const unsigned aHi = smem_u32(Ah);

    // chunk 13 is odd -> lands in B1 (gemm_tc parity convention)
    prefetch_chunk(B1, 13, tid);

    // stage z[128 rows][256] as fp16 A
    for (int idx = tid; idx < 8192; idx += 512) {
        int rr = idx >> 6, c4 = (idx & 63) * 4;
        float4 v = *reinterpret_cast<const float4*>(g_z + (b0 + rr) * 256 + c4);
        storeA2(Ah, rr, c4,     v.x, v.y);
        storeA2(Ah, rr, c4 + 2, v.z, v.w);
    }
    if (tid < 64)
        reinterpret_cast<float4*>(pbo)[tid] = reinterpret_cast<const float4*>(bo)[tid];

    float acc[2][8][4];
    gemm_tc(acc, aHi, B0, B1, 13, 4, 17, wm, wn4, lane, tid);

    const float rs = *res_p;
#pragma unroll
    for (int mt = 0; mt < 2; mt++)
#pragma unroll
        for (int nt = 0; nt < 8; nt++) {
            int C = wn4 * 64 + nt * 8 + tp * 2;
            float e0 = pbo[C], e1 = pbo[C + 1];
#pragma unroll
            for (int rh = 0; rh < 2; rh++) {
                int row = wm*32 + mt*16 + rh*8 + g8;
                size_t off = (b0 + row) * 256 + C;
                float2 hv = *reinterpret_cast<const float2*>(g_h0 + off);
                float2 o;
                o.x = hv.x + rs * (acc[mt][nt][rh*2]   + e0);
                o.y = hv.y + rs * (acc[mt][nt][rh*2+1] + e1);
                *reinterpret_cast<float2*>(out + off) = o;
            }
        }
}

// ============================================================
extern "C" void kernel_launch(void* const* d_in, const int* in_sizes, int n_in,
                              void* d_out, int out_size)
{
    const float* h_dyn   = (const float*)d_in[0];
    const float* x_stat  = (const float*)d_in[1];
    const float* W_dyn   = (const float*)d_in[2];
    const float* b_dyn   = (const float*)d_in[3];
    const float* W_stat  = (const float*)d_in[4];
    const float* b_stat  = (const float*)d_in[5];
    const float* g_ndyn  = (const float*)d_in[6];
    const float* b_ndyn  = (const float*)d_in[7];
    const float* g_nstat = (const float*)d_in[8];
    const float* b_nstat = (const float*)d_in[9];
    const float* Wq  = (const float*)d_in[10];
    const float* bq  = (const float*)d_in[11];
    const float* Wk  = (const float*)d_in[12];
    const float* bk  = (const float*)d_in[13];
    const float* Wv  = (const float*)d_in[14];
    const float* bv  = (const float*)d_in[15];
    const float* g_mlp = (const float*)d_in[16];
    const float* b_mlp = (const float*)d_in[17];
    const float* W1  = (const float*)d_in[18];
    const float* b1  = (const float*)d_in[19];
    const float* W2  = (const float*)d_in[20];
    const float* b2  = (const float*)d_in[21];
    const float* Wo  = (const float*)d_in[22];
    const float* bo  = (const float*)d_in[23];
    const float* res_sc = (const float*)d_in[24];
    float* out = (float*)d_out;

    const int SMEM1 = (32*512 + 32*256 + 32*256 + 16*WT_STRIDE + 5*256) * 4;
    cudaFuncSetAttribute(k1,  cudaFuncAttributeMaxDynamicSharedMemorySize, SMEM1);
    cudaFuncSetAttribute(k2m, cudaFuncAttributeMaxDynamicSharedMemorySize, SMEM2);
    cudaFuncSetAttribute(k3t, cudaFuncAttributeMaxDynamicSharedMemorySize, SMEM3T);

    k0<<<NCHUNK, 256>>>(W_stat, Wv, W1, W2, Wo);
    k1<<<B_ROWS / 32, 256, SMEM1>>>(h_dyn, W_dyn, b_dyn, g_ndyn, b_ndyn, Wq, bq, Wk, bk);
    k2m<<<B_ROWS / 2, 512, SMEM2>>>(x_stat, b_stat, g_nstat, b_nstat, bv,
                                    g_mlp, b_mlp, b1, b2, out);
    k3t<<<B_ROWS / 128, 512, SMEM3T>>>(bo, res_sc, out);
}

// round 15
// speedup vs baseline: 1.9199x; 1.0361x over previous
#include <cuda_runtime.h>
#include <cuda_fp16.h>
#include <math.h>
#include <stdint.h>

#define B_ROWS 4096
#define DM     256
#define DDYN   512
#define SCALE  0.125f
#define LN_EPS 1e-5f
#define WT_STRIDE 260
#define NCHUNK 25

// ---------------- device scratch ----------------
__device__ float g_h0 [B_ROWS * DM];
__device__ float g_u  [B_ROWS * DM * 4];
__device__ float g_qbk[B_ROWS * 4];
__device__ float g_y  [B_ROWS * 4 * DM];   // y[b][h][j]
__device__ float g_sw [B_ROWS * 4];        // sw[b][h]
__device__ float g_M  [4 * DM * DM];       // M_h = W2_h @ Wo_h
__device__ float g_P  [4 * DM];            // P_h = b2_h @ Wo_h
// 25 chunks (Wstat 1, Wv 4, W1 4, M 16): [256 n][64 k fp16 = 128B row, XOR-8]
__device__ uint4 g_B[NCHUNK * 2048];

__device__ __forceinline__ uint32_t smem_u32(const void* p) {
    uint32_t a;
    asm("{ .reg .u64 t; cvta.to.shared.u64 t, %1; cvt.u32.u64 %0, t; }" : "=r"(a) : "l"(p));
    return a;
}

// ---------------- mma / ldmatrix ----------------
__device__ __forceinline__ void mma_f16(float* d, const unsigned* a, unsigned b0, unsigned b1) {
    asm volatile("mma.sync.aligned.m16n8k16.row.col.f32.f16.f16.f32 "
        "{%0,%1,%2,%3}, {%4,%5,%6,%7}, {%8,%9}, {%0,%1,%2,%3};"
        : "+f"(d[0]), "+f"(d[1]), "+f"(d[2]), "+f"(d[3])
        : "r"(a[0]), "r"(a[1]), "r"(a[2]), "r"(a[3]), "r"(b0), "r"(b1));
}
__device__ __forceinline__ void ldsm4(unsigned* r, unsigned addr) {
    asm volatile("ldmatrix.sync.aligned.m8n8.x4.shared.b16 {%0,%1,%2,%3}, [%4];"
        : "=r"(r[0]), "=r"(r[1]), "=r"(r[2]), "=r"(r[3]) : "r"(addr));
}

// A smem layout: blocked atoms 8 rows x 64 cols (1KB), atom = (row>>3) + (col>>6)*16
__device__ __forceinline__ void storeA2(char* Ah, int row, int col,
                                        float v0, float v1) {
    unsigned byte = ((unsigned)(row >> 3) << 10) + ((unsigned)(col >> 6) << 14)
                  + ((unsigned)(row & 7) << 7)
                  + ((((unsigned)(col & 63)) * 2u) ^ (((unsigned)(row & 7)) << 4));
    __half h0 = __float2half_rn(v0), h1 = __float2half_rn(v1);
    *(unsigned*)(Ah + byte) = (unsigned)__half_as_ushort(h0) |
                              ((unsigned)__half_as_ushort(h1) << 16);
}

// ---------------- k0b: M_h = W2_h @ Wo_h ; P_h = b2_h @ Wo_h (fp32) ----------------
__global__ void k0b(const float* __restrict__ W2, const float* __restrict__ Wo,
                    const float* __restrict__ b2) {
    const int j = blockIdx.x, e = threadIdx.x;
#pragma unroll
    for (int h = 0; h < 4; h++) {
        float a = 0.f;
        for (int dl = 0; dl < 64; dl++)
            a = fmaf(W2[(size_t)j * 256 + h * 64 + dl],
                     Wo[(size_t)(h * 64 + dl) * 256 + e], a);
        g_M[(size_t)h * 65536 + (size_t)j * 256 + e] = a;
    }
    if (j == 0) {
#pragma unroll
        for (int h = 0; h < 4; h++) {
            float p = 0.f;
            for (int dl = 0; dl < 64; dl++)
                p = fmaf(b2[h * 64 + dl], Wo[(size_t)(h * 64 + dl) * 256 + e], p);
            g_P[h * 256 + e] = p;
        }
    }
}

// ---------------- k0: weights -> single-fp16 swizzled chunk images ----------------
__global__ void k0(const float* __restrict__ Ws, const float* __restrict__ Wv,
                   const float* __restrict__ W1) {
    const int c = blockIdx.x, n = threadIdx.x;   // c: 0..24
    const float* W; int kbase;
    if (c == 0)      { W = Ws; kbase = 0; }
    else if (c <= 4) { W = Wv; kbase = (c - 1) * 64; }
    else if (c <= 8) { W = W1; kbase = (c - 5) * 64; }
    else             { W = g_M + (size_t)((c - 9) >> 2) * 65536; kbase = ((c - 9) & 3) * 64; }
    char* bp = (char*)(g_B + (size_t)c * 2048) + n * 128;
    const unsigned nm = ((unsigned)n & 7u) << 4;
    for (int kl = 0; kl < 64; kl++) {
        float v = W[(size_t)(kbase + kl) * 256 + n];
        *(__half*)(bp + (((unsigned)kl * 2u) ^ nm)) = __float2half_rn(v);
    }
}

// ---------------- fp32 tiled GEMM helper (k1) ----------------
template<int NTHREADS>
__device__ __forceinline__ void gemm_acc(
    const float* __restrict__ Asm, int astride, int kdim,
    const float* __restrict__ Wg, float* __restrict__ Wt,
    float acc[4][8], int tid)
{
#pragma unroll
    for (int t = 0; t < 4; t++)
#pragma unroll
        for (int j = 0; j < 8; j++) acc[t][j] = 0.f;
    const int tc = tid & 31, tok0 = (tid >> 5) * 4, col0 = tc * 8;
    const int nkt = kdim >> 4;
    for (int kt = 0; kt < nkt; ++kt) {
        const float4* src = reinterpret_cast<const float4*>(Wg + kt * 16 * DM);
#pragma unroll
        for (int f = tid; f < 1024; f += NTHREADS) {
            int row = f >> 6, c4 = f & 63;
            *reinterpret_cast<float4*>(Wt + row * WT_STRIDE + c4 * 4) = src[f];
        }
        __syncthreads();
#pragma unroll
        for (int kk4 = 0; kk4 < 4; ++kk4) {
            const int kbase = kt * 16 + kk4 * 4;
            float a_[4][4];
#pragma unroll
            for (int t = 0; t < 4; t++) {
                float4 v = *reinterpret_cast<const float4*>(Asm + (tok0 + t) * astride + kbase);
                a_[t][0]=v.x; a_[t][1]=v.y; a_[t][2]=v.z; a_[t][3]=v.w;
            }
#pragma unroll
            for (int r = 0; r < 4; r++) {
                const float4 w0 = *reinterpret_cast<const float4*>(Wt + (kk4*4+r)*WT_STRIDE + col0);
                const float4 w1 = *reinterpret_cast<const float4*>(Wt + (kk4*4+r)*WT_STRIDE + col0 + 4);
                float w[8] = {w0.x,w0.y,w0.z,w0.w,w1.x,w1.y,w1.z,w1.w};
#pragma unroll
                for (int t = 0; t < 4; t++) {
                    const float a = a_[t][r];
#pragma unroll
                    for (int j = 0; j < 8; j++) acc[t][j] = fmaf(a, w[j], acc[t][j]);
                }
            }
        }
        __syncthreads();
    }
}

// ---------------- k1 (unchanged from R14) ----------------
__global__ void __launch_bounds__(256, 1) k1(
    const float* __restrict__ h_dyn, const float* __restrict__ W_dyn,
    const float* __restrict__ b_dyn, const float* __restrict__ g_ndyn,
    const float* __restrict__ b_ndyn, const float* __restrict__ Wq,
    const float* __restrict__ bq, const float* __restrict__ Wk,
    const float* __restrict__ bk)
{
    extern __shared__ float sm[];
    float* sm_hd  = sm;
    float* sm_h   = sm_hd + 32 * 512;
    float* sm_q   = sm_h  + 32 * 256;
    float* sm_wt  = sm_q  + 32 * 256;
    float* p_bdyn = sm_wt + 16 * WT_STRIDE;
    float* p_gn = p_bdyn + 256; float* p_bn = p_gn + 256;
    float* p_bq = p_bn + 256;   float* p_bk = p_bq + 256;

    const int tid = threadIdx.x;
    const int row0 = blockIdx.x * 32;
    {
        const float4* src = reinterpret_cast<const float4*>(h_dyn + (size_t)row0 * DDYN);
        for (int f = tid; f < 4096; f += 256) reinterpret_cast<float4*>(sm_hd)[f] = src[f];
    }
    if (tid < 64) {
        reinterpret_cast<float4*>(p_bdyn)[tid] = reinterpret_cast<const float4*>(b_dyn)[tid];
        reinterpret_cast<float4*>(p_gn)[tid]   = reinterpret_cast<const float4*>(g_ndyn)[tid];
        reinterpret_cast<float4*>(p_bn)[tid]   = reinterpret_cast<const float4*>(b_ndyn)[tid];
        reinterpret_cast<float4*>(p_bq)[tid]   = reinterpret_cast<const float4*>(bq)[tid];
        reinterpret_cast<float4*>(p_bk)[tid]   = reinterpret_cast<const float4*>(bk)[tid];
    }
    __syncthreads();

    float acc[4][8];
    gemm_acc<256>(sm_hd, 512, 512, W_dyn, sm_wt, acc, tid);
    {
        const int tc = tid & 31, tok0 = (tid >> 5) * 4, col0 = tc * 8;
#pragma unroll
        for (int t = 0; t < 4; t++) {
            float s = 0.f, s2 = 0.f;
#pragma unroll
            for (int j = 0; j < 8; j++) {
                float v = acc[t][j] + p_bdyn[col0 + j];
                acc[t][j] = v; s += v; s2 += v * v;
            }
            float* h0p = g_h0 + (size_t)(row0 + tok0 + t) * DM + col0;
            reinterpret_cast<float4*>(h0p)[0] = make_float4(acc[t][0],acc[t][1],acc[t][2],acc[t][3]);
            reinterpret_cast<float4*>(h0p)[1] = make_float4(acc[t][4],acc[t][5],acc[t][6],acc[t][7]);
#pragma unroll
            for (int off = 16; off; off >>= 1) {
                s  += __shfl_xor_sync(0xffffffffu, s,  off);
                s2 += __shfl_xor_sync(0xffffffffu, s2, off);
            }
            float mean = s * (1.f/256.f);
            float rstd = rsqrtf(s2 * (1.f/256.f) - mean*mean + LN_EPS);
#pragma unroll
            for (int j = 0; j < 8; j++)
                sm_h[(tok0+t)*DM + col0+j] = (acc[t][j]-mean)*rstd*p_gn[col0+j] + p_bn[col0+j];
        }
    }
    __syncthreads();

    gemm_acc<256>(sm_h, 256, 256, Wq, sm_wt, acc, tid);
    {
        const int tc = tid & 31, tok0 = (tid >> 5) * 4, col0 = tc * 8;
#pragma unroll
        for (int t = 0; t < 4; t++)
#pragma unroll
            for (int j = 0; j < 8; j++)
                sm_q[(tok0+t)*DM + col0+j] = acc[t][j] + p_bq[col0+j];
    }
    __syncthreads();

    {
        const int w = tid >> 5, lane = tid & 31;
        const int h = w & 3, jh = w >> 2;
        float4 qr[16];
#pragma unroll
        for (int d4 = 0; d4 < 16; d4++)
            qr[d4] = *reinterpret_cast<const float4*>(sm_q + lane * DM + h * 64 + d4 * 4);
        const int j0 = jh * 128;
        for (int j = j0; j < j0 + 128; j++) {
            const float4* wrow = reinterpret_cast<const float4*>(Wk + (size_t)j * DM + h * 64);
            float a = 0.f;
#pragma unroll
            for (int d4 = 0; d4 < 16; d4++) {
                float4 wv = wrow[d4];
                a += qr[d4].x*wv.x + qr[d4].y*wv.y + qr[d4].z*wv.z + qr[d4].w*wv.w;
            }
            g_u[(size_t)(row0 + lane) * 1024 + j * 4 + h] = a;
        }
    }

    if (tid < 128) {
        const int r = tid >> 2, h = tid & 3;
        float a = 0.f;
#pragma unroll
        for (int d = 0; d < 64; d++) a += sm_q[r*DM + h*64 + d] * p_bk[h*64 + d];
        g_qbk[(size_t)(row0+r)*4 + h] = a;
    }
}

// ---------------- shared HMMA machinery ----------------
#define O_AH   0
#define O_B0   65536
#define O_B1   98304
#define O_PB   131072
#define O_US   140288
#define O_PS   148480
#define O_LG   152576
#define O_WN   160768
#define O_TAIL 162816
#define SMEM2  162880

__device__ __forceinline__ void prefetch_chunk(char* buf, int g, int tid) {
    const char* src = (const char*)(g_B + (size_t)g * 2048);
    unsigned dst = smem_u32(buf);
#pragma unroll
    for (int i = 0; i < 4; i++) {
        int o = (tid + i * 512) * 16;
        asm volatile("cp.async.cg.shared.global [%0], [%1], 16;"
            :: "r"(dst + o), "l"(src + o) : "memory");
    }
    asm volatile("cp.async.commit_group;" ::: "memory");
}

// warp grid: 16 warps = 4 (wm, 32 rows) x 4 (wn4, 64 cols); each chunk covers 64 k
__device__ __forceinline__ void gemm_tc(float acc[2][8][4],
    unsigned aHi, char* B0, char* B1,
    int g0, int nc, int gmax, int wm, int wn4, int lane, int tid, bool zero)
{
    if (zero) {
#pragma unroll
        for (int mt = 0; mt < 2; mt++)
#pragma unroll
            for (int nt = 0; nt < 8; nt++)
#pragma unroll
                for (int q = 0; q < 4; q++) acc[mt][nt][q] = 0.f;
    }
    const int aseg = lane >> 4;
    unsigned Arow[2], Axor[2];
#pragma unroll
    for (int mt = 0; mt < 2; mt++) {
        int row = wm * 32 + mt * 16 + (lane & 15);
        Arow[mt] = ((unsigned)(row >> 3) << 10) | ((unsigned)(row & 7) << 7);
        Axor[mt] = (unsigned)(row & 7) << 4;
    }
    const unsigned bseg = (lane >> 3) & 1;
    unsigned Bn[4], Bx[4];
#pragma unroll
    for (int p = 0; p < 4; p++) {
        int n = wn4 * 64 + p * 16 + (lane >> 4) * 8 + (lane & 7);
        Bn[p] = (unsigned)n * 128u;
        Bx[p] = ((unsigned)n & 7u) << 4;
    }

    for (int kc = 0; kc < nc; kc++) {
        const int g = g0 + kc;
        asm volatile("cp.async.wait_group 0;" ::: "memory");
        __syncthreads();
        if (g + 1 < gmax) prefetch_chunk(((g + 1) & 1) ? B1 : B0, g + 1, tid);
        const unsigned bbase = smem_u32((g & 1) ? B1 : B0);
        const unsigned acol = (unsigned)kc << 14;
#pragma unroll
        for (int ks = 0; ks < 4; ks++) {
            const unsigned asub = (unsigned)(ks * 32 + aseg * 16);
            unsigned ahi[2][4];
#pragma unroll
            for (int mt = 0; mt < 2; mt++) {
                unsigned off = acol + Arow[mt] + (asub ^ Axor[mt]);
                ldsm4(ahi[mt], aHi + off);
            }
            const unsigned bsub = (unsigned)(ks * 32 + bseg * 16);
#pragma unroll
            for (int p = 0; p < 4; p++) {
                unsigned b[4];
                ldsm4(b, bbase + Bn[p] + (bsub ^ Bx[p]));
#pragma unroll
                for (int mt = 0; mt < 2; mt++) {
                    mma_f16(acc[mt][2*p],   ahi[mt], b[0], b[1]);
                    mma_f16(acc[mt][2*p+1], ahi[mt], b[2], b[3]);
                }
            }
        }
    }
    __syncthreads();
}

// LN epilogue on register fragments; optional logit partials (S1)
__device__ __forceinline__ void epi_ln_m(float acc[2][8][4],
    const float* bias, const float* gg, const float* bb,
    char* Ah, float* ps, const float* us, float* lg,
    int wm, int wn4, int lane, bool do_logits)
{
    const int g8 = lane >> 2, tp = lane & 3;
    float s[4] = {0,0,0,0}, s2[4] = {0,0,0,0};
#pragma unroll
    for (int mt = 0; mt < 2; mt++)
#pragma unroll
        for (int nt = 0; nt < 8; nt++) {
            int C = wn4 * 64 + nt * 8 + tp * 2;
            float b0v = bias[C], b1v = bias[C + 1];
            float v0 = acc[mt][nt][0] + b0v, v1 = acc[mt][nt][1] + b1v;
            float v2 = acc[mt][nt][2] + b0v, v3 = acc[mt][nt][3] + b1v;
            acc[mt][nt][0]=v0; acc[mt][nt][1]=v1; acc[mt][nt][2]=v2; acc[mt][nt][3]=v3;
            s[mt*2]   += v0 + v1;  s2[mt*2]   += v0*v0 + v1*v1;
            s[mt*2+1] += v2 + v3;  s2[mt*2+1] += v2*v2 + v3*v3;
        }
#pragma unroll
    for (int off = 1; off <= 2; off <<= 1)
#pragma unroll
        for (int i = 0; i < 4; i++) {
            s[i]  += __shfl_xor_sync(0xffffffffu, s[i],  off);
            s2[i] += __shfl_xor_sync(0xffffffffu, s2[i], off);
        }
    if (tp == 0) {
#pragma unroll
        for (int i = 0; i < 4; i++) {
            int row = wm*32 + (i>>1)*16 + (i&1)*8 + g8;
            ps[(row*4 + wn4)*2]     = s[i];
            ps[(row*4 + wn4)*2 + 1] = s2[i];
        }
    }
    __syncthreads();
    float mean[4], rstd[4];
#pragma unroll
    for (int i = 0; i < 4; i++) {
        int row = wm*32 + (i>>1)*16 + (i&1)*8 + g8;
        float ss = 0.f, ss2 = 0.f;
#pragma unroll
        for (int x = 0; x < 4; x++) { ss += ps[(row*4+x)*2]; ss2 += ps[(row*4+x)*2+1]; }
        mean[i] = ss * (1.f/256.f);
        rstd[i] = rsqrtf(ss2 * (1.f/256.f) - mean[i]*mean[i] + LN_EPS);
    }
    float la[4][4];
    if (do_logits)
#pragma unroll
        for (int i = 0; i < 4; i++)
#pragma unroll
            for (int h = 0; h < 4; h++) la[i][h] = 0.f;
    const int half = wm >> 1;
#pragma unroll
    for (int mt = 0; mt < 2; mt++)
#pragma unroll
        for (int nt = 0; nt < 8; nt++) {
            int C = wn4 * 64 + nt * 8 + tp * 2;
            float g0 = gg[C], g1 = gg[C+1], e0 = bb[C], e1 = bb[C+1];
#pragma unroll
            for (int rh = 0; rh < 2; rh++) {
                int i = mt*2 + rh;
                int row = wm*32 + mt*16 + rh*8 + g8;
                float n0 = (acc[mt][nt][rh*2]   - mean[i]) * rstd[i] * g0 + e0;
                float n1 = (acc[mt][nt][rh*2+1] - mean[i]) * rstd[i] * g1 + e1;
                storeA2(Ah, row, C, n0, n1);
                if (do_logits) {
                    float4 u0 = *(const float4*)(us + half*1024 + C*4);
                    float4 u1 = *(const float4*)(us + half*1024 + (C+1)*4);
                    la[i][0] += n0*u0.x + n1*u1.x;
                    la[i][1] += n0*u0.y + n1*u1.y;
                    la[i][2] += n0*u0.z + n1*u1.z;
                    la[i][3] += n0*u0.w + n1*u1.w;
                }
            }
        }
    if (do_logits) {
#pragma unroll
        for (int off = 1; off <= 2; off <<= 1)
#pragma unroll
            for (int i = 0; i < 4; i++)
#pragma unroll
                for (int h = 0; h < 4; h++)
                    la[i][h] += __shfl_xor_sync(0xffffffffu, la[i][h], off);
        if (tp == 0)
#pragma unroll
            for (int i = 0; i < 4; i++) {
                int row = wm*32 + (i>>1)*16 + (i&1)*8 + g8;
#pragma unroll
                for (int h = 0; h < 4; h++) lg[row*16 + wn4*4 + h] = la[i][h];
            }
    }
    __syncthreads();
}

__global__ void __launch_bounds__(512, 1) k2m(
    const float* __restrict__ x_stat,
    const float* __restrict__ b_stat, const float* __restrict__ g_nstat,
    const float* __restrict__ b_nstat, const float* __restrict__ bv,
    const float* __restrict__ g_mlp,  const float* __restrict__ b_mlp,
    const float* __restrict__ b1,
    float* __restrict__ out)
{
    extern __shared__ char smc[];
    char*  Ah  = smc + O_AH;
    char*  B0  = smc + O_B0;
    char*  B1  = smc + O_B1;
    float* pb  = (float*)(smc + O_PB);
    float* us  = (float*)(smc + O_US);
    float* ps  = (float*)(smc + O_PS);
    float* lg  = (float*)(smc + O_LG);
    float* ysm = (float*)(smc + O_LG);   // reuse after S1 (2048 floats)
    float* wns = (float*)(smc + O_WN);
    float* qbk = (float*)(smc + O_TAIL);
    float* ssm = (float*)(smc + O_TAIL + 32);

    const int tid = threadIdx.x, lane = tid & 31, w = tid >> 5;
    const int wm = w & 3, wn4 = w >> 2;
    const int g8 = lane >> 2, tp = lane & 3;
    const size_t b0 = (size_t)blockIdx.x * 2;
    const unsigned aHi = smem_u32(Ah);

    prefetch_chunk(B0, 0, tid);

    // ---- cooperative staging ----
    for (int idx = tid; idx < 2048; idx += 512) {
        int rr = idx >> 4, c4 = (idx & 15) * 4;
        float4 v = *reinterpret_cast<const float4*>(
            x_stat + (b0 + (rr >> 6)) * 4096 + (size_t)(rr & 63) * 64 + c4);
        storeA2(Ah, rr, c4,     v.x, v.y);
        storeA2(Ah, rr, c4 + 2, v.z, v.w);
    }
    if (tid < 512)
        reinterpret_cast<float4*>(us)[tid] =
            reinterpret_cast<const float4*>(g_u + b0 * 1024)[tid];
    if (tid < 64) {
        reinterpret_cast<float4*>(pb + 0*256)[tid] = reinterpret_cast<const float4*>(b_stat)[tid];
        reinterpret_cast<float4*>(pb + 1*256)[tid] = reinterpret_cast<const float4*>(g_nstat)[tid];
        reinterpret_cast<float4*>(pb + 2*256)[tid] = reinterpret_cast<const float4*>(b_nstat)[tid];
        reinterpret_cast<float4*>(pb + 3*256)[tid] = reinterpret_cast<const float4*>(bv)[tid];
        reinterpret_cast<float4*>(pb + 4*256)[tid] = reinterpret_cast<const float4*>(g_mlp)[tid];
        reinterpret_cast<float4*>(pb + 5*256)[tid] = reinterpret_cast<const float4*>(b_mlp)[tid];
        reinterpret_cast<float4*>(pb + 6*256)[tid] = reinterpret_cast<const float4*>(b1)[tid];
    }
    if (tid < 8) qbk[tid] = g_qbk[b0 * 4 + tid];

    float acc[2][8][4];

    // ---- S1: s = x_stat @ W_stat ; LN -> A ; logit partials (chunk 0) ----
    gemm_tc(acc, aHi, B0, B1, 0, 1, 9, wm, wn4, lane, tid, true);
    epi_ln_m(acc, pb + 0*256, pb + 1*256, pb + 2*256, Ah, ps, us, lg,
             wm, wn4, lane, true);

    // ---- logits -> sigmoid -> normalize -> w_mean, sw ----
    {
        int row = tid >> 2, h = tid & 3;
        float lv = qbk[(row >> 6) * 4 + h];
#pragma unroll
        for (int x = 0; x < 4; x++) lv += lg[row*16 + x*4 + h];
        wns[tid] = 1.f / (1.f + expf(-lv * SCALE));
    }
    __syncthreads();
    if (tid < 8) {
        int half = tid >> 2, h = tid & 3;
        float sum = 0.f;
        for (int k = 0; k < 64; k++) sum += wns[(half*64 + k)*4 + h];
        float denom = sum + 1e-6f;
        ssm[tid] = denom;
        g_sw[(b0 + half) * 4 + h] = sum / denom;
    }
    __syncthreads();
    wns[tid] = wns[tid] / ssm[(tid >> 8) * 4 + (tid & 3)];
    __syncthreads();
    if (tid < 128)
        out[(size_t)B_ROWS * DM + (b0 + (tid >> 6)) * 64 + (tid & 63)] =
            0.25f * (wns[tid*4] + wns[tid*4+1] + wns[tid*4+2] + wns[tid*4+3]);
    // zero y accumulator (lg region no longer needed)
#pragma unroll
    for (int i = 0; i < 4; i++) ysm[tid + i * 512] = 0.f;
    __syncthreads();

    // ---- S2: v = s @ Wv ; LN(g_mlp) -> A (chunks 1-4) ----
    gemm_tc(acc, aHi, B0, B1, 1, 4, 9, wm, wn4, lane, tid, true);
    epi_ln_m(acc, pb + 3*256, pb + 4*256, pb + 5*256, Ah, ps, us, lg,
             wm, wn4, lane, false);

    // ---- S3: t = gelu(v @ W1 + b1) ; y_h = sum_k w[h,k]*t[k,:] (chunks 5-8) ----
    gemm_tc(acc, aHi, B0, B1, 5, 4, 9, wm, wn4, lane, tid, true);
#pragma unroll
    for (int mt = 0; mt < 2; mt++)
#pragma unroll
        for (int nt = 0; nt < 8; nt++) {
            int C = wn4 * 64 + nt * 8 + tp * 2;
            float e0 = pb[6*256 + C], e1 = pb[6*256 + C + 1];
#pragma unroll
            for (int rh = 0; rh < 2; rh++) {
                float x0 = acc[mt][nt][rh*2]   + e0;
                float x1 = acc[mt][nt][rh*2+1] + e1;
                acc[mt][nt][rh*2]   = 0.5f * x0 * (1.f + erff(x0 * 0.70710678118f));
                acc[mt][nt][rh*2+1] = 0.5f * x1 * (1.f + erff(x1 * 0.70710678118f));
            }
        }
    {
        const int half = wm >> 1;
#pragma unroll
        for (int h = 0; h < 4; h++) {
            float yp[16];
#pragma unroll
            for (int i = 0; i < 16; i++) yp[i] = 0.f;
#pragma unroll
            for (int mt = 0; mt < 2; mt++)
#pragma unroll
                for (int rh = 0; rh < 2; rh++) {
                    int row = wm*32 + mt*16 + rh*8 + g8;
                    float wf = wns[row*4 + h];
#pragma unroll
                    for (int nt = 0; nt < 8; nt++) {
                        yp[nt*2]   += wf * acc[mt][nt][rh*2];
                        yp[nt*2+1] += wf * acc[mt][nt][rh*2+1];
                    }
                }
#pragma unroll
            for (int off = 4; off <= 16; off <<= 1)
#pragma unroll
                for (int i = 0; i < 16; i++)
                    yp[i] += __shfl_xor_sync(0xffffffffu, yp[i], off);
            if (lane < 4) {
#pragma unroll
                for (int nt = 0; nt < 8; nt++) {
                    int C = wn4 * 64 + nt * 8 + lane * 2;
                    atomicAdd(&ysm[half*1024 + h*256 + C],     yp[nt*2]);
                    atomicAdd(&ysm[half*1024 + h*256 + C + 1], yp[nt*2+1]);
                }
            }
        }
    }
    __syncthreads();
#pragma unroll
    for (int i = 0; i < 4; i++) {
        int idx = tid + i * 512;   // [half][h][j]
        g_y[(b0 + (idx >> 10)) * 1024 + (idx & 1023)] = ysm[idx];
    }
}

// ---------------- k3t: c = sum_h y_h @ M_h ; out = h0 + rs*(c + sw·P + bo) ----------------
#define O3_AH  0
#define O3_B0  65536
#define O3_B1  98304
#define O3_PS  131072   // psm 4KB
#define O3_BO  135168   // pbo 1KB
#define O3_SW  136192   // swm 2KB
#define SMEM3T 138240

__global__ void __launch_bounds__(512, 1) k3t(
    const float* __restrict__ bo, const float* __restrict__ res_p,
    float* __restrict__ out)
{
    extern __shared__ char smc[];
    char*  Ah  = smc + O3_AH;
    char*  B0  = smc + O3_B0;
    char*  B1  = smc + O3_B1;
    float* psm = (float*)(smc + O3_PS);
    float* pbo = (float*)(smc + O3_BO);
    float* swm = (float*)(smc + O3_SW);

    const int tid = threadIdx.x, lane = tid & 31, w = tid >> 5;
    const int wm = w & 3, wn4 = w >> 2;
    const int g8 = lane >> 2, tp = lane & 3;
    const size_t b0 = (size_t)blockIdx.x * 128;
    const unsigned aHi = smem_u32(Ah);

    // chunk 9 is odd -> B1 (parity convention)
    prefetch_chunk(B1, 9, tid);

    if (tid < 64)
        reinterpret_cast<float4*>(pbo)[tid] = reinterpret_cast<const float4*>(bo)[tid];
    if (tid < 256)
        reinterpret_cast<float4*>(psm)[tid] = reinterpret_cast<const float4*>(g_P)[tid];
    swm[tid] = g_sw[b0 * 4 + tid];  // 512 = 128 rows x 4 h

    float acc[2][8][4];
#pragma unroll
    for (int h = 0; h < 4; h++) {
        // stage A = y[:, h, :] (128 rows x 256) as fp16
        for (int idx = tid; idx < 8192; idx += 512) {
            int rr = idx >> 6, c4 = (idx & 63) * 4;
            float4 v = *reinterpret_cast<const float4*>(
                g_y + (b0 + rr) * 1024 + h * 256 + c4);
            storeA2(Ah, rr, c4,     v.x, v.y);
            storeA2(Ah, rr, c4 + 2, v.z, v.w);
        }
        gemm_tc(acc, aHi, B0, B1, 9 + 4*h, 4, 25, wm, wn4, lane, tid, h == 0);
    }

    const float rs = *res_p;
#pragma unroll
    for (int mt = 0; mt < 2; mt++)
#pragma unroll
        for (int nt = 0; nt < 8; nt++) {
            int C = wn4 * 64 + nt * 8 + tp * 2;
            float e0 = pbo[C], e1 = pbo[C + 1];
#pragma unroll
            for (int rh = 0; rh < 2; rh++) {
                int row = wm*32 + mt*16 + rh*8 + g8;
                float c0 = acc[mt][nt][rh*2]   + e0;
                float c1 = acc[mt][nt][rh*2+1] + e1;
#pragma unroll
                for (int h = 0; h < 4; h++) {
                    float sw = swm[row*4 + h];
                    c0 += sw * psm[h*256 + C];
                    c1 += sw * psm[h*256 + C + 1];
                }
                size_t off = (b0 + row) * 256 + C;
                float2 hv = *reinterpret_cast<const float2*>(g_h0 + off);
                float2 o;
                o.x = hv.x + rs * c0;
                o.y = hv.y + rs * c1;
                *reinterpret_cast<float2*>(out + off) = o;
            }
        }
}

// ============================================================
extern "C" void kernel_launch(void* const* d_in, const int* in_sizes, int n_in,
                              void* d_out, int out_size)
{
    const float* h_dyn   = (const float*)d_in[0];
    const float* x_stat  = (const float*)d_in[1];
    const float* W_dyn   = (const float*)d_in[2];
    const float* b_dyn   = (const float*)d_in[3];
    const float* W_stat  = (const float*)d_in[4];
    const float* b_stat  = (const float*)d_in[5];
    const float* g_ndyn  = (const float*)d_in[6];
    const float* b_ndyn  = (const float*)d_in[7];
    const float* g_nstat = (const float*)d_in[8];
    const float* b_nstat = (const float*)d_in[9];
    const float* Wq  = (const float*)d_in[10];
    const float* bq  = (const float*)d_in[11];
    const float* Wk  = (const float*)d_in[12];
    const float* bk  = (const float*)d_in[13];
    const float* Wv  = (const float*)d_in[14];
    const float* bv  = (const float*)d_in[15];
    const float* g_mlp = (const float*)d_in[16];
    const float* b_mlp = (const float*)d_in[17];
    const float* W1  = (const float*)d_in[18];
    const float* b1  = (const float*)d_in[19];
    const float* W2  = (const float*)d_in[20];
    const float* b2  = (const float*)d_in[21];
    const float* Wo  = (const float*)d_in[22];
    const float* bo  = (const float*)d_in[23];
    const float* res_sc = (const float*)d_in[24];
    float* out = (float*)d_out;

    const int SMEM1 = (32*512 + 32*256 + 32*256 + 16*WT_STRIDE + 5*256) * 4;
    cudaFuncSetAttribute(k1,  cudaFuncAttributeMaxDynamicSharedMemorySize, SMEM1);
    cudaFuncSetAttribute(k2m, cudaFuncAttributeMaxDynamicSharedMemorySize, SMEM2);
    cudaFuncSetAttribute(k3t, cudaFuncAttributeMaxDynamicSharedMemorySize, SMEM3T);

    k0b<<<256, 256>>>(W2, Wo, b2);
    k0<<<NCHUNK, 256>>>(W_stat, Wv, W1);
    k1<<<B_ROWS / 32, 256, SMEM1>>>(h_dyn, W_dyn, b_dyn, g_ndyn, b_ndyn, Wq, bq, Wk, bk);
    k2m<<<B_ROWS / 2, 512, SMEM2>>>(x_stat, b_stat, g_nstat, b_nstat, bv,
                                    g_mlp, b_mlp, b1, out);
    k3t<<<B_ROWS / 128, 512, SMEM3T>>>(bo, res_sc, out);
}

// round 16
// speedup vs baseline: 2.0750x; 1.0808x over previous
#include <cuda_runtime.h>
#include <cuda_fp16.h>
#include <math.h>
#include <stdint.h>

#define B_ROWS 4096
#define DM     256
#define DDYN   512
#define SCALE  0.125f
#define LN_EPS 1e-5f
#define NCHUNK 49

// ---------------- device scratch ----------------
__device__ float g_h0 [B_ROWS * DM];
__device__ float g_u  [B_ROWS * DM * 4];
__device__ float g_qbk[B_ROWS * 4];
__device__ float g_y  [B_ROWS * 4 * DM];   // y[b][h][j]
__device__ float g_sw [B_ROWS * 4];        // sw[b][h]
__device__ float g_M  [4 * DM * DM];       // M_h = W2_h @ Wo_h
__device__ float g_P  [4 * DM];            // P_h = b2_h @ Wo_h
// chunks 0-8: k2m single-fp16 (64k); 9-24: k3t M (64k); 25-40: W_dyn hi/lo (32k);
// 41-48: Wq hi/lo (32k). Each chunk 32KB.
__device__ uint4 g_B[NCHUNK * 2048];

__device__ __forceinline__ uint32_t smem_u32(const void* p) {
    uint32_t a;
    asm("{ .reg .u64 t; cvta.to.shared.u64 t, %1; cvt.u32.u64 %0, t; }" : "=r"(a) : "l"(p));
    return a;
}

// ---------------- mma / ldmatrix ----------------
__device__ __forceinline__ void mma_f16(float* d, const unsigned* a, unsigned b0, unsigned b1) {
    asm volatile("mma.sync.aligned.m16n8k16.row.col.f32.f16.f16.f32 "
        "{%0,%1,%2,%3}, {%4,%5,%6,%7}, {%8,%9}, {%0,%1,%2,%3};"
        : "+f"(d[0]), "+f"(d[1]), "+f"(d[2]), "+f"(d[3])
        : "r"(a[0]), "r"(a[1]), "r"(a[2]), "r"(a[3]), "r"(b0), "r"(b1));
}
__device__ __forceinline__ void ldsm4(unsigned* r, unsigned addr) {
    asm volatile("ldmatrix.sync.aligned.m8n8.x4.shared.b16 {%0,%1,%2,%3}, [%4];"
        : "=r"(r[0]), "=r"(r[1]), "=r"(r[2]), "=r"(r[3]) : "r"(addr));
}

// A layout (M=128): atom = (row>>3) + (col>>6)*16
__device__ __forceinline__ void storeA2(char* Ah, int row, int col,
                                        float v0, float v1) {
    unsigned byte = ((unsigned)(row >> 3) << 10) + ((unsigned)(col >> 6) << 14)
                  + ((unsigned)(row & 7) << 7)
                  + ((((unsigned)(col & 63)) * 2u) ^ (((unsigned)(row & 7)) << 4));
    __half h0 = __float2half_rn(v0), h1 = __float2half_rn(v1);
    *(unsigned*)(Ah + byte) = (unsigned)__half_as_ushort(h0) |
                              ((unsigned)__half_as_ushort(h1) << 16);
}
// A layout (M=32, split hi/lo): atom = (row>>3) + (col>>6)*4
__device__ __forceinline__ void storeA2s32(char* Ah, char* Al, int row, int col,
                                           float v0, float v1) {
    unsigned byte = ((unsigned)((row >> 3) + ((col >> 6) << 2)) << 10)
                  + ((unsigned)(row & 7) << 7)
                  + ((((unsigned)(col & 63)) * 2u) ^ (((unsigned)(row & 7)) << 4));
    __half h0 = __float2half_rn(v0), h1 = __float2half_rn(v1);
    *(unsigned*)(Ah + byte) = (unsigned)__half_as_ushort(h0) |
                              ((unsigned)__half_as_ushort(h1) << 16);
    __half l0 = __float2half_rn(v0 - __half2float(h0));
    __half l1 = __float2half_rn(v1 - __half2float(h1));
    *(unsigned*)(Al + byte) = (unsigned)__half_as_ushort(l0) |
                              ((unsigned)__half_as_ushort(l1) << 16);
}

// ---------------- k0b: M_h = W2_h @ Wo_h ; P_h = b2_h @ Wo_h ----------------
__global__ void k0b(const float* __restrict__ W2, const float* __restrict__ Wo,
                    const float* __restrict__ b2) {
    const int j = blockIdx.x, e = threadIdx.x;
#pragma unroll
    for (int h = 0; h < 4; h++) {
        float a = 0.f;
        for (int dl = 0; dl < 64; dl++)
            a = fmaf(W2[(size_t)j * 256 + h * 64 + dl],
                     Wo[(size_t)(h * 64 + dl) * 256 + e], a);
        g_M[(size_t)h * 65536 + (size_t)j * 256 + e] = a;
    }
    if (j == 0) {
#pragma unroll
        for (int h = 0; h < 4; h++) {
            float p = 0.f;
            for (int dl = 0; dl < 64; dl++)
                p = fmaf(b2[h * 64 + dl], Wo[(size_t)(h * 64 + dl) * 256 + e], p);
            g_P[h * 256 + e] = p;
        }
    }
}

// ---------------- k0: single-fp16 chunks 0..24 ----------------
__global__ void k0(const float* __restrict__ Ws, const float* __restrict__ Wv,
                   const float* __restrict__ W1) {
    const int c = blockIdx.x, n = threadIdx.x;
    const float* W; int kbase;
    if (c == 0)      { W = Ws; kbase = 0; }
    else if (c <= 4) { W = Wv; kbase = (c - 1) * 64; }
    else if (c <= 8) { W = W1; kbase = (c - 5) * 64; }
    else             { W = g_M + (size_t)((c - 9) >> 2) * 65536; kbase = ((c - 9) & 3) * 64; }
    char* bp = (char*)(g_B + (size_t)c * 2048) + n * 128;
    const unsigned nm = ((unsigned)n & 7u) << 4;
    for (int kl = 0; kl < 64; kl++) {
        float v = W[(size_t)(kbase + kl) * 256 + n];
        *(__half*)(bp + (((unsigned)kl * 2u) ^ nm)) = __float2half_rn(v);
    }
}

// ---------------- k0c: hi/lo split chunks 25..48 (W_dyn 16, Wq 8) ----------------
__global__ void k0c(const float* __restrict__ Wd, const float* __restrict__ Wq) {
    const int c = blockIdx.x, n = threadIdx.x;   // c 0..23
    const float* W; int kbase;
    if (c < 16) { W = Wd; kbase = c * 32; }
    else        { W = Wq; kbase = (c - 16) * 32; }
    char* bp = (char*)(g_B + (size_t)(25 + c) * 2048) + n * 128;
    const unsigned nm = ((unsigned)n & 7u) << 4;
    for (int kl = 0; kl < 32; kl++) {
        float v = W[(size_t)(kbase + kl) * 256 + n];
        __half h = __float2half_rn(v);
        __half l = __float2half_rn(v - __half2float(h));
        *(__half*)(bp + (((unsigned)kl * 2u) ^ nm))        = h;
        *(__half*)(bp + ((64u + (unsigned)kl * 2u) ^ nm))  = l;
    }
}

// ---------------- prefetch ----------------
__device__ __forceinline__ void prefetch_chunk(char* buf, int g, int tid) {  // 512 thr
    const char* src = (const char*)(g_B + (size_t)g * 2048);
    unsigned dst = smem_u32(buf);
#pragma unroll
    for (int i = 0; i < 4; i++) {
        int o = (tid + i * 512) * 16;
        asm volatile("cp.async.cg.shared.global [%0], [%1], 16;"
            :: "r"(dst + o), "l"(src + o) : "memory");
    }
    asm volatile("cp.async.commit_group;" ::: "memory");
}
__device__ __forceinline__ void prefetch_chunk256(char* buf, int g, int tid) {  // 256 thr
    const char* src = (const char*)(g_B + (size_t)g * 2048);
    unsigned dst = smem_u32(buf);
#pragma unroll
    for (int i = 0; i < 8; i++) {
        int o = (tid + i * 256) * 16;
        asm volatile("cp.async.cg.shared.global [%0], [%1], 16;"
            :: "r"(dst + o), "l"(src + o) : "memory");
    }
    asm volatile("cp.async.commit_group;" ::: "memory");
}

// ---------------- k1m: HMMA 3-term-split GEMMs + fp32 u-stage ----------------
#define K1_AH 0
#define K1_AL 32768
#define K1_B0 65536
#define K1_B1 98304
#define K1_Q  131072
#define K1_PS 163840
#define K1_PB 165888
#define SMEM1M 171008

// M=32 3-term gemm: 8 warps (wn), 32 cols each. koff = k16 offset of g0 in A.
__device__ __forceinline__ void gemm32(float acc[2][4][4],
    unsigned aHi, unsigned aLo, char* B0, char* B1,
    int g0, int nc, int gmax, int wn, int lane, int tid, bool zero)
{
    if (zero) {
#pragma unroll
        for (int mt = 0; mt < 2; mt++)
#pragma unroll
            for (int nt = 0; nt < 4; nt++)
#pragma unroll
                for (int q = 0; q < 4; q++) acc[mt][nt][q] = 0.f;
    }
    const int aseg = lane >> 4;
    unsigned Arow[2], Axor[2];
#pragma unroll
    for (int mt = 0; mt < 2; mt++) {
        int row = mt * 16 + (lane & 15);
        Arow[mt] = (unsigned)(row >> 3) << 10;
        Axor[mt] = (unsigned)(row & 7) << 4;
        Arow[mt] += (unsigned)(row & 7) << 7;
    }
    const unsigned bseg = (lane >> 3) & 1;
    unsigned Bn[2], Bx[2];
#pragma unroll
    for (int p = 0; p < 2; p++) {
        int n = wn * 32 + p * 16 + (lane >> 4) * 8 + (lane & 7);
        Bn[p] = (unsigned)n * 128u;
        Bx[p] = ((unsigned)n & 7u) << 4;
    }

    for (int kc = 0; kc < nc; kc++) {
        const int g = g0 + kc;
        asm volatile("cp.async.wait_group 0;" ::: "memory");
        __syncthreads();
        if (g + 1 < gmax) prefetch_chunk256(((g + 1) & 1) ? B1 : B0, g + 1, tid);
        const unsigned bbase = smem_u32((g & 1) ? B1 : B0);
#pragma unroll
        for (int ks = 0; ks < 2; ks++) {
            const int kl16 = kc * 2 + ks;
            const unsigned acol = (unsigned)(kl16 >> 2) << 12;
            const unsigned asub = (unsigned)((kl16 & 3) * 32 + aseg * 16);
            unsigned ah[2][4], al[2][4];
#pragma unroll
            for (int mt = 0; mt < 2; mt++) {
                unsigned off = acol + Arow[mt] + (asub ^ Axor[mt]);
                ldsm4(ah[mt], aHi + off);
                ldsm4(al[mt], aLo + off);
            }
            const unsigned bsub = (unsigned)(ks * 32 + bseg * 16);
#pragma unroll
            for (int p = 0; p < 2; p++) {
                unsigned bh[4], bl[4];
                ldsm4(bh, bbase + Bn[p] + (bsub ^ Bx[p]));
                ldsm4(bl, bbase + Bn[p] + ((64u + bsub) ^ Bx[p]));
#pragma unroll
                for (int mt = 0; mt < 2; mt++) {
                    mma_f16(acc[mt][2*p],   ah[mt], bh[0], bh[1]);
                    mma_f16(acc[mt][2*p],   al[mt], bh[0], bh[1]);
                    mma_f16(acc[mt][2*p],   ah[mt], bl[0], bl[1]);
                    mma_f16(acc[mt][2*p+1], ah[mt], bh[2], bh[3]);
                    mma_f16(acc[mt][2*p+1], al[mt], bh[2], bh[3]);
                    mma_f16(acc[mt][2*p+1], ah[mt], bl[2], bl[3]);
                }
            }
        }
    }
    __syncthreads();
}

__global__ void __launch_bounds__(256, 1) k1m(
    const float* __restrict__ h_dyn, const float* __restrict__ b_dyn,
    const float* __restrict__ g_ndyn, const float* __restrict__ b_ndyn,
    const float* __restrict__ bq, const float* __restrict__ Wk,
    const float* __restrict__ bk)
{
    extern __shared__ char smc[];
    char*  Ah  = smc + K1_AH;
    char*  Al  = smc + K1_AL;
    char*  B0  = smc + K1_B0;
    char*  B1  = smc + K1_B1;
    float* smq = (float*)(smc + K1_Q);
    float* ps  = (float*)(smc + K1_PS);
    float* pb  = (float*)(smc + K1_PB);   // bdyn, gn, bn, bq, bk

    const int tid = threadIdx.x, lane = tid & 31, wn = tid >> 5;
    const int g8 = lane >> 2, tp = lane & 3;
    const int row0 = blockIdx.x * 32;
    const unsigned aHi = smem_u32(Ah), aLo = smem_u32(Al);

    prefetch_chunk256(B1, 25, tid);   // chunk 25 odd -> B1

    // stage A = split(h_dyn[32 x 512])
    for (int idx = tid; idx < 4096; idx += 256) {
        int rr = idx >> 7, c4 = (idx & 127) * 4;
        float4 v = *reinterpret_cast<const float4*>(
            h_dyn + (size_t)(row0 + rr) * DDYN + c4);
        storeA2s32(Ah, Al, rr, c4,     v.x, v.y);
        storeA2s32(Ah, Al, rr, c4 + 2, v.z, v.w);
    }
    if (tid < 64) {
        reinterpret_cast<float4*>(pb + 0*256)[tid] = reinterpret_cast<const float4*>(b_dyn)[tid];
        reinterpret_cast<float4*>(pb + 1*256)[tid] = reinterpret_cast<const float4*>(g_ndyn)[tid];
        reinterpret_cast<float4*>(pb + 2*256)[tid] = reinterpret_cast<const float4*>(b_ndyn)[tid];
        reinterpret_cast<float4*>(pb + 3*256)[tid] = reinterpret_cast<const float4*>(bq)[tid];
        reinterpret_cast<float4*>(pb + 4*256)[tid] = reinterpret_cast<const float4*>(bk)[tid];
    }

    float acc[2][4][4];

    // ---- GEMM1: h0 = h_dyn @ W_dyn (chunks 25-40) ----
    gemm32(acc, aHi, aLo, B0, B1, 25, 16, 49, wn, lane, tid, true);

    // epilogue1: +b_dyn -> h0 out ; LN -> split A
    {
        float s[4] = {0,0,0,0}, s2[4] = {0,0,0,0};
#pragma unroll
        for (int mt = 0; mt < 2; mt++)
#pragma unroll
            for (int nt = 0; nt < 4; nt++) {
                int C = wn * 32 + (nt >> 1) * 16 + (nt & 1) * 8 + tp * 2;
                float e0 = pb[C], e1 = pb[C + 1];
#pragma unroll
                for (int rh = 0; rh < 2; rh++) {
                    int i = mt*2 + rh;
                    int row = mt*16 + rh*8 + g8;
                    float v0 = acc[mt][nt][rh*2]   + e0;
                    float v1 = acc[mt][nt][rh*2+1] + e1;
                    acc[mt][nt][rh*2] = v0; acc[mt][nt][rh*2+1] = v1;
                    s[i] += v0 + v1; s2[i] += v0*v0 + v1*v1;
                    *reinterpret_cast<float2*>(
                        g_h0 + (size_t)(row0 + row) * 256 + C) = make_float2(v0, v1);
                }
            }
#pragma unroll
        for (int off = 1; off <= 2; off <<= 1)
#pragma unroll
            for (int i = 0; i < 4; i++) {
                s[i]  += __shfl_xor_sync(0xffffffffu, s[i],  off);
                s2[i] += __shfl_xor_sync(0xffffffffu, s2[i], off);
            }
        if (tp == 0) {
#pragma unroll
            for (int i = 0; i < 4; i++) {
                int row = (i>>1)*16 + (i&1)*8 + g8;
                ps[(row*8 + wn)*2]     = s[i];
                ps[(row*8 + wn)*2 + 1] = s2[i];
            }
        }
        __syncthreads();
        float mean[4], rstd[4];
#pragma unroll
        for (int i = 0; i < 4; i++) {
            int row = (i>>1)*16 + (i&1)*8 + g8;
            float ss = 0.f, ss2 = 0.f;
#pragma unroll
            for (int x = 0; x < 8; x++) { ss += ps[(row*8+x)*2]; ss2 += ps[(row*8+x)*2+1]; }
            mean[i] = ss * (1.f/256.f);
            rstd[i] = rsqrtf(ss2 * (1.f/256.f) - mean[i]*mean[i] + LN_EPS);
        }
#pragma unroll
        for (int mt = 0; mt < 2; mt++)
#pragma unroll
            for (int nt = 0; nt < 4; nt++) {
                int C = wn * 32 + (nt >> 1) * 16 + (nt & 1) * 8 + tp * 2;
                float gg0 = pb[256 + C], gg1 = pb[256 + C + 1];
                float ee0 = pb[512 + C], ee1 = pb[512 + C + 1];
#pragma unroll
                for (int rh = 0; rh < 2; rh++) {
                    int i = mt*2 + rh;
                    int row = mt*16 + rh*8 + g8;
                    float n0 = (acc[mt][nt][rh*2]   - mean[i]) * rstd[i] * gg0 + ee0;
                    float n1 = (acc[mt][nt][rh*2+1] - mean[i]) * rstd[i] * gg1 + ee1;
                    storeA2s32(Ah, Al, row, C, n0, n1);
                }
            }
    }

    // ---- GEMM2: q = h @ Wq (chunks 41-48) ----
    gemm32(acc, aHi, aLo, B0, B1, 41, 8, 49, wn, lane, tid, true);
#pragma unroll
    for (int mt = 0; mt < 2; mt++)
#pragma unroll
        for (int nt = 0; nt < 4; nt++) {
            int C = wn * 32 + (nt >> 1) * 16 + (nt & 1) * 8 + tp * 2;
            float e0 = pb[768 + C], e1 = pb[768 + C + 1];
#pragma unroll
            for (int rh = 0; rh < 2; rh++) {
                int row = mt*16 + rh*8 + g8;
                smq[row*256 + C]     = acc[mt][nt][rh*2]   + e0;
                smq[row*256 + C + 1] = acc[mt][nt][rh*2+1] + e1;
            }
        }
    __syncthreads();

    // ---- u-stage (fp32, exact): warp=(h, jh), lane=row ----
    {
        const int h = wn & 3, jh = wn >> 2;
        float4 qr[16];
#pragma unroll
        for (int d4 = 0; d4 < 16; d4++)
            qr[d4] = *reinterpret_cast<const float4*>(smq + lane * 256 + h * 64 + d4 * 4);
        const int j0 = jh * 128;
        for (int j = j0; j < j0 + 128; j++) {
            const float4* wrow = reinterpret_cast<const float4*>(Wk + (size_t)j * DM + h * 64);
            float a = 0.f;
#pragma unroll
            for (int d4 = 0; d4 < 16; d4++) {
                float4 wv = wrow[d4];
                a += qr[d4].x*wv.x + qr[d4].y*wv.y + qr[d4].z*wv.z + qr[d4].w*wv.w;
            }
            g_u[(size_t)(row0 + lane) * 1024 + j * 4 + h] = a;
        }
    }
    if (tid < 128) {
        const int r = tid >> 2, h = tid & 3;
        float a = 0.f;
#pragma unroll
        for (int d = 0; d < 64; d++) a += smq[r*256 + h*64 + d] * pb[1024 + h*64 + d];
        g_qbk[(size_t)(row0+r)*4 + h] = a;
    }
}

// ---------------- shared HMMA machinery (M=128; unchanged from R15) ----------------
#define O_AH   0
#define O_B0   65536
#define O_B1   98304
#define O_PB   131072
#define O_US   140288
#define O_PS   148480
#define O_LG   152576
#define O_WN   160768
#define O_TAIL 162816
#define SMEM2  162880

__device__ __forceinline__ void gemm_tc(float acc[2][8][4],
    unsigned aHi, char* B0, char* B1,
    int g0, int nc, int gmax, int wm, int wn4, int lane, int tid, bool zero)
{
    if (zero) {
#pragma unroll
        for (int mt = 0; mt < 2; mt++)
#pragma unroll
            for (int nt = 0; nt < 8; nt++)
#pragma unroll
                for (int q = 0; q < 4; q++) acc[mt][nt][q] = 0.f;
    }
    const int aseg = lane >> 4;
    unsigned Arow[2], Axor[2];
#pragma unroll
    for (int mt = 0; mt < 2; mt++) {
        int row = wm * 32 + mt * 16 + (lane & 15);
        Arow[mt] = ((unsigned)(row >> 3) << 10) | ((unsigned)(row & 7) << 7);
        Axor[mt] = (unsigned)(row & 7) << 4;
    }
    const unsigned bseg = (lane >> 3) & 1;
    unsigned Bn[4], Bx[4];
#pragma unroll
    for (int p = 0; p < 4; p++) {
        int n = wn4 * 64 + p * 16 + (lane >> 4) * 8 + (lane & 7);
        Bn[p] = (unsigned)n * 128u;
        Bx[p] = ((unsigned)n & 7u) << 4;
    }

    for (int kc = 0; kc < nc; kc++) {
        const int g = g0 + kc;
        asm volatile("cp.async.wait_group 0;" ::: "memory");
        __syncthreads();
        if (g + 1 < gmax) prefetch_chunk(((g + 1) & 1) ? B1 : B0, g + 1, tid);
        const unsigned bbase = smem_u32((g & 1) ? B1 : B0);
        const unsigned acol = (unsigned)kc << 14;
#pragma unroll
        for (int ks = 0; ks < 4; ks++) {
            const unsigned asub = (unsigned)(ks * 32 + aseg * 16);
            unsigned ahi[2][4];
#pragma unroll
            for (int mt = 0; mt < 2; mt++) {
                unsigned off = acol + Arow[mt] + (asub ^ Axor[mt]);
                ldsm4(ahi[mt], aHi + off);
            }
            const unsigned bsub = (unsigned)(ks * 32 + bseg * 16);
#pragma unroll
            for (int p = 0; p < 4; p++) {
                unsigned b[4];
                ldsm4(b, bbase + Bn[p] + (bsub ^ Bx[p]));
#pragma unroll
                for (int mt = 0; mt < 2; mt++) {
                    mma_f16(acc[mt][2*p],   ahi[mt], b[0], b[1]);
                    mma_f16(acc[mt][2*p+1], ahi[mt], b[2], b[3]);
                }
            }
        }
    }
    __syncthreads();
}

__device__ __forceinline__ void epi_ln_m(float acc[2][8][4],
    const float* bias, const float* gg, const float* bb,
    char* Ah, float* ps, const float* us, float* lg,
    int wm, int wn4, int lane, bool do_logits)
{
    const int g8 = lane >> 2, tp = lane & 3;
    float s[4] = {0,0,0,0}, s2[4] = {0,0,0,0};
#pragma unroll
    for (int mt = 0; mt < 2; mt++)
#pragma unroll
        for (int nt = 0; nt < 8; nt++) {
            int C = wn4 * 64 + nt * 8 + tp * 2;
            float b0v = bias[C], b1v = bias[C + 1];
            float v0 = acc[mt][nt][0] + b0v, v1 = acc[mt][nt][1] + b1v;
            float v2 = acc[mt][nt][2] + b0v, v3 = acc[mt][nt][3] + b1v;
            acc[mt][nt][0]=v0; acc[mt][nt][1]=v1; acc[mt][nt][2]=v2; acc[mt][nt][3]=v3;
            s[mt*2]   += v0 + v1;  s2[mt*2]   += v0*v0 + v1*v1;
            s[mt*2+1] += v2 + v3;  s2[mt*2+1] += v2*v2 + v3*v3;
        }
#pragma unroll
    for (int off = 1; off <= 2; off <<= 1)
#pragma unroll
        for (int i = 0; i < 4; i++) {
            s[i]  += __shfl_xor_sync(0xffffffffu, s[i],  off);
            s2[i] += __shfl_xor_sync(0xffffffffu, s2[i], off);
        }
    if (tp == 0) {
#pragma unroll
        for (int i = 0; i < 4; i++) {
            int row = wm*32 + (i>>1)*16 + (i&1)*8 + g8;
            ps[(row*4 + wn4)*2]     = s[i];
            ps[(row*4 + wn4)*2 + 1] = s2[i];
        }
    }
    __syncthreads();
    float mean[4], rstd[4];
#pragma unroll
    for (int i = 0; i < 4; i++) {
        int row = wm*32 + (i>>1)*16 + (i&1)*8 + g8;
        float ss = 0.f, ss2 = 0.f;
#pragma unroll
        for (int x = 0; x < 4; x++) { ss += ps[(row*4+x)*2]; ss2 += ps[(row*4+x)*2+1]; }
        mean[i] = ss * (1.f/256.f);
        rstd[i] = rsqrtf(ss2 * (1.f/256.f) - mean[i]*mean[i] + LN_EPS);
    }
    float la[4][4];
    if (do_logits)
#pragma unroll
        for (int i = 0; i < 4; i++)
#pragma unroll
            for (int h = 0; h < 4; h++) la[i][h] = 0.f;
    const int half = wm >> 1;
#pragma unroll
    for (int mt = 0; mt < 2; mt++)
#pragma unroll
        for (int nt = 0; nt < 8; nt++) {
            int C = wn4 * 64 + nt * 8 + tp * 2;
            float g0 = gg[C], g1 = gg[C+1], e0 = bb[C], e1 = bb[C+1];
#pragma unroll
            for (int rh = 0; rh < 2; rh++) {
                int i = mt*2 + rh;
                int row = wm*32 + mt*16 + rh*8 + g8;
                float n0 = (acc[mt][nt][rh*2]   - mean[i]) * rstd[i] * g0 + e0;
                float n1 = (acc[mt][nt][rh*2+1] - mean[i]) * rstd[i] * g1 + e1;
                storeA2(Ah, row, C, n0, n1);
                if (do_logits) {
                    float4 u0 = *(const float4*)(us + half*1024 + C*4);
                    float4 u1 = *(const float4*)(us + half*1024 + (C+1)*4);
                    la[i][0] += n0*u0.x + n1*u1.x;
                    la[i][1] += n0*u0.y + n1*u1.y;
                    la[i][2] += n0*u0.z + n1*u1.z;
                    la[i][3] += n0*u0.w + n1*u1.w;
                }
            }
        }
    if (do_logits) {
#pragma unroll
        for (int off = 1; off <= 2; off <<= 1)
#pragma unroll
            for (int i = 0; i < 4; i++)
#pragma unroll
                for (int h = 0; h < 4; h++)
                    la[i][h] += __shfl_xor_sync(0xffffffffu, la[i][h], off);
        if (tp == 0)
#pragma unroll
            for (int i = 0; i < 4; i++) {
                int row = wm*32 + (i>>1)*16 + (i&1)*8 + g8;
#pragma unroll
                for (int h = 0; h < 4; h++) lg[row*16 + wn4*4 + h] = la[i][h];
            }
    }
    __syncthreads();
}

__global__ void __launch_bounds__(512, 1) k2m(
    const float* __restrict__ x_stat,
    const float* __restrict__ b_stat, const float* __restrict__ g_nstat,
    const float* __restrict__ b_nstat, const float* __restrict__ bv,
    const float* __restrict__ g_mlp,  const float* __restrict__ b_mlp,
    const float* __restrict__ b1,
    float* __restrict__ out)
{
    extern __shared__ char smc[];
    char*  Ah  = smc + O_AH;
    char*  B0  = smc + O_B0;
    char*  B1  = smc + O_B1;
    float* pb  = (float*)(smc + O_PB);
    float* us  = (float*)(smc + O_US);
    float* ps  = (float*)(smc + O_PS);
    float* lg  = (float*)(smc + O_LG);
    float* ysm = (float*)(smc + O_LG);
    float* wns = (float*)(smc + O_WN);
    float* qbk = (float*)(smc + O_TAIL);
    float* ssm = (float*)(smc + O_TAIL + 32);

    const int tid = threadIdx.x, lane = tid & 31, w = tid >> 5;
    const int wm = w & 3, wn4 = w >> 2;
    const int g8 = lane >> 2, tp = lane & 3;
    const size_t b0 = (size_t)blockIdx.x * 2;
    const unsigned aHi = smem_u32(Ah);

    prefetch_chunk(B0, 0, tid);

    for (int idx = tid; idx < 2048; idx += 512) {
        int rr = idx >> 4, c4 = (idx & 15) * 4;
        float4 v = *reinterpret_cast<const float4*>(
            x_stat + (b0 + (rr >> 6)) * 4096 + (size_t)(rr & 63) * 64 + c4);
        storeA2(Ah, rr, c4,     v.x, v.y);
        storeA2(Ah, rr, c4 + 2, v.z, v.w);
    }
    if (tid < 512)
        reinterpret_cast<float4*>(us)[tid] =
            reinterpret_cast<const float4*>(g_u + b0 * 1024)[tid];
    if (tid < 64) {
        reinterpret_cast<float4*>(pb + 0*256)[tid] = reinterpret_cast<const float4*>(b_stat)[tid];
        reinterpret_cast<float4*>(pb + 1*256)[tid] = reinterpret_cast<const float4*>(g_nstat)[tid];
        reinterpret_cast<float4*>(pb + 2*256)[tid] = reinterpret_cast<const float4*>(b_nstat)[tid];
        reinterpret_cast<float4*>(pb + 3*256)[tid] = reinterpret_cast<const float4*>(bv)[tid];
        reinterpret_cast<float4*>(pb + 4*256)[tid] = reinterpret_cast<const float4*>(g_mlp)[tid];
        reinterpret_cast<float4*>(pb + 5*256)[tid] = reinterpret_cast<const float4*>(b_mlp)[tid];
        reinterpret_cast<float4*>(pb + 6*256)[tid] = reinterpret_cast<const float4*>(b1)[tid];
    }
    if (tid < 8) qbk[tid] = g_qbk[b0 * 4 + tid];

    float acc[2][8][4];

    gemm_tc(acc, aHi, B0, B1, 0, 1, 9, wm, wn4, lane, tid, true);
    epi_ln_m(acc, pb + 0*256, pb + 1*256, pb + 2*256, Ah, ps, us, lg,
             wm, wn4, lane, true);

    {
        int row = tid >> 2, h = tid & 3;
        float lv = qbk[(row >> 6) * 4 + h];
#pragma unroll
        for (int x = 0; x < 4; x++) lv += lg[row*16 + x*4 + h];
        wns[tid] = 1.f / (1.f + expf(-lv * SCALE));
    }
    __syncthreads();
    if (tid < 8) {
        int half = tid >> 2, h = tid & 3;
        float sum = 0.f;
        for (int k = 0; k < 64; k++) sum += wns[(half*64 + k)*4 + h];
        float denom = sum + 1e-6f;
        ssm[tid] = denom;
        g_sw[(b0 + half) * 4 + h] = sum / denom;
    }
    __syncthreads();
    wns[tid] = wns[tid] / ssm[(tid >> 8) * 4 + (tid & 3)];
    __syncthreads();
    if (tid < 128)
        out[(size_t)B_ROWS * DM + (b0 + (tid >> 6)) * 64 + (tid & 63)] =
            0.25f * (wns[tid*4] + wns[tid*4+1] + wns[tid*4+2] + wns[tid*4+3]);
#pragma unroll
    for (int i = 0; i < 4; i++) ysm[tid + i * 512] = 0.f;
    __syncthreads();

    gemm_tc(acc, aHi, B0, B1, 1, 4, 9, wm, wn4, lane, tid, true);
    epi_ln_m(acc, pb + 3*256, pb + 4*256, pb + 5*256, Ah, ps, us, lg,
             wm, wn4, lane, false);

    gemm_tc(acc, aHi, B0, B1, 5, 4, 9, wm, wn4, lane, tid, true);
#pragma unroll
    for (int mt = 0; mt < 2; mt++)
#pragma unroll
        for (int nt = 0; nt < 8; nt++) {
            int C = wn4 * 64 + nt * 8 + tp * 2;
            float e0 = pb[6*256 + C], e1 = pb[6*256 + C + 1];
#pragma unroll
            for (int rh = 0; rh < 2; rh++) {
                float x0 = acc[mt][nt][rh*2]   + e0;
                float x1 = acc[mt][nt][rh*2+1] + e1;
                acc[mt][nt][rh*2]   = 0.5f * x0 * (1.f + erff(x0 * 0.70710678118f));
                acc[mt][nt][rh*2+1] = 0.5f * x1 * (1.f + erff(x1 * 0.70710678118f));
            }
        }
    {
        const int half = wm >> 1;
#pragma unroll
        for (int h = 0; h < 4; h++) {
            float yp[16];
#pragma unroll
            for (int i = 0; i < 16; i++) yp[i] = 0.f;
#pragma unroll
            for (int mt = 0; mt < 2; mt++)
#pragma unroll
                for (int rh = 0; rh < 2; rh++) {
                    int row = wm*32 + mt*16 + rh*8 + g8;
                    float wf = wns[row*4 + h];
#pragma unroll
                    for (int nt = 0; nt < 8; nt++) {
                        yp[nt*2]   += wf * acc[mt][nt][rh*2];
                        yp[nt*2+1] += wf * acc[mt][nt][rh*2+1];
                    }
                }
#pragma unroll
            for (int off = 4; off <= 16; off <<= 1)
#pragma unroll
                for (int i = 0; i < 16; i++)
                    yp[i] += __shfl_xor_sync(0xffffffffu, yp[i], off);
            if (lane < 4) {
#pragma unroll
                for (int nt = 0; nt < 8; nt++) {
                    int C = wn4 * 64 + nt * 8 + lane * 2;
                    atomicAdd(&ysm[half*1024 + h*256 + C],     yp[nt*2]);
                    atomicAdd(&ysm[half*1024 + h*256 + C + 1], yp[nt*2+1]);
                }
            }
        }
    }
    __syncthreads();
#pragma unroll
    for (int i = 0; i < 4; i++) {
        int idx = tid + i * 512;
        g_y[(b0 + (idx >> 10)) * 1024 + (idx & 1023)] = ysm[idx];
    }
}

// ---------------- k3t (unchanged from R15) ----------------
#define O3_AH  0
#define O3_B0  65536
#define O3_B1  98304
#define O3_PS  131072
#define O3_BO  135168
#define O3_SW  136192
#define SMEM3T 138240

__global__ void __launch_bounds__(512, 1) k3t(
    const float* __restrict__ bo, const float* __restrict__ res_p,
    float* __restrict__ out)
{
    extern __shared__ char smc[];
    char*  Ah  = smc + O3_AH;
    char*  B0  = smc + O3_B0;
    char*  B1  = smc + O3_B1;
    float* psm = (float*)(smc + O3_PS);
    float* pbo = (float*)(smc + O3_BO);
    float* swm = (float*)(smc + O3_SW);

    const int tid = threadIdx.x, lane = tid & 31, w = tid >> 5;
    const int wm = w & 3, wn4 = w >> 2;
    const int g8 = lane >> 2, tp = lane & 3;
    const size_t b0 = (size_t)blockIdx.x * 128;
    const unsigned aHi = smem_u32(Ah);

    prefetch_chunk(B1, 9, tid);

    if (tid < 64)
        reinterpret_cast<float4*>(pbo)[tid] = reinterpret_cast<const float4*>(bo)[tid];
    if (tid < 256)
        reinterpret_cast<float4*>(psm)[tid] = reinterpret_cast<const float4*>(g_P)[tid];
    swm[tid] = g_sw[b0 * 4 + tid];

    float acc[2][8][4];
#pragma unroll
    for (int h = 0; h < 4; h++) {
        for (int idx = tid; idx < 8192; idx += 512) {
            int rr = idx >> 6, c4 = (idx & 63) * 4;
            float4 v = *reinterpret_cast<const float4*>(
                g_y + (b0 + rr) * 1024 + h * 256 + c4);
            storeA2(Ah, rr, c4,     v.x, v.y);
            storeA2(Ah, rr, c4 + 2, v.z, v.w);
        }
        gemm_tc(acc, aHi, B0, B1, 9 + 4*h, 4, 25, wm, wn4, lane, tid, h == 0);
    }

    const float rs = *res_p;
#pragma unroll
    for (int mt = 0; mt < 2; mt++)
#pragma unroll
        for (int nt = 0; nt < 8; nt++) {
            int C = wn4 * 64 + nt * 8 + tp * 2;
            float e0 = pbo[C], e1 = pbo[C + 1];
#pragma unroll
            for (int rh = 0; rh < 2; rh++) {
                int row = wm*32 + mt*16 + rh*8 + g8;
                float c0 = acc[mt][nt][rh*2]   + e0;
                float c1 = acc[mt][nt][rh*2+1] + e1;
#pragma unroll
                for (int h = 0; h < 4; h++) {
                    float sw = swm[row*4 + h];
                    c0 += sw * psm[h*256 + C];
                    c1 += sw * psm[h*256 + C + 1];
                }
                size_t off = (b0 + row) * 256 + C;
                float2 hv = *reinterpret_cast<const float2*>(g_h0 + off);
                float2 o;
                o.x = hv.x + rs * c0;
                o.y = hv.y + rs * c1;
                *reinterpret_cast<float2*>(out + off) = o;
            }
        }
}

// ============================================================
extern "C" void kernel_launch(void* const* d_in, const int* in_sizes, int n_in,
                              void* d_out, int out_size)
{
    const float* h_dyn   = (const float*)d_in[0];
    const float* x_stat  = (const float*)d_in[1];
    const float* W_dyn   = (const float*)d_in[2];
    const float* b_dyn   = (const float*)d_in[3];
    const float* W_stat  = (const float*)d_in[4];
    const float* b_stat  = (const float*)d_in[5];
    const float* g_ndyn  = (const float*)d_in[6];
    const float* b_ndyn  = (const float*)d_in[7];
    const float* g_nstat = (const float*)d_in[8];
    const float* b_nstat = (const float*)d_in[9];
    const float* Wq  = (const float*)d_in[10];
    const float* bq  = (const float*)d_in[11];
    const float* Wk  = (const float*)d_in[12];
    const float* bk  = (const float*)d_in[13];
    const float* Wv  = (const float*)d_in[14];
    const float* bv  = (const float*)d_in[15];
    const float* g_mlp = (const float*)d_in[16];
    const float* b_mlp = (const float*)d_in[17];
    const float* W1  = (const float*)d_in[18];
    const float* b1  = (const float*)d_in[19];
    const float* W2  = (const float*)d_in[20];
    const float* b2  = (const float*)d_in[21];
    const float* Wo  = (const float*)d_in[22];
    const float* bo  = (const float*)d_in[23];
    const float* res_sc = (const float*)d_in[24];
    float* out = (float*)d_out;

    cudaFuncSetAttribute(k1m, cudaFuncAttributeMaxDynamicSharedMemorySize, SMEM1M);
    cudaFuncSetAttribute(k2m, cudaFuncAttributeMaxDynamicSharedMemorySize, SMEM2);
    cudaFuncSetAttribute(k3t, cudaFuncAttributeMaxDynamicSharedMemorySize, SMEM3T);

    k0b<<<256, 256>>>(W2, Wo, b2);
    k0<<<25, 256>>>(W_stat, Wv, W1);
    k0c<<<24, 256>>>(W_dyn, Wq);
    k1m<<<B_ROWS / 32, 256, SMEM1M>>>(h_dyn, b_dyn, g_ndyn, b_ndyn, bq, Wk, bk);
    k2m<<<B_ROWS / 2, 512, SMEM2>>>(x_stat, b_stat, g_nstat, b_nstat, bv,
                                    g_mlp, b_mlp, b1, out);
    k3t<<<B_ROWS / 128, 512, SMEM3T>>>(bo, res_sc, out);
}

// round 17
// speedup vs baseline: 2.1249x; 1.0240x over previous
#include <cuda_runtime.h>
#include <cuda_fp16.h>
#include <math.h>
#include <stdint.h>

#define B_ROWS 4096
#define DM     256
#define DDYN   512
#define SCALE  0.125f
#define LN_EPS 1e-5f
#define NCHUNK 49

// ---------------- device scratch ----------------
__device__ float g_h0 [B_ROWS * DM];
__device__ float g_u  [B_ROWS * DM * 4];
__device__ float g_qbk[B_ROWS * 4];
__device__ float g_y  [B_ROWS * 4 * DM];   // y[b][h][j]
__device__ float g_sw [B_ROWS * 4];        // sw[b][h]
__device__ float g_M  [4 * DM * DM];       // M_h = W2_h @ Wo_h
__device__ float g_P  [4 * DM];            // P_h = b2_h @ Wo_h
// chunks 0-8: k2m single-fp16 (64k); 9-24: k3t M (64k); 25-40: W_dyn hi/lo (32k);
// 41-48: Wq hi/lo (32k). Each chunk 32KB.
__device__ uint4 g_B[NCHUNK * 2048];

__device__ __forceinline__ uint32_t smem_u32(const void* p) {
    uint32_t a;
    asm("{ .reg .u64 t; cvta.to.shared.u64 t, %1; cvt.u32.u64 %0, t; }" : "=r"(a) : "l"(p));
    return a;
}

// ---------------- mma / ldmatrix ----------------
__device__ __forceinline__ void mma_f16(float* d, const unsigned* a, unsigned b0, unsigned b1) {
    asm volatile("mma.sync.aligned.m16n8k16.row.col.f32.f16.f16.f32 "
        "{%0,%1,%2,%3}, {%4,%5,%6,%7}, {%8,%9}, {%0,%1,%2,%3};"
        : "+f"(d[0]), "+f"(d[1]), "+f"(d[2]), "+f"(d[3])
        : "r"(a[0]), "r"(a[1]), "r"(a[2]), "r"(a[3]), "r"(b0), "r"(b1));
}
__device__ __forceinline__ void ldsm4(unsigned* r, unsigned addr) {
    asm volatile("ldmatrix.sync.aligned.m8n8.x4.shared.b16 {%0,%1,%2,%3}, [%4];"
        : "=r"(r[0]), "=r"(r[1]), "=r"(r[2]), "=r"(r[3]) : "r"(addr));
}

// A layout (M=128): atom = (row>>3) + (col>>6)*16
__device__ __forceinline__ void storeA2(char* Ah, int row, int col,
                                        float v0, float v1) {
    unsigned byte = ((unsigned)(row >> 3) << 10) + ((unsigned)(col >> 6) << 14)
                  + ((unsigned)(row & 7) << 7)
                  + ((((unsigned)(col & 63)) * 2u) ^ (((unsigned)(row & 7)) << 4));
    __half h0 = __float2half_rn(v0), h1 = __float2half_rn(v1);
    *(unsigned*)(Ah + byte) = (unsigned)__half_as_ushort(h0) |
                              ((unsigned)__half_as_ushort(h1) << 16);
}
// A layout (M=32, split hi/lo): atom = (row>>3) + (col>>6)*4
__device__ __forceinline__ void storeA2s32(char* Ah, char* Al, int row, int col,
                                           float v0, float v1) {
    unsigned byte = ((unsigned)((row >> 3) + ((col >> 6) << 2)) << 10)
                  + ((unsigned)(row & 7) << 7)
                  + ((((unsigned)(col & 63)) * 2u) ^ (((unsigned)(row & 7)) << 4));
    __half h0 = __float2half_rn(v0), h1 = __float2half_rn(v1);
    *(unsigned*)(Ah + byte) = (unsigned)__half_as_ushort(h0) |
                              ((unsigned)__half_as_ushort(h1) << 16);
    __half l0 = __float2half_rn(v0 - __half2float(h0));
    __half l1 = __float2half_rn(v1 - __half2float(h1));
    *(unsigned*)(Al + byte) = (unsigned)__half_as_ushort(l0) |
                              ((unsigned)__half_as_ushort(l1) << 16);
}

// ---------------- k0b: M_h = W2_h @ Wo_h ; P_h = b2_h @ Wo_h ----------------
__global__ void k0b(const float* __restrict__ W2, const float* __restrict__ Wo,
                    const float* __restrict__ b2) {
    const int j = blockIdx.x, e = threadIdx.x;
#pragma unroll
    for (int h = 0; h < 4; h++) {
        float a = 0.f;
        for (int dl = 0; dl < 64; dl++)
            a = fmaf(W2[(size_t)j * 256 + h * 64 + dl],
                     Wo[(size_t)(h * 64 + dl) * 256 + e], a);
        g_M[(size_t)h * 65536 + (size_t)j * 256 + e] = a;
    }
    if (j == 0) {
#pragma unroll
        for (int h = 0; h < 4; h++) {
            float p = 0.f;
            for (int dl = 0; dl < 64; dl++)
                p = fmaf(b2[h * 64 + dl], Wo[(size_t)(h * 64 + dl) * 256 + e], p);
            g_P[h * 256 + e] = p;
        }
    }
}

// ---------------- k0: single-fp16 chunks 0..24 ----------------
__global__ void k0(const float* __restrict__ Ws, const float* __restrict__ Wv,
                   const float* __restrict__ W1) {
    const int c = blockIdx.x, n = threadIdx.x;
    const float* W; int kbase;
    if (c == 0)      { W = Ws; kbase = 0; }
    else if (c <= 4) { W = Wv; kbase = (c - 1) * 64; }
    else if (c <= 8) { W = W1; kbase = (c - 5) * 64; }
    else             { W = g_M + (size_t)((c - 9) >> 2) * 65536; kbase = ((c - 9) & 3) * 64; }
    char* bp = (char*)(g_B + (size_t)c * 2048) + n * 128;
    const unsigned nm = ((unsigned)n & 7u) << 4;
    for (int kl = 0; kl < 64; kl++) {
        float v = W[(size_t)(kbase + kl) * 256 + n];
        *(__half*)(bp + (((unsigned)kl * 2u) ^ nm)) = __float2half_rn(v);
    }
}

// ---------------- k0c: hi/lo split chunks 25..48 (W_dyn 16, Wq 8) ----------------
__global__ void k0c(const float* __restrict__ Wd, const float* __restrict__ Wq) {
    const int c = blockIdx.x, n = threadIdx.x;   // c 0..23
    const float* W; int kbase;
    if (c < 16) { W = Wd; kbase = c * 32; }
    else        { W = Wq; kbase = (c - 16) * 32; }
    char* bp = (char*)(g_B + (size_t)(25 + c) * 2048) + n * 128;
    const unsigned nm = ((unsigned)n & 7u) << 4;
    for (int kl = 0; kl < 32; kl++) {
        float v = W[(size_t)(kbase + kl) * 256 + n];
        __half h = __float2half_rn(v);
        __half l = __float2half_rn(v - __half2float(h));
        *(__half*)(bp + (((unsigned)kl * 2u) ^ nm))        = h;
        *(__half*)(bp + ((64u + (unsigned)kl * 2u) ^ nm))  = l;
    }
}

// ---------------- prefetch (512 threads) ----------------
__device__ __forceinline__ void prefetch_chunk(char* buf, int g, int tid) {
    const char* src = (const char*)(g_B + (size_t)g * 2048);
    unsigned dst = smem_u32(buf);
#pragma unroll
    for (int i = 0; i < 4; i++) {
        int o = (tid + i * 512) * 16;
        asm volatile("cp.async.cg.shared.global [%0], [%1], 16;"
            :: "r"(dst + o), "l"(src + o) : "memory");
    }
    asm volatile("cp.async.commit_group;" ::: "memory");
}

// ---------------- k1m: HMMA 3-term-split GEMMs + fp32 u-stage (512 thr) ----------------
#define K1_AH 0
#define K1_AL 32768
#define K1_B0 65536
#define K1_B1 98304
#define K1_Q  131072
#define K1_PS 163840
#define K1_PB 167936
#define SMEM1M 173056

// M=32 3-term gemm: 16 warps (wn), 16 cols each
__device__ __forceinline__ void gemm32(float acc[2][2][4],
    unsigned aHi, unsigned aLo, char* B0, char* B1,
    int g0, int nc, int gmax, int wn, int lane, int tid, bool zero)
{
    if (zero) {
#pragma unroll
        for (int mt = 0; mt < 2; mt++)
#pragma unroll
            for (int nt = 0; nt < 2; nt++)
#pragma unroll
                for (int q = 0; q < 4; q++) acc[mt][nt][q] = 0.f;
    }
    const int aseg = lane >> 4;
    unsigned Arow[2], Axor[2];
#pragma unroll
    for (int mt = 0; mt < 2; mt++) {
        int row = mt * 16 + (lane & 15);
        Arow[mt] = ((unsigned)(row >> 3) << 10) + ((unsigned)(row & 7) << 7);
        Axor[mt] = (unsigned)(row & 7) << 4;
    }
    const unsigned bseg = (lane >> 3) & 1;
    int n = wn * 16 + (lane >> 4) * 8 + (lane & 7);
    const unsigned Bn = (unsigned)n * 128u;
    const unsigned Bx = ((unsigned)n & 7u) << 4;

    for (int kc = 0; kc < nc; kc++) {
        const int g = g0 + kc;
        asm volatile("cp.async.wait_group 0;" ::: "memory");
        __syncthreads();
        if (g + 1 < gmax) prefetch_chunk(((g + 1) & 1) ? B1 : B0, g + 1, tid);
        const unsigned bbase = smem_u32((g & 1) ? B1 : B0);
#pragma unroll
        for (int ks = 0; ks < 2; ks++) {
            const int kl16 = kc * 2 + ks;
            const unsigned acol = (unsigned)(kl16 >> 2) << 12;
            const unsigned asub = (unsigned)((kl16 & 3) * 32 + aseg * 16);
            unsigned ah[2][4], al[2][4];
#pragma unroll
            for (int mt = 0; mt < 2; mt++) {
                unsigned off = acol + Arow[mt] + (asub ^ Axor[mt]);
                ldsm4(ah[mt], aHi + off);
                ldsm4(al[mt], aLo + off);
            }
            const unsigned bsub = (unsigned)(ks * 32 + bseg * 16);
            unsigned bh[4], bl[4];
            ldsm4(bh, bbase + Bn + (bsub ^ Bx));
            ldsm4(bl, bbase + Bn + ((64u + bsub) ^ Bx));
#pragma unroll
            for (int mt = 0; mt < 2; mt++) {
                mma_f16(acc[mt][0], ah[mt], bh[0], bh[1]);
                mma_f16(acc[mt][0], al[mt], bh[0], bh[1]);
                mma_f16(acc[mt][0], ah[mt], bl[0], bl[1]);
                mma_f16(acc[mt][1], ah[mt], bh[2], bh[3]);
                mma_f16(acc[mt][1], al[mt], bh[2], bh[3]);
                mma_f16(acc[mt][1], ah[mt], bl[2], bl[3]);
            }
        }
    }
    __syncthreads();
}

__global__ void __launch_bounds__(512, 1) k1m(
    const float* __restrict__ h_dyn, const float* __restrict__ b_dyn,
    const float* __restrict__ g_ndyn, const float* __restrict__ b_ndyn,
    const float* __restrict__ bq, const float* __restrict__ Wk,
    const float* __restrict__ bk)
{
    extern __shared__ char smc[];
    char*  Ah  = smc + K1_AH;
    char*  Al  = smc + K1_AL;
    char*  B0  = smc + K1_B0;
    char*  B1  = smc + K1_B1;
    float* smq = (float*)(smc + K1_Q);
    float* ps  = (float*)(smc + K1_PS);   // 32 rows x 16 warps x 2
    float* pb  = (float*)(smc + K1_PB);   // bdyn, gn, bn, bq, bk

    const int tid = threadIdx.x, lane = tid & 31, wn = tid >> 5;
    const int g8 = lane >> 2, tp = lane & 3;
    const int row0 = blockIdx.x * 32;
    const unsigned aHi = smem_u32(Ah), aLo = smem_u32(Al);

    prefetch_chunk(B1, 25, tid);   // chunk 25 odd -> B1

    // stage A = split(h_dyn[32 x 512])
    for (int idx = tid; idx < 4096; idx += 512) {
        int rr = idx >> 7, c4 = (idx & 127) * 4;
        float4 v = *reinterpret_cast<const float4*>(
            h_dyn + (size_t)(row0 + rr) * DDYN + c4);
        storeA2s32(Ah, Al, rr, c4,     v.x, v.y);
        storeA2s32(Ah, Al, rr, c4 + 2, v.z, v.w);
    }
    if (tid < 64) {
        reinterpret_cast<float4*>(pb + 0*256)[tid] = reinterpret_cast<const float4*>(b_dyn)[tid];
        reinterpret_cast<float4*>(pb + 1*256)[tid] = reinterpret_cast<const float4*>(g_ndyn)[tid];
        reinterpret_cast<float4*>(pb + 2*256)[tid] = reinterpret_cast<const float4*>(b_ndyn)[tid];
        reinterpret_cast<float4*>(pb + 3*256)[tid] = reinterpret_cast<const float4*>(bq)[tid];
        reinterpret_cast<float4*>(pb + 4*256)[tid] = reinterpret_cast<const float4*>(bk)[tid];
    }

    float acc[2][2][4];

    // ---- GEMM1: h0 = h_dyn @ W_dyn (chunks 25-40) ----
    gemm32(acc, aHi, aLo, B0, B1, 25, 16, 49, wn, lane, tid, true);

    // epilogue1: +b_dyn -> h0 out ; LN -> split A
    {
        float s[4] = {0,0,0,0}, s2[4] = {0,0,0,0};
#pragma unroll
        for (int mt = 0; mt < 2; mt++)
#pragma unroll
            for (int nt = 0; nt < 2; nt++) {
                int C = wn * 16 + nt * 8 + tp * 2;
                float e0 = pb[C], e1 = pb[C + 1];
#pragma unroll
                for (int rh = 0; rh < 2; rh++) {
                    int i = mt*2 + rh;
                    int row = mt*16 + rh*8 + g8;
                    float v0 = acc[mt][nt][rh*2]   + e0;
                    float v1 = acc[mt][nt][rh*2+1] + e1;
                    acc[mt][nt][rh*2] = v0; acc[mt][nt][rh*2+1] = v1;
                    s[i] += v0 + v1; s2[i] += v0*v0 + v1*v1;
                    *reinterpret_cast<float2*>(
                        g_h0 + (size_t)(row0 + row) * 256 + C) = make_float2(v0, v1);
                }
            }
#pragma unroll
        for (int off = 1; off <= 2; off <<= 1)
#pragma unroll
            for (int i = 0; i < 4; i++) {
                s[i]  += __shfl_xor_sync(0xffffffffu, s[i],  off);
                s2[i] += __shfl_xor_sync(0xffffffffu, s2[i], off);
            }
        if (tp == 0) {
#pragma unroll
            for (int i = 0; i < 4; i++) {
                int row = (i>>1)*16 + (i&1)*8 + g8;
                ps[(row*16 + wn)*2]     = s[i];
                ps[(row*16 + wn)*2 + 1] = s2[i];
            }
        }
        __syncthreads();
        float mean[4], rstd[4];
#pragma unroll
        for (int i = 0; i < 4; i++) {
            int row = (i>>1)*16 + (i&1)*8 + g8;
            float ss = 0.f, ss2 = 0.f;
#pragma unroll
            for (int x = 0; x < 16; x++) { ss += ps[(row*16+x)*2]; ss2 += ps[(row*16+x)*2+1]; }
            mean[i] = ss * (1.f/256.f);
            rstd[i] = rsqrtf(ss2 * (1.f/256.f) - mean[i]*mean[i] + LN_EPS);
        }
#pragma unroll
        for (int mt = 0; mt < 2; mt++)
#pragma unroll
            for (int nt = 0; nt < 2; nt++) {
                int C = wn * 16 + nt * 8 + tp * 2;
                float gg0 = pb[256 + C], gg1 = pb[256 + C + 1];
                float ee0 = pb[512 + C], ee1 = pb[512 + C + 1];
#pragma unroll
                for (int rh = 0; rh < 2; rh++) {
                    int i = mt*2 + rh;
                    int row = mt*16 + rh*8 + g8;
                    float n0 = (acc[mt][nt][rh*2]   - mean[i]) * rstd[i] * gg0 + ee0;
                    float n1 = (acc[mt][nt][rh*2+1] - mean[i]) * rstd[i] * gg1 + ee1;
                    storeA2s32(Ah, Al, row, C, n0, n1);
                }
            }
    }

    // ---- GEMM2: q = h @ Wq (chunks 41-48) ----
    gemm32(acc, aHi, aLo, B0, B1, 41, 8, 49, wn, lane, tid, true);
#pragma unroll
    for (int mt = 0; mt < 2; mt++)
#pragma unroll
        for (int nt = 0; nt < 2; nt++) {
            int C = wn * 16 + nt * 8 + tp * 2;
            float e0 = pb[768 + C], e1 = pb[768 + C + 1];
#pragma unroll
            for (int rh = 0; rh < 2; rh++) {
                int row = mt*16 + rh*8 + g8;
                smq[row*256 + C]     = acc[mt][nt][rh*2]   + e0;
                smq[row*256 + C + 1] = acc[mt][nt][rh*2+1] + e1;
            }
        }
    __syncthreads();

    // ---- u-stage (fp32, exact): warp=(h, j-quarter), lane=row ----
    {
        const int h = wn & 3, jq = wn >> 2;   // jq 0..3
        float4 qr[16];
#pragma unroll
        for (int d4 = 0; d4 < 16; d4++)
            qr[d4] = *reinterpret_cast<const float4*>(smq + lane * 256 + h * 64 + d4 * 4);
        const int j0 = jq * 64;
        for (int j = j0; j < j0 + 64; j++) {
            const float4* wrow = reinterpret_cast<const float4*>(Wk + (size_t)j * DM + h * 64);
            float a = 0.f;
#pragma unroll
            for (int d4 = 0; d4 < 16; d4++) {
                float4 wv = wrow[d4];
                a += qr[d4].x*wv.x + qr[d4].y*wv.y + qr[d4].z*wv.z + qr[d4].w*wv.w;
            }
            g_u[(size_t)(row0 + lane) * 1024 + j * 4 + h] = a;
        }
    }
    if (tid < 128) {
        const int r = tid >> 2, h = tid & 3;
        float a = 0.f;
#pragma unroll
        for (int d = 0; d < 64; d++) a += smq[r*256 + h*64 + d] * pb[1024 + h*64 + d];
        g_qbk[(size_t)(row0+r)*4 + h] = a;
    }
}

// ---------------- shared HMMA machinery (M=128; unchanged) ----------------
#define O_AH   0
#define O_B0   65536
#define O_B1   98304
#define O_PB   131072
#define O_US   140288
#define O_PS   148480
#define O_LG   152576
#define O_WN   160768
#define O_TAIL 162816
#define SMEM2  162880

__device__ __forceinline__ void gemm_tc(float acc[2][8][4],
    unsigned aHi, char* B0, char* B1,
    int g0, int nc, int gmax, int wm, int wn4, int lane, int tid, bool zero)
{
    if (zero) {
#pragma unroll
        for (int mt = 0; mt < 2; mt++)
#pragma unroll
            for (int nt = 0; nt < 8; nt++)
#pragma unroll
                for (int q = 0; q < 4; q++) acc[mt][nt][q] = 0.f;
    }
    const int aseg = lane >> 4;
    unsigned Arow[2], Axor[2];
#pragma unroll
    for (int mt = 0; mt < 2; mt++) {
        int row = wm * 32 + mt * 16 + (lane & 15);
        Arow[mt] = ((unsigned)(row >> 3) << 10) | ((unsigned)(row & 7) << 7);
        Axor[mt] = (unsigned)(row & 7) << 4;
    }
    const unsigned bseg = (lane >> 3) & 1;
    unsigned Bn[4], Bx[4];
#pragma unroll
    for (int p = 0; p < 4; p++) {
        int n = wn4 * 64 + p * 16 + (lane >> 4) * 8 + (lane & 7);
        Bn[p] = (unsigned)n * 128u;
        Bx[p] = ((unsigned)n & 7u) << 4;
    }

    for (int kc = 0; kc < nc; kc++) {
        const int g = g0 + kc;
        asm volatile("cp.async.wait_group 0;" ::: "memory");
        __syncthreads();
        if (g + 1 < gmax) prefetch_chunk(((g + 1) & 1) ? B1 : B0, g + 1, tid);
        const unsigned bbase = smem_u32((g & 1) ? B1 : B0);
        const unsigned acol = (unsigned)kc << 14;
#pragma unroll
        for (int ks = 0; ks < 4; ks++) {
            const unsigned asub = (unsigned)(ks * 32 + aseg * 16);
            unsigned ahi[2][4];
#pragma unroll
            for (int mt = 0; mt < 2; mt++) {
                unsigned off = acol + Arow[mt] + (asub ^ Axor[mt]);
                ldsm4(ahi[mt], aHi + off);
            }
            const unsigned bsub = (unsigned)(ks * 32 + bseg * 16);
#pragma unroll
            for (int p = 0; p < 4; p++) {
                unsigned b[4];
                ldsm4(b, bbase + Bn[p] + (bsub ^ Bx[p]));
#pragma unroll
                for (int mt = 0; mt < 2; mt++) {
                    mma_f16(acc[mt][2*p],   ahi[mt], b[0], b[1]);
                    mma_f16(acc[mt][2*p+1], ahi[mt], b[2], b[3]);
                }
            }
        }
    }
    __syncthreads();
}

__device__ __forceinline__ void epi_ln_m(float acc[2][8][4],
    const float* bias, const float* gg, const float* bb,
    char* Ah, float* ps, const float* us, float* lg,
    int wm, int wn4, int lane, bool do_logits)
{
    const int g8 = lane >> 2, tp = lane & 3;
    float s[4] = {0,0,0,0}, s2[4] = {0,0,0,0};
#pragma unroll
    for (int mt = 0; mt < 2; mt++)
#pragma unroll
        for (int nt = 0; nt < 8; nt++) {
            int C = wn4 * 64 + nt * 8 + tp * 2;
            float b0v = bias[C], b1v = bias[C + 1];
            float v0 = acc[mt][nt][0] + b0v, v1 = acc[mt][nt][1] + b1v;
            float v2 = acc[mt][nt][2] + b0v, v3 = acc[mt][nt][3] + b1v;
            acc[mt][nt][0]=v0; acc[mt][nt][1]=v1; acc[mt][nt][2]=v2; acc[mt][nt][3]=v3;
            s[mt*2]   += v0 + v1;  s2[mt*2]   += v0*v0 + v1*v1;
            s[mt*2+1] += v2 + v3;  s2[mt*2+1] += v2*v2 + v3*v3;
        }
#pragma unroll
    for (int off = 1; off <= 2; off <<= 1)
#pragma unroll
        for (int i = 0; i < 4; i++) {
            s[i]  += __shfl_xor_sync(0xffffffffu, s[i],  off);
            s2[i] += __shfl_xor_sync(0xffffffffu, s2[i], off);
        }
    if (tp == 0) {
#pragma unroll
        for (int i = 0; i < 4; i++) {
            int row = wm*32 + (i>>1)*16 + (i&1)*8 + g8;
            ps[(row*4 + wn4)*2]     = s[i];
            ps[(row*4 + wn4)*2 + 1] = s2[i];
        }
    }
    __syncthreads();
    float mean[4], rstd[4];
#pragma unroll
    for (int i = 0; i < 4; i++) {
        int row = wm*32 + (i>>1)*16 + (i&1)*8 + g8;
        float ss = 0.f, ss2 = 0.f;
#pragma unroll
        for (int x = 0; x < 4; x++) { ss += ps[(row*4+x)*2]; ss2 += ps[(row*4+x)*2+1]; }
        mean[i] = ss * (1.f/256.f);
        rstd[i] = rsqrtf(ss2 * (1.f/256.f) - mean[i]*mean[i] + LN_EPS);
    }
    float la[4][4];
    if (do_logits)
#pragma unroll
        for (int i = 0; i < 4; i++)
#pragma unroll
            for (int h = 0; h < 4; h++) la[i][h] = 0.f;
    const int half = wm >> 1;
#pragma unroll
    for (int mt = 0; mt < 2; mt++)
#pragma unroll
        for (int nt = 0; nt < 8; nt++) {
            int C = wn4 * 64 + nt * 8 + tp * 2;
            float g0 = gg[C], g1 = gg[C+1], e0 = bb[C], e1 = bb[C+1];
#pragma unroll
            for (int rh = 0; rh < 2; rh++) {
                int i = mt*2 + rh;
                int row = wm*32 + mt*16 + rh*8 + g8;
                float n0 = (acc[mt][nt][rh*2]   - mean[i]) * rstd[i] * g0 + e0;
                float n1 = (acc[mt][nt][rh*2+1] - mean[i]) * rstd[i] * g1 + e1;
                storeA2(Ah, row, C, n0, n1);
                if (do_logits) {
                    float4 u0 = *(const float4*)(us + half*1024 + C*4);
                    float4 u1 = *(const float4*)(us + half*1024 + (C+1)*4);
                    la[i][0] += n0*u0.x + n1*u1.x;
                    la[i][1] += n0*u0.y + n1*u1.y;
                    la[i][2] += n0*u0.z + n1*u1.z;
                    la[i][3] += n0*u0.w + n1*u1.w;
                }
            }
        }
    if (do_logits) {
#pragma unroll
        for (int off = 1; off <= 2; off <<= 1)
#pragma unroll
            for (int i = 0; i < 4; i++)
#pragma unroll
                for (int h = 0; h < 4; h++)
                    la[i][h] += __shfl_xor_sync(0xffffffffu, la[i][h], off);
        if (tp == 0)
#pragma unroll
            for (int i = 0; i < 4; i++) {
                int row = wm*32 + (i>>1)*16 + (i&1)*8 + g8;
#pragma unroll
                for (int h = 0; h < 4; h++) lg[row*16 + wn4*4 + h] = la[i][h];
            }
    }
    __syncthreads();
}

__global__ void __launch_bounds__(512, 1) k2m(
    const float* __restrict__ x_stat,
    const float* __restrict__ b_stat, const float* __restrict__ g_nstat,
    const float* __restrict__ b_nstat, const float* __restrict__ bv,
    const float* __restrict__ g_mlp,  const float* __restrict__ b_mlp,
    const float* __restrict__ b1,
    float* __restrict__ out)
{
    extern __shared__ char smc[];
    char*  Ah  = smc + O_AH;
    char*  B0  = smc + O_B0;
    char*  B1  = smc + O_B1;
    float* pb  = (float*)(smc + O_PB);
    float* us  = (float*)(smc + O_US);
    float* ps  = (float*)(smc + O_PS);
    float* lg  = (float*)(smc + O_LG);
    float* ysm = (float*)(smc + O_LG);
    float* wns = (float*)(smc + O_WN);
    float* qbk = (float*)(smc + O_TAIL);
    float* ssm = (float*)(smc + O_TAIL + 32);

    const int tid = threadIdx.x, lane = tid & 31, w = tid >> 5;
    const int wm = w & 3, wn4 = w >> 2;
    const int g8 = lane >> 2, tp = lane & 3;
    const size_t b0 = (size_t)blockIdx.x * 2;
    const unsigned aHi = smem_u32(Ah);

    prefetch_chunk(B0, 0, tid);

    for (int idx = tid; idx < 2048; idx += 512) {
        int rr = idx >> 4, c4 = (idx & 15) * 4;
        float4 v = *reinterpret_cast<const float4*>(
            x_stat + (b0 + (rr >> 6)) * 4096 + (size_t)(rr & 63) * 64 + c4);
        storeA2(Ah, rr, c4,     v.x, v.y);
        storeA2(Ah, rr, c4 + 2, v.z, v.w);
    }
    if (tid < 512)
        reinterpret_cast<float4*>(us)[tid] =
            reinterpret_cast<const float4*>(g_u + b0 * 1024)[tid];
    if (tid < 64) {
        reinterpret_cast<float4*>(pb + 0*256)[tid] = reinterpret_cast<const float4*>(b_stat)[tid];
        reinterpret_cast<float4*>(pb + 1*256)[tid] = reinterpret_cast<const float4*>(g_nstat)[tid];
        reinterpret_cast<float4*>(pb + 2*256)[tid] = reinterpret_cast<const float4*>(b_nstat)[tid];
        reinterpret_cast<float4*>(pb + 3*256)[tid] = reinterpret_cast<const float4*>(bv)[tid];
        reinterpret_cast<float4*>(pb + 4*256)[tid] = reinterpret_cast<const float4*>(g_mlp)[tid];
        reinterpret_cast<float4*>(pb + 5*256)[tid] = reinterpret_cast<const float4*>(b_mlp)[tid];
        reinterpret_cast<float4*>(pb + 6*256)[tid] = reinterpret_cast<const float4*>(b1)[tid];
    }
    if (tid < 8) qbk[tid] = g_qbk[b0 * 4 + tid];

    float acc[2][8][4];

    gemm_tc(acc, aHi, B0, B1, 0, 1, 9, wm, wn4, lane, tid, true);
    epi_ln_m(acc, pb + 0*256, pb + 1*256, pb + 2*256, Ah, ps, us, lg,
             wm, wn4, lane, true);

    {
        int row = tid >> 2, h = tid & 3;
        float lv = qbk[(row >> 6) * 4 + h];
#pragma unroll
        for (int x = 0; x < 4; x++) lv += lg[row*16 + x*4 + h];
        wns[tid] = 1.f / (1.f + expf(-lv * SCALE));
    }
    __syncthreads();
    if (tid < 8) {
        int half = tid >> 2, h = tid & 3;
        float sum = 0.f;
        for (int k = 0; k < 64; k++) sum += wns[(half*64 + k)*4 + h];
        float denom = sum + 1e-6f;
        ssm[tid] = denom;
        g_sw[(b0 + half) * 4 + h] = sum / denom;
    }
    __syncthreads();
    wns[tid] = wns[tid] / ssm[(tid >> 8) * 4 + (tid & 3)];
    __syncthreads();
    if (tid < 128)
        out[(size_t)B_ROWS * DM + (b0 + (tid >> 6)) * 64 + (tid & 63)] =
            0.25f * (wns[tid*4] + wns[tid*4+1] + wns[tid*4+2] + wns[tid*4+3]);
#pragma unroll
    for (int i = 0; i < 4; i++) ysm[tid + i * 512] = 0.f;
    __syncthreads();

    gemm_tc(acc, aHi, B0, B1, 1, 4, 9, wm, wn4, lane, tid, true);
    epi_ln_m(acc, pb + 3*256, pb + 4*256, pb + 5*256, Ah, ps, us, lg,
             wm, wn4, lane, false);

    gemm_tc(acc, aHi, B0, B1, 5, 4, 9, wm, wn4, lane, tid, true);
#pragma unroll
    for (int mt = 0; mt < 2; mt++)
#pragma unroll
        for (int nt = 0; nt < 8; nt++) {
            int C = wn4 * 64 + nt * 8 + tp * 2;
            float e0 = pb[6*256 + C], e1 = pb[6*256 + C + 1];
#pragma unroll
            for (int rh = 0; rh < 2; rh++) {
                float x0 = acc[mt][nt][rh*2]   + e0;
                float x1 = acc[mt][nt][rh*2+1] + e1;
                acc[mt][nt][rh*2]   = 0.5f * x0 * (1.f + erff(x0 * 0.70710678118f));
                acc[mt][nt][rh*2+1] = 0.5f * x1 * (1.f + erff(x1 * 0.70710678118f));
            }
        }
    {
        const int half = wm >> 1;
#pragma unroll
        for (int h = 0; h < 4; h++) {
            float yp[16];
#pragma unroll
            for (int i = 0; i < 16; i++) yp[i] = 0.f;
#pragma unroll
            for (int mt = 0; mt < 2; mt++)
#pragma unroll
                for (int rh = 0; rh < 2; rh++) {
                    int row = wm*32 + mt*16 + rh*8 + g8;
                    float wf = wns[row*4 + h];
#pragma unroll
                    for (int nt = 0; nt < 8; nt++) {
                        yp[nt*2]   += wf * acc[mt][nt][rh*2];
                        yp[nt*2+1] += wf * acc[mt][nt][rh*2+1];
                    }
                }
#pragma unroll
            for (int off = 4; off <= 16; off <<= 1)
#pragma unroll
                for (int i = 0; i < 16; i++)
                    yp[i] += __shfl_xor_sync(0xffffffffu, yp[i], off);
            if (lane < 4) {
#pragma unroll
                for (int nt = 0; nt < 8; nt++) {
                    int C = wn4 * 64 + nt * 8 + lane * 2;
                    atomicAdd(&ysm[half*1024 + h*256 + C],     yp[nt*2]);
                    atomicAdd(&ysm[half*1024 + h*256 + C + 1], yp[nt*2+1]);
                }
            }
        }
    }
    __syncthreads();
#pragma unroll
    for (int i = 0; i < 4; i++) {
        int idx = tid + i * 512;
        g_y[(b0 + (idx >> 10)) * 1024 + (idx & 1023)] = ysm[idx];
    }
}

// ---------------- k3t (unchanged) ----------------
#define O3_AH  0
#define O3_B0  65536
#define O3_B1  98304
#define O3_PS  131072
#define O3_BO  135168
#define O3_SW  136192
#define SMEM3T 138240

__global__ void __launch_bounds__(512, 1) k3t(
    const float* __restrict__ bo, const float* __restrict__ res_p,
    float* __restrict__ out)
{
    extern __shared__ char smc[];
    char*  Ah  = smc + O3_AH;
    char*  B0  = smc + O3_B0;
    char*  B1  = smc + O3_B1;
    float* psm = (float*)(smc + O3_PS);
    float* pbo = (float*)(smc + O3_BO);
    float* swm = (float*)(smc + O3_SW);

    const int tid = threadIdx.x, lane = tid & 31, w = tid >> 5;
    const int wm = w & 3, wn4 = w >> 2;
    const int g8 = lane >> 2, tp = lane & 3;
    const size_t b0 = (size_t)blockIdx.x * 128;
    const unsigned aHi = smem_u32(Ah);

    prefetch_chunk(B1, 9, tid);

    if (tid < 64)
        reinterpret_cast<float4*>(pbo)[tid] = reinterpret_cast<const float4*>(bo)[tid];
    if (tid < 256)
        reinterpret_cast<float4*>(psm)[tid] = reinterpret_cast<const float4*>(g_P)[tid];
    swm[tid] = g_sw[b0 * 4 + tid];

    float acc[2][8][4];
#pragma unroll
    for (int h = 0; h < 4; h++) {
        for (int idx = tid; idx < 8192; idx += 512) {
            int rr = idx >> 6, c4 = (idx & 63) * 4;
            float4 v = *reinterpret_cast<const float4*>(
                g_y + (b0 + rr) * 1024 + h * 256 + c4);
            storeA2(Ah, rr, c4,     v.x, v.y);
            storeA2(Ah, rr, c4 + 2, v.z, v.w);
        }
        gemm_tc(acc, aHi, B0, B1, 9 + 4*h, 4, 25, wm, wn4, lane, tid, h == 0);
    }

    const float rs = *res_p;
#pragma unroll
    for (int mt = 0; mt < 2; mt++)
#pragma unroll
        for (int nt = 0; nt < 8; nt++) {
            int C = wn4 * 64 + nt * 8 + tp * 2;
            float e0 = pbo[C], e1 = pbo[C + 1];
#pragma unroll
            for (int rh = 0; rh < 2; rh++) {
                int row = wm*32 + mt*16 + rh*8 + g8;
                float c0 = acc[mt][nt][rh*2]   + e0;
                float c1 = acc[mt][nt][rh*2+1] + e1;
#pragma unroll
                for (int h = 0; h < 4; h++) {
                    float sw = swm[row*4 + h];
                    c0 += sw * psm[h*256 + C];
                    c1 += sw * psm[h*256 + C + 1];
                }
                size_t off = (b0 + row) * 256 + C;
                float2 hv = *reinterpret_cast<const float2*>(g_h0 + off);
                float2 o;
                o.x = hv.x + rs * c0;
                o.y = hv.y + rs * c1;
                *reinterpret_cast<float2*>(out + off) = o;
            }
        }
}

// ============================================================
extern "C" void kernel_launch(void* const* d_in, const int* in_sizes, int n_in,
                              void* d_out, int out_size)
{
    const float* h_dyn   = (const float*)d_in[0];
    const float* x_stat  = (const float*)d_in[1];
    const float* W_dyn   = (const float*)d_in[2];
    const float* b_dyn   = (const float*)d_in[3];
    const float* W_stat  = (const float*)d_in[4];
    const float* b_stat  = (const float*)d_in[5];
    const float* g_ndyn  = (const float*)d_in[6];
    const float* b_ndyn  = (const float*)d_in[7];
    const float* g_nstat = (const float*)d_in[8];
    const float* b_nstat = (const float*)d_in[9];
    const float* Wq  = (const float*)d_in[10];
    const float* bq  = (const float*)d_in[11];
    const float* Wk  = (const float*)d_in[12];
    const float* bk  = (const float*)d_in[13];
    const float* Wv  = (const float*)d_in[14];
    const float* bv  = (const float*)d_in[15];
    const float* g_mlp = (const float*)d_in[16];
    const float* b_mlp = (const float*)d_in[17];
    const float* W1  = (const float*)d_in[18];
    const float* b1  = (const float*)d_in[19];
    const float* W2  = (const float*)d_in[20];
    const float* b2  = (const float*)d_in[21];
    const float* Wo  = (const float*)d_in[22];
    const float* bo  = (const float*)d_in[23];
    const float* res_sc = (const float*)d_in[24];
    float* out = (float*)d_out;

    cudaFuncSetAttribute(k1m, cudaFuncAttributeMaxDynamicSharedMemorySize, SMEM1M);
    cudaFuncSetAttribute(k2m, cudaFuncAttributeMaxDynamicSharedMemorySize, SMEM2);
    cudaFuncSetAttribute(k3t, cudaFuncAttributeMaxDynamicSharedMemorySize, SMEM3T);

    k0b<<<256, 256>>>(W2, Wo, b2);
    k0<<<25, 256>>>(W_stat, Wv, W1);
    k0c<<<24, 256>>>(W_dyn, Wq);
    k1m<<<B_ROWS / 32, 512, SMEM1M>>>(h_dyn, b_dyn, g_ndyn, b_ndyn, bq, Wk, bk);
    k2m<<<B_ROWS / 2, 512, SMEM2>>>(x_stat, b_stat, g_nstat, b_nstat, bv,
                                    g_mlp, b_mlp, b1, out);
    k3t<<<B_ROWS / 128, 512, SMEM3T>>>(bo, res_sc, out);
}